// round 1
// baseline (speedup 1.0000x reference)
#include <cuda_runtime.h>
#include <math.h>
#include <stdint.h>

// ---------------- problem constants ----------------
#define NB   8
#define LL   512
#define DD   256
#define HH   16
#define QK   32
#define VD   32
#define OUTD 256
#define NL   (NB*LL)          // 4096
#define QKH  (QK*HH)          // 512
#define FEAT 640              // 512 node + 128 spatial
#define HID  512              // OUT*2

// ---------------- scratch (no allocs allowed) ----------------
__device__ float g_q[(size_t)NL*QKH];
__device__ float g_k[(size_t)NL*QKH];
__device__ float g_v[(size_t)NL*QKH];
__device__ float g_t[(size_t)NL*QK];
__device__ float g_feat[(size_t)NL*FEAT];

// ============================================================
// K0: t = relu(pos_CA @ se_W1 + se_b1)   (4096 x 32)
// ============================================================
__global__ void k_spat(const float* __restrict__ posCA,
                       const float* __restrict__ seW1,
                       const float* __restrict__ seb1)
{
    int r = blockIdx.x * blockDim.x + threadIdx.x;
    if (r >= NL) return;
    float p0 = posCA[r*3+0], p1 = posCA[r*3+1], p2 = posCA[r*3+2];
#pragma unroll
    for (int j = 0; j < QK; j++) {
        float v = seb1[j] + p0*seW1[j] + p1*seW1[QK + j] + p2*seW1[2*QK + j];
        g_t[(size_t)r*QK + j] = fmaxf(v, 0.0f);
    }
}

// ============================================================
// K1: fused QKV projection GEMM  (4096 x 1536, K=256)
// Q columns get an extra K-chunk: t(4096x32) @ se_W2(32x512) + se_b2
// BM=BN=64, BK=32, 256 threads, 4x4 register tile.
// ============================================================
__global__ void __launch_bounds__(256) k_qkv(
    const float* __restrict__ x,
    const float* __restrict__ Wq, const float* __restrict__ Wk,
    const float* __restrict__ Wv,
    const float* __restrict__ seW2, const float* __restrict__ seb2)
{
    __shared__ float As[64][33];   // [m][k]
    __shared__ float Bs[32][68];   // [k][n], float4-aligned rows

    const int tid = threadIdx.x;
    const int ty = tid >> 4, tx = tid & 15;
    const int bm = blockIdx.x * 64;
    const int gcol = blockIdx.y * 64;
    const int mat = gcol / QKH;              // 0=q 1=k 2=v
    const int bn = gcol - mat * QKH;
    const float* W = (mat == 0) ? Wq : (mat == 1) ? Wk : Wv;

    float acc[4][4];
#pragma unroll
    for (int i = 0; i < 4; i++)
#pragma unroll
        for (int j = 0; j < 4; j++) acc[i][j] = 0.0f;

    const int nchunks = (mat == 0) ? 9 : 8;
    for (int ch = 0; ch < nchunks; ch++) {
        // ---- load A tile (64 x 32) ----
        {
            const float* Asrc; int lda, kc;
            if (ch < 8) { Asrc = x;   lda = DD; kc = ch * 32; }
            else        { Asrc = g_t; lda = QK; kc = 0; }
            int m  = tid >> 2;
            int k0 = (tid & 3) * 8;
            const float* p = Asrc + (size_t)(bm + m) * lda + kc + k0;
            float4 v0 = *(const float4*)p;
            float4 v1 = *(const float4*)(p + 4);
            float* d = &As[m][k0];
            d[0]=v0.x; d[1]=v0.y; d[2]=v0.z; d[3]=v0.w;
            d[4]=v1.x; d[5]=v1.y; d[6]=v1.z; d[7]=v1.w;
        }
        // ---- load B tile (32 x 64) ----
        {
            const float* Bsrc = (ch < 8) ? W : seW2;
            int bk = (ch < 8) ? ch * 32 : 0;
            int k  = tid >> 3;
            int c0 = (tid & 7) * 8;
            const float* p = Bsrc + (size_t)(bk + k) * QKH + bn + c0;
            float4 v0 = *(const float4*)p;
            float4 v1 = *(const float4*)(p + 4);
            float* d = &Bs[k][c0];
            d[0]=v0.x; d[1]=v0.y; d[2]=v0.z; d[3]=v0.w;
            d[4]=v1.x; d[5]=v1.y; d[6]=v1.z; d[7]=v1.w;
        }
        __syncthreads();
#pragma unroll
        for (int k = 0; k < 32; k++) {
            float a0 = As[ty*4+0][k], a1 = As[ty*4+1][k];
            float a2 = As[ty*4+2][k], a3 = As[ty*4+3][k];
            float4 bv = *(const float4*)&Bs[k][tx*4];
            acc[0][0] += a0*bv.x; acc[0][1] += a0*bv.y; acc[0][2] += a0*bv.z; acc[0][3] += a0*bv.w;
            acc[1][0] += a1*bv.x; acc[1][1] += a1*bv.y; acc[1][2] += a1*bv.z; acc[1][3] += a1*bv.w;
            acc[2][0] += a2*bv.x; acc[2][1] += a2*bv.y; acc[2][2] += a2*bv.z; acc[2][3] += a2*bv.w;
            acc[3][0] += a3*bv.x; acc[3][1] += a3*bv.y; acc[3][2] += a3*bv.z; acc[3][3] += a3*bv.w;
        }
        __syncthreads();
    }

    float* dst = (mat == 0) ? g_q : (mat == 1) ? g_k : g_v;
#pragma unroll
    for (int i = 0; i < 4; i++) {
        int row = bm + ty*4 + i;
        int col = bn + tx*4;
        float4 v;
        v.x = acc[i][0]; v.y = acc[i][1]; v.z = acc[i][2]; v.w = acc[i][3];
        if (mat == 0) {
            v.x += seb2[col+0]; v.y += seb2[col+1];
            v.z += seb2[col+2]; v.w += seb2[col+3];
        }
        *(float4*)&dst[(size_t)row*QKH + col] = v;
    }
}

// ============================================================
// K2: attention per (b,h). 512 threads = one query row each.
// Online softmax; writes node feats + spatial feats to g_feat.
// dyn smem: k(64K) + v(64K) + posCB(6K) + mask(2K) = 139264 B
// ============================================================
__global__ void __launch_bounds__(512, 1) k_attn(
    const float* __restrict__ posCA,
    const float* __restrict__ posCB,
    const float* __restrict__ frame,
    const int*   __restrict__ mask)
{
    extern __shared__ float sm[];
    float* ks  = sm;                   // [512][32]
    float* vs  = sm + 512*32;          // [512][32]
    float* pcb = sm + 2*512*32;        // [512][3]
    int*   mk  = (int*)(sm + 2*512*32 + 512*3);  // [512]

    const int h = blockIdx.x;
    const int b = blockIdx.y;
    const int tid = threadIdx.x;

    const size_t base = ((size_t)b * LL) * QKH + h * QK;
    for (int e = tid; e < 512*32; e += 512) {
        int j = e >> 5, d = e & 31;
        ks[e] = g_k[base + (size_t)j * QKH + d];
        vs[e] = g_v[base + (size_t)j * QKH + d];
    }
    for (int e = tid; e < 512*3; e += 512) pcb[e] = posCB[(size_t)b*LL*3 + e];
    mk[tid] = mask[b*LL + tid];
    __syncthreads();

    const int row = tid;
    const size_t grow = (size_t)b * LL + row;

    // load q row into registers
    float q[32];
    {
        const float4* qp = (const float4*)(g_q + grow * QKH + h * QK);
#pragma unroll
        for (int t = 0; t < 8; t++) {
            float4 v = qp[t];
            q[4*t+0]=v.x; q[4*t+1]=v.y; q[4*t+2]=v.z; q[4*t+3]=v.w;
        }
    }

    float m = -1e30f, s = 0.0f;
    float av[32];
#pragma unroll
    for (int d = 0; d < 32; d++) av[d] = 0.0f;
    float ap0 = 0.0f, ap1 = 0.0f, ap2 = 0.0f;

    for (int j = 0; j < LL; j++) {
        if (!mk[j]) continue;
        const float4* k4 = (const float4*)(ks + j*32);
        float lg = 0.0f;
#pragma unroll
        for (int t = 0; t < 8; t++) {
            float4 kv = k4[t];
            lg += q[4*t+0]*kv.x + q[4*t+1]*kv.y + q[4*t+2]*kv.z + q[4*t+3]*kv.w;
        }
        if (lg > m) {
            float c = __expf(m - lg);
            m = lg;
            s *= c;
#pragma unroll
            for (int d = 0; d < 32; d++) av[d] *= c;
            ap0 *= c; ap1 *= c; ap2 *= c;
        }
        float p = __expf(lg - m);
        s += p;
        const float4* v4 = (const float4*)(vs + j*32);
#pragma unroll
        for (int t = 0; t < 8; t++) {
            float4 vv = v4[t];
            av[4*t+0] += p*vv.x; av[4*t+1] += p*vv.y;
            av[4*t+2] += p*vv.z; av[4*t+3] += p*vv.w;
        }
        ap0 += p * pcb[j*3+0];
        ap1 += p * pcb[j*3+1];
        ap2 += p * pcb[j*3+2];
    }

    float* fr = g_feat + grow * FEAT;
    const bool ok = (mk[row] != 0) && (s > 0.0f);
    if (!ok) {
#pragma unroll
        for (int d = 0; d < 32; d++) fr[h*32 + d] = 0.0f;
        fr[512 + h*3+0] = 0.0f; fr[512 + h*3+1] = 0.0f; fr[512 + h*3+2] = 0.0f;
        fr[560 + h] = 0.0f;
        fr[576 + h*3+0] = 0.0f; fr[576 + h*3+1] = 0.0f; fr[576 + h*3+2] = 0.0f;
        fr[624 + h] = 0.0f;
        return;
    }
    const float inv = 1.0f / s;
#pragma unroll
    for (int d = 0; d < 32; d++) av[d] *= inv;
    // apb = sum(alpha * posCB) - posCA   (since sum(alpha)=1)
    ap0 = ap0 * inv - posCA[grow*3+0];
    ap1 = ap1 * inv - posCA[grow*3+1];
    ap2 = ap2 * inv - posCA[grow*3+2];

    const float* F = frame + grow * 9;
    float pt0 = F[0]*ap0 + F[1]*ap1 + F[2]*ap2;
    float pt1 = F[3]*ap0 + F[4]*ap1 + F[5]*ap2;
    float pt2 = F[6]*ap0 + F[7]*ap1 + F[8]*ap2;

    float dist = sqrtf(ap0*ap0 + ap1*ap1 + ap2*ap2);
    float pn   = sqrtf(pt0*pt0 + pt1*pt1 + pt2*pt2);
    float id   = 1.0f / (pn + 1e-10f);
    float ang  = atan2f(pt1, pt0);

#pragma unroll
    for (int d = 0; d < 32; d++) fr[h*32 + d] = av[d];
    fr[512 + h*3+0] = pt0; fr[512 + h*3+1] = pt1; fr[512 + h*3+2] = pt2;
    fr[560 + h] = dist;
    fr[576 + h*3+0] = pt0*id; fr[576 + h*3+1] = pt1*id; fr[576 + h*3+2] = pt2*id;
    fr[624 + h] = ang;
}

// ============================================================
// K3: output MLP + residual + layernorm. 32-row tiles.
// dyn smem: feat tile 32*640 + h1 tile 32*512 = 147456 B
// ============================================================
__global__ void __launch_bounds__(256, 1) k_out(
    const float* __restrict__ x,
    const float* __restrict__ W1, const float* __restrict__ b1,
    const float* __restrict__ W2, const float* __restrict__ b2,
    const int*   __restrict__ mask,
    const float* __restrict__ lng, const float* __restrict__ lnb,
    float* __restrict__ out)
{
    extern __shared__ float sm[];
    float* Fs = sm;                 // [32][640]
    float* Hs = sm + 32*FEAT;       // [32][512]

    const int rb  = blockIdx.x * 32;
    const int tid = threadIdx.x;

    for (int e = tid; e < 32*FEAT; e += 256)
        Fs[e] = g_feat[(size_t)rb * FEAT + e];
    __syncthreads();

    // ---- phase A: h1 = relu(feat @ W1 + b1), each thread 2 cols x 32 rows
    {
        float a0[32], a1[32];
#pragma unroll
        for (int r = 0; r < 32; r++) { a0[r] = 0.0f; a1[r] = 0.0f; }
        const int c0 = tid, c1 = tid + 256;
        for (int k = 0; k < FEAT; k++) {
            float w0 = W1[(size_t)k * HID + c0];
            float w1 = W1[(size_t)k * HID + c1];
#pragma unroll
            for (int r = 0; r < 32; r++) {
                float f = Fs[r*FEAT + k];
                a0[r] += f * w0;
                a1[r] += f * w1;
            }
        }
        float bb0 = b1[c0], bb1 = b1[c1];
#pragma unroll
        for (int r = 0; r < 32; r++) {
            Hs[r*HID + c0] = fmaxf(a0[r] + bb0, 0.0f);
            Hs[r*HID + c1] = fmaxf(a1[r] + bb1, 0.0f);
        }
    }
    __syncthreads();

    // ---- phase B: out = h1 @ W2 + b2, each thread 1 col x 32 rows
    float acc[32];
#pragma unroll
    for (int r = 0; r < 32; r++) acc[r] = 0.0f;
    for (int k = 0; k < HID; k++) {
        float w = W2[(size_t)k * OUTD + tid];
#pragma unroll
        for (int r = 0; r < 32; r++)
            acc[r] += Hs[r*HID + k] * w;
    }
    __syncthreads();   // done with Fs contents; reuse as Ys

    float* Ys = Fs;    // [32][256]
    const float bcol = b2[tid];
#pragma unroll
    for (int r = 0; r < 32; r++) {
        int grow = rb + r;
        float o = acc[r] + bcol;
        if (!mask[grow]) o = 0.0f;
        Ys[r*OUTD + tid] = x[(size_t)grow*OUTD + tid] + o;
    }
    __syncthreads();

    // ---- layernorm: warp w handles rows w*4..w*4+3
    const int wid = tid >> 5, lane = tid & 31;
    for (int rr = 0; rr < 4; rr++) {
        int r = wid * 4 + rr;
        float yv[8];
        float ssum = 0.0f, ssq = 0.0f;
#pragma unroll
        for (int i = 0; i < 8; i++) {
            float v = Ys[r*OUTD + lane*8 + i];
            yv[i] = v;
            ssum += v;
            ssq  += v * v;
        }
#pragma unroll
        for (int off = 16; off > 0; off >>= 1) {
            ssum += __shfl_xor_sync(0xFFFFFFFF, ssum, off);
            ssq  += __shfl_xor_sync(0xFFFFFFFF, ssq,  off);
        }
        float mu  = ssum * (1.0f / OUTD);
        float var = ssq * (1.0f / OUTD) - mu * mu;
        float rs  = rsqrtf(var + 1e-5f);
        int grow = rb + r;
#pragma unroll
        for (int i = 0; i < 8; i++) {
            int c = lane*8 + i;
            out[(size_t)grow*OUTD + c] = (yv[i] - mu) * rs * lng[c] + lnb[c];
        }
    }
}

// ============================================================
extern "C" void kernel_launch(void* const* d_in, const int* in_sizes, int n_in,
                              void* d_out, int out_size)
{
    const float* x     = (const float*)d_in[0];
    const float* posCA = (const float*)d_in[1];
    const float* posCB = (const float*)d_in[2];
    const float* frame = (const float*)d_in[3];
    const int*   mask  = (const int*)  d_in[4];   // nonzero test works for i32 or f32 encodings
    const float* Wq    = (const float*)d_in[5];
    const float* Wk    = (const float*)d_in[6];
    const float* Wv    = (const float*)d_in[7];
    const float* seW1  = (const float*)d_in[8];
    const float* seb1  = (const float*)d_in[9];
    const float* seW2  = (const float*)d_in[10];
    const float* seb2  = (const float*)d_in[11];
    const float* otW1  = (const float*)d_in[12];
    const float* otb1  = (const float*)d_in[13];
    const float* otW2  = (const float*)d_in[14];
    const float* otb2  = (const float*)d_in[15];
    const float* lng   = (const float*)d_in[16];
    const float* lnb   = (const float*)d_in[17];
    float* out = (float*)d_out;

    const int smem_attn = (2*512*32 + 512*3 + 512) * 4;   // 139264
    const int smem_out  = (32*FEAT + 32*HID) * 4;         // 147456
    cudaFuncSetAttribute(k_attn, cudaFuncAttributeMaxDynamicSharedMemorySize, smem_attn);
    cudaFuncSetAttribute(k_out,  cudaFuncAttributeMaxDynamicSharedMemorySize, smem_out);

    k_spat<<<NL/128, 128>>>(posCA, seW1, seb1);
    k_qkv<<<dim3(NL/64, (3*QKH)/64), 256>>>(x, Wq, Wk, Wv, seW2, seb2);
    k_attn<<<dim3(HH, NB), 512, smem_attn>>>(posCA, posCB, frame, mask);
    k_out<<<NL/32, 256, smem_out>>>(x, otW1, otb1, otW2, otb2, mask, lng, lnb, out);
}

// round 2
// speedup vs baseline: 1.3379x; 1.3379x over previous
#include <cuda_runtime.h>
#include <math.h>
#include <stdint.h>

// ---------------- problem constants ----------------
#define NB   8
#define LL   512
#define DD   256
#define HH   16
#define QK   32
#define VD   32
#define OUTD 256
#define NL   (NB*LL)          // 4096
#define QKH  (QK*HH)          // 512
#define FEAT 640              // 512 node + 128 spatial
#define HID  512              // OUT*2

// ---------------- scratch (no allocs allowed) ----------------
__device__ float g_q[(size_t)NL*QKH];
__device__ float g_k[(size_t)NL*QKH];
__device__ float g_v[(size_t)NL*QKH];
__device__ float g_t[(size_t)NL*QK];
__device__ float g_feat[(size_t)NL*FEAT];
__device__ float g_h1[(size_t)NL*HID];
__device__ float g_y[(size_t)NL*OUTD];

// ============================================================
// K0: t = relu(pos_CA @ se_W1 + se_b1)   (4096 x 32)
// ============================================================
__global__ void k_spat(const float* __restrict__ posCA,
                       const float* __restrict__ seW1,
                       const float* __restrict__ seb1)
{
    int r = blockIdx.x * blockDim.x + threadIdx.x;
    if (r >= NL) return;
    float p0 = posCA[r*3+0], p1 = posCA[r*3+1], p2 = posCA[r*3+2];
#pragma unroll
    for (int j = 0; j < QK; j++) {
        float v = seb1[j] + p0*seW1[j] + p1*seW1[QK + j] + p2*seW1[2*QK + j];
        g_t[(size_t)r*QK + j] = fmaxf(v, 0.0f);
    }
}

// ============================================================
// K1: fused QKV projection GEMM  (4096 x 1536, K=256)
// Q columns get an extra K-chunk: t(4096x32) @ se_W2(32x512) + se_b2
// BM=BN=64, BK=32, 256 threads, 4x4 register tile.
// ============================================================
__global__ void __launch_bounds__(256) k_qkv(
    const float* __restrict__ x,
    const float* __restrict__ Wq, const float* __restrict__ Wk,
    const float* __restrict__ Wv,
    const float* __restrict__ seW2, const float* __restrict__ seb2)
{
    __shared__ float As[64][33];   // [m][k]
    __shared__ float Bs[32][68];   // [k][n], float4-aligned rows

    const int tid = threadIdx.x;
    const int ty = tid >> 4, tx = tid & 15;
    const int bm = blockIdx.x * 64;
    const int gcol = blockIdx.y * 64;
    const int mat = gcol / QKH;              // 0=q 1=k 2=v
    const int bn = gcol - mat * QKH;
    const float* W = (mat == 0) ? Wq : (mat == 1) ? Wk : Wv;

    float acc[4][4];
#pragma unroll
    for (int i = 0; i < 4; i++)
#pragma unroll
        for (int j = 0; j < 4; j++) acc[i][j] = 0.0f;

    const int nchunks = (mat == 0) ? 9 : 8;
    for (int ch = 0; ch < nchunks; ch++) {
        // ---- load A tile (64 x 32) ----
        {
            const float* Asrc; int lda, kc;
            if (ch < 8) { Asrc = x;   lda = DD; kc = ch * 32; }
            else        { Asrc = g_t; lda = QK; kc = 0; }
            int m  = tid >> 2;
            int k0 = (tid & 3) * 8;
            const float* p = Asrc + (size_t)(bm + m) * lda + kc + k0;
            float4 v0 = *(const float4*)p;
            float4 v1 = *(const float4*)(p + 4);
            float* d = &As[m][k0];
            d[0]=v0.x; d[1]=v0.y; d[2]=v0.z; d[3]=v0.w;
            d[4]=v1.x; d[5]=v1.y; d[6]=v1.z; d[7]=v1.w;
        }
        // ---- load B tile (32 x 64) ----
        {
            const float* Bsrc = (ch < 8) ? W : seW2;
            int bk = (ch < 8) ? ch * 32 : 0;
            int k  = tid >> 3;
            int c0 = (tid & 7) * 8;
            const float* p = Bsrc + (size_t)(bk + k) * QKH + bn + c0;
            float4 v0 = *(const float4*)p;
            float4 v1 = *(const float4*)(p + 4);
            float* d = &Bs[k][c0];
            d[0]=v0.x; d[1]=v0.y; d[2]=v0.z; d[3]=v0.w;
            d[4]=v1.x; d[5]=v1.y; d[6]=v1.z; d[7]=v1.w;
        }
        __syncthreads();
#pragma unroll
        for (int k = 0; k < 32; k++) {
            float a0 = As[ty*4+0][k], a1 = As[ty*4+1][k];
            float a2 = As[ty*4+2][k], a3 = As[ty*4+3][k];
            float4 bv = *(const float4*)&Bs[k][tx*4];
            acc[0][0] += a0*bv.x; acc[0][1] += a0*bv.y; acc[0][2] += a0*bv.z; acc[0][3] += a0*bv.w;
            acc[1][0] += a1*bv.x; acc[1][1] += a1*bv.y; acc[1][2] += a1*bv.z; acc[1][3] += a1*bv.w;
            acc[2][0] += a2*bv.x; acc[2][1] += a2*bv.y; acc[2][2] += a2*bv.z; acc[2][3] += a2*bv.w;
            acc[3][0] += a3*bv.x; acc[3][1] += a3*bv.y; acc[3][2] += a3*bv.z; acc[3][3] += a3*bv.w;
        }
        __syncthreads();
    }

    float* dst = (mat == 0) ? g_q : (mat == 1) ? g_k : g_v;
#pragma unroll
    for (int i = 0; i < 4; i++) {
        int row = bm + ty*4 + i;
        int col = bn + tx*4;
        float4 v;
        v.x = acc[i][0]; v.y = acc[i][1]; v.z = acc[i][2]; v.w = acc[i][3];
        if (mat == 0) {
            v.x += seb2[col+0]; v.y += seb2[col+1];
            v.z += seb2[col+2]; v.w += seb2[col+3];
        }
        *(float4*)&dst[(size_t)row*QKH + col] = v;
    }
}

// ============================================================
// K2: attention per (b,h). 512 threads = one query row each.
// Online softmax; writes node feats + spatial feats to g_feat.
// dyn smem: k(64K) + v(64K) + posCB(6K) + mask(2K) = 139264 B
// ============================================================
__global__ void __launch_bounds__(512, 1) k_attn(
    const float* __restrict__ posCA,
    const float* __restrict__ posCB,
    const float* __restrict__ frame,
    const int*   __restrict__ mask)
{
    extern __shared__ float sm[];
    float* ks  = sm;                   // [512][32]
    float* vs  = sm + 512*32;          // [512][32]
    float* pcb = sm + 2*512*32;        // [512][3]
    int*   mk  = (int*)(sm + 2*512*32 + 512*3);  // [512]

    const int h = blockIdx.x;
    const int b = blockIdx.y;
    const int tid = threadIdx.x;

    const size_t base = ((size_t)b * LL) * QKH + h * QK;
    for (int e = tid; e < 512*32; e += 512) {
        int j = e >> 5, d = e & 31;
        ks[e] = g_k[base + (size_t)j * QKH + d];
        vs[e] = g_v[base + (size_t)j * QKH + d];
    }
    for (int e = tid; e < 512*3; e += 512) pcb[e] = posCB[(size_t)b*LL*3 + e];
    mk[tid] = mask[b*LL + tid];
    __syncthreads();

    const int row = tid;
    const size_t grow = (size_t)b * LL + row;

    // load q row into registers
    float q[32];
    {
        const float4* qp = (const float4*)(g_q + grow * QKH + h * QK);
#pragma unroll
        for (int t = 0; t < 8; t++) {
            float4 v = qp[t];
            q[4*t+0]=v.x; q[4*t+1]=v.y; q[4*t+2]=v.z; q[4*t+3]=v.w;
        }
    }

    float m = -1e30f, s = 0.0f;
    float av[32];
#pragma unroll
    for (int d = 0; d < 32; d++) av[d] = 0.0f;
    float ap0 = 0.0f, ap1 = 0.0f, ap2 = 0.0f;

    for (int j = 0; j < LL; j++) {
        if (!mk[j]) continue;
        const float4* k4 = (const float4*)(ks + j*32);
        float lg = 0.0f;
#pragma unroll
        for (int t = 0; t < 8; t++) {
            float4 kv = k4[t];
            lg += q[4*t+0]*kv.x + q[4*t+1]*kv.y + q[4*t+2]*kv.z + q[4*t+3]*kv.w;
        }
        if (lg > m) {
            float c = __expf(m - lg);
            m = lg;
            s *= c;
#pragma unroll
            for (int d = 0; d < 32; d++) av[d] *= c;
            ap0 *= c; ap1 *= c; ap2 *= c;
        }
        float p = __expf(lg - m);
        s += p;
        const float4* v4 = (const float4*)(vs + j*32);
#pragma unroll
        for (int t = 0; t < 8; t++) {
            float4 vv = v4[t];
            av[4*t+0] += p*vv.x; av[4*t+1] += p*vv.y;
            av[4*t+2] += p*vv.z; av[4*t+3] += p*vv.w;
        }
        ap0 += p * pcb[j*3+0];
        ap1 += p * pcb[j*3+1];
        ap2 += p * pcb[j*3+2];
    }

    float* fr = g_feat + grow * FEAT;
    const bool ok = (mk[row] != 0) && (s > 0.0f);
    if (!ok) {
#pragma unroll
        for (int d = 0; d < 32; d++) fr[h*32 + d] = 0.0f;
        fr[512 + h*3+0] = 0.0f; fr[512 + h*3+1] = 0.0f; fr[512 + h*3+2] = 0.0f;
        fr[560 + h] = 0.0f;
        fr[576 + h*3+0] = 0.0f; fr[576 + h*3+1] = 0.0f; fr[576 + h*3+2] = 0.0f;
        fr[624 + h] = 0.0f;
        return;
    }
    const float inv = 1.0f / s;
#pragma unroll
    for (int d = 0; d < 32; d++) av[d] *= inv;
    // apb = sum(alpha * posCB) - posCA   (since sum(alpha)=1)
    ap0 = ap0 * inv - posCA[grow*3+0];
    ap1 = ap1 * inv - posCA[grow*3+1];
    ap2 = ap2 * inv - posCA[grow*3+2];

    const float* F = frame + grow * 9;
    float pt0 = F[0]*ap0 + F[1]*ap1 + F[2]*ap2;
    float pt1 = F[3]*ap0 + F[4]*ap1 + F[5]*ap2;
    float pt2 = F[6]*ap0 + F[7]*ap1 + F[8]*ap2;

    float dist = sqrtf(ap0*ap0 + ap1*ap1 + ap2*ap2);
    float pn   = sqrtf(pt0*pt0 + pt1*pt1 + pt2*pt2);
    float id   = 1.0f / (pn + 1e-10f);
    float ang  = atan2f(pt1, pt0);

#pragma unroll
    for (int d = 0; d < 32; d++) fr[h*32 + d] = av[d];
    fr[512 + h*3+0] = pt0; fr[512 + h*3+1] = pt1; fr[512 + h*3+2] = pt2;
    fr[560 + h] = dist;
    fr[576 + h*3+0] = pt0*id; fr[576 + h*3+1] = pt1*id; fr[576 + h*3+2] = pt2*id;
    fr[624 + h] = ang;
}

// ============================================================
// K3a: h1 = relu(feat @ W1 + b1)   (4096x512, K=640)
// Same tiling as k_qkv: BM=BN=64, BK=32, 256 thr, 4x4 reg tile.
// ============================================================
__global__ void __launch_bounds__(256) k_mlp1(
    const float* __restrict__ W1, const float* __restrict__ b1)
{
    __shared__ float As[64][33];
    __shared__ float Bs[32][68];

    const int tid = threadIdx.x;
    const int ty = tid >> 4, tx = tid & 15;
    const int bm = blockIdx.x * 64;
    const int bn = blockIdx.y * 64;

    float acc[4][4];
#pragma unroll
    for (int i = 0; i < 4; i++)
#pragma unroll
        for (int j = 0; j < 4; j++) acc[i][j] = 0.0f;

    for (int ch = 0; ch < FEAT/32; ch++) {
        {
            int m  = tid >> 2;
            int k0 = (tid & 3) * 8;
            const float* p = g_feat + (size_t)(bm + m) * FEAT + ch*32 + k0;
            float4 v0 = *(const float4*)p;
            float4 v1 = *(const float4*)(p + 4);
            float* d = &As[m][k0];
            d[0]=v0.x; d[1]=v0.y; d[2]=v0.z; d[3]=v0.w;
            d[4]=v1.x; d[5]=v1.y; d[6]=v1.z; d[7]=v1.w;
        }
        {
            int k  = tid >> 3;
            int c0 = (tid & 7) * 8;
            const float* p = W1 + (size_t)(ch*32 + k) * HID + bn + c0;
            float4 v0 = *(const float4*)p;
            float4 v1 = *(const float4*)(p + 4);
            float* d = &Bs[k][c0];
            d[0]=v0.x; d[1]=v0.y; d[2]=v0.z; d[3]=v0.w;
            d[4]=v1.x; d[5]=v1.y; d[6]=v1.z; d[7]=v1.w;
        }
        __syncthreads();
#pragma unroll
        for (int k = 0; k < 32; k++) {
            float a0 = As[ty*4+0][k], a1 = As[ty*4+1][k];
            float a2 = As[ty*4+2][k], a3 = As[ty*4+3][k];
            float4 bv = *(const float4*)&Bs[k][tx*4];
            acc[0][0] += a0*bv.x; acc[0][1] += a0*bv.y; acc[0][2] += a0*bv.z; acc[0][3] += a0*bv.w;
            acc[1][0] += a1*bv.x; acc[1][1] += a1*bv.y; acc[1][2] += a1*bv.z; acc[1][3] += a1*bv.w;
            acc[2][0] += a2*bv.x; acc[2][1] += a2*bv.y; acc[2][2] += a2*bv.z; acc[2][3] += a2*bv.w;
            acc[3][0] += a3*bv.x; acc[3][1] += a3*bv.y; acc[3][2] += a3*bv.z; acc[3][3] += a3*bv.w;
        }
        __syncthreads();
    }

#pragma unroll
    for (int i = 0; i < 4; i++) {
        int row = bm + ty*4 + i;
        int col = bn + tx*4;
        float4 v;
        v.x = fmaxf(acc[i][0] + b1[col+0], 0.0f);
        v.y = fmaxf(acc[i][1] + b1[col+1], 0.0f);
        v.z = fmaxf(acc[i][2] + b1[col+2], 0.0f);
        v.w = fmaxf(acc[i][3] + b1[col+3], 0.0f);
        *(float4*)&g_h1[(size_t)row*HID + col] = v;
    }
}

// ============================================================
// K3b: y = x + mask*(h1 @ W2 + b2)   (4096x256, K=512)
// ============================================================
__global__ void __launch_bounds__(256) k_mlp2(
    const float* __restrict__ x,
    const float* __restrict__ W2, const float* __restrict__ b2,
    const int*   __restrict__ mask)
{
    __shared__ float As[64][33];
    __shared__ float Bs[32][68];

    const int tid = threadIdx.x;
    const int ty = tid >> 4, tx = tid & 15;
    const int bm = blockIdx.x * 64;
    const int bn = blockIdx.y * 64;

    float acc[4][4];
#pragma unroll
    for (int i = 0; i < 4; i++)
#pragma unroll
        for (int j = 0; j < 4; j++) acc[i][j] = 0.0f;

    for (int ch = 0; ch < HID/32; ch++) {
        {
            int m  = tid >> 2;
            int k0 = (tid & 3) * 8;
            const float* p = g_h1 + (size_t)(bm + m) * HID + ch*32 + k0;
            float4 v0 = *(const float4*)p;
            float4 v1 = *(const float4*)(p + 4);
            float* d = &As[m][k0];
            d[0]=v0.x; d[1]=v0.y; d[2]=v0.z; d[3]=v0.w;
            d[4]=v1.x; d[5]=v1.y; d[6]=v1.z; d[7]=v1.w;
        }
        {
            int k  = tid >> 3;
            int c0 = (tid & 7) * 8;
            const float* p = W2 + (size_t)(ch*32 + k) * OUTD + bn + c0;
            float4 v0 = *(const float4*)p;
            float4 v1 = *(const float4*)(p + 4);
            float* d = &Bs[k][c0];
            d[0]=v0.x; d[1]=v0.y; d[2]=v0.z; d[3]=v0.w;
            d[4]=v1.x; d[5]=v1.y; d[6]=v1.z; d[7]=v1.w;
        }
        __syncthreads();
#pragma unroll
        for (int k = 0; k < 32; k++) {
            float a0 = As[ty*4+0][k], a1 = As[ty*4+1][k];
            float a2 = As[ty*4+2][k], a3 = As[ty*4+3][k];
            float4 bv = *(const float4*)&Bs[k][tx*4];
            acc[0][0] += a0*bv.x; acc[0][1] += a0*bv.y; acc[0][2] += a0*bv.z; acc[0][3] += a0*bv.w;
            acc[1][0] += a1*bv.x; acc[1][1] += a1*bv.y; acc[1][2] += a1*bv.z; acc[1][3] += a1*bv.w;
            acc[2][0] += a2*bv.x; acc[2][1] += a2*bv.y; acc[2][2] += a2*bv.z; acc[2][3] += a2*bv.w;
            acc[3][0] += a3*bv.x; acc[3][1] += a3*bv.y; acc[3][2] += a3*bv.z; acc[3][3] += a3*bv.w;
        }
        __syncthreads();
    }

#pragma unroll
    for (int i = 0; i < 4; i++) {
        int row = bm + ty*4 + i;
        int col = bn + tx*4;
        int mk = mask[row];
        const float4 xv = *(const float4*)&x[(size_t)row*OUTD + col];
        float4 v;
        if (mk) {
            v.x = xv.x + acc[i][0] + b2[col+0];
            v.y = xv.y + acc[i][1] + b2[col+1];
            v.z = xv.z + acc[i][2] + b2[col+2];
            v.w = xv.w + acc[i][3] + b2[col+3];
        } else {
            v = xv;
        }
        *(float4*)&g_y[(size_t)row*OUTD + col] = v;
    }
}

// ============================================================
// K4: LayerNorm. One warp per row (256 cols, 8 per lane).
// ============================================================
__global__ void __launch_bounds__(256) k_ln(
    const float* __restrict__ lng, const float* __restrict__ lnb,
    float* __restrict__ out)
{
    const int wid  = threadIdx.x >> 5;
    const int lane = threadIdx.x & 31;
    const int row  = blockIdx.x * 8 + wid;

    const float* yr = g_y + (size_t)row * OUTD;
    float yv[8];
    float ssum = 0.0f, ssq = 0.0f;
#pragma unroll
    for (int t = 0; t < 2; t++) {
        float4 v = *(const float4*)&yr[lane*4 + t*128];
        yv[t*4+0]=v.x; yv[t*4+1]=v.y; yv[t*4+2]=v.z; yv[t*4+3]=v.w;
        ssum += v.x+v.y+v.z+v.w;
        ssq  += v.x*v.x+v.y*v.y+v.z*v.z+v.w*v.w;
    }
#pragma unroll
    for (int off = 16; off > 0; off >>= 1) {
        ssum += __shfl_xor_sync(0xFFFFFFFF, ssum, off);
        ssq  += __shfl_xor_sync(0xFFFFFFFF, ssq,  off);
    }
    float mu  = ssum * (1.0f / OUTD);
    float var = ssq * (1.0f / OUTD) - mu * mu;
    float rs  = rsqrtf(var + 1e-5f);
#pragma unroll
    for (int t = 0; t < 2; t++) {
        int c = lane*4 + t*128;
        float4 g = *(const float4*)&lng[c];
        float4 bb = *(const float4*)&lnb[c];
        float4 o;
        o.x = (yv[t*4+0]-mu)*rs*g.x + bb.x;
        o.y = (yv[t*4+1]-mu)*rs*g.y + bb.y;
        o.z = (yv[t*4+2]-mu)*rs*g.z + bb.z;
        o.w = (yv[t*4+3]-mu)*rs*g.w + bb.w;
        *(float4*)&out[(size_t)row*OUTD + c] = o;
    }
}

// ============================================================
extern "C" void kernel_launch(void* const* d_in, const int* in_sizes, int n_in,
                              void* d_out, int out_size)
{
    const float* x     = (const float*)d_in[0];
    const float* posCA = (const float*)d_in[1];
    const float* posCB = (const float*)d_in[2];
    const float* frame = (const float*)d_in[3];
    const int*   mask  = (const int*)  d_in[4];
    const float* Wq    = (const float*)d_in[5];
    const float* Wk    = (const float*)d_in[6];
    const float* Wv    = (const float*)d_in[7];
    const float* seW1  = (const float*)d_in[8];
    const float* seb1  = (const float*)d_in[9];
    const float* seW2  = (const float*)d_in[10];
    const float* seb2  = (const float*)d_in[11];
    const float* otW1  = (const float*)d_in[12];
    const float* otb1  = (const float*)d_in[13];
    const float* otW2  = (const float*)d_in[14];
    const float* otb2  = (const float*)d_in[15];
    const float* lng   = (const float*)d_in[16];
    const float* lnb   = (const float*)d_in[17];
    float* out = (float*)d_out;

    const int smem_attn = (2*512*32 + 512*3 + 512) * 4;   // 139264
    cudaFuncSetAttribute(k_attn, cudaFuncAttributeMaxDynamicSharedMemorySize, smem_attn);

    k_spat<<<NL/128, 128>>>(posCA, seW1, seb1);
    k_qkv<<<dim3(NL/64, (3*QKH)/64), 256>>>(x, Wq, Wk, Wv, seW2, seb2);
    k_attn<<<dim3(HH, NB), 512, smem_attn>>>(posCA, posCB, frame, mask);
    k_mlp1<<<dim3(NL/64, HID/64),  256>>>(otW1, otb1);
    k_mlp2<<<dim3(NL/64, OUTD/64), 256>>>(x, otW2, otb2, mask);
    k_ln<<<NL/8, 256>>>(lng, lnb, out);
}

// round 3
// speedup vs baseline: 1.4895x; 1.1133x over previous
#include <cuda_runtime.h>
#include <math.h>
#include <stdint.h>

// ---------------- problem constants ----------------
#define NB   8
#define LL   512
#define DD   256
#define HH   16
#define QK   32
#define VD   32
#define OUTD 256
#define NL   (NB*LL)          // 4096
#define QKH  (QK*HH)          // 512
#define FEAT 640              // 512 node + 128 spatial
#define HID  512              // OUT*2

typedef unsigned long long ull;

// ---------------- f32x2 packed math (sm_100+) ----------------
__device__ __forceinline__ ull ff2(ull a, ull b, ull c) {
    ull d;
    asm("fma.rn.f32x2 %0, %1, %2, %3;" : "=l"(d) : "l"(a), "l"(b), "l"(c));
    return d;
}
__device__ __forceinline__ ull add2(ull a, ull b) {
    ull d;
    asm("add.rn.f32x2 %0, %1, %2;" : "=l"(d) : "l"(a), "l"(b));
    return d;
}
__device__ __forceinline__ ull pk2(float lo, float hi) {
    ull d;
    asm("mov.b64 %0, {%1, %2};" : "=l"(d) : "f"(lo), "f"(hi));
    return d;
}
__device__ __forceinline__ float2 up2(ull v) {
    float lo, hi;
    asm("mov.b64 {%0, %1}, %2;" : "=f"(lo), "=f"(hi) : "l"(v));
    return make_float2(lo, hi);
}

// ---------------- scratch (no allocs allowed) ----------------
__device__ float g_q[(size_t)NL*QKH];
__device__ float g_k[(size_t)NL*QKH];
__device__ float g_v[(size_t)NL*QKH];
__device__ float g_t[(size_t)NL*QK];
__device__ float g_feat[(size_t)NL*FEAT];
__device__ float g_h1[(size_t)NL*HID];
__device__ float g_y[(size_t)NL*OUTD];

// ============================================================
// K0: t = relu(pos_CA @ se_W1 + se_b1)   (4096 x 32)
// ============================================================
__global__ void k_spat(const float* __restrict__ posCA,
                       const float* __restrict__ seW1,
                       const float* __restrict__ seb1)
{
    int r = blockIdx.x * blockDim.x + threadIdx.x;
    if (r >= NL) return;
    float p0 = posCA[r*3+0], p1 = posCA[r*3+1], p2 = posCA[r*3+2];
#pragma unroll
    for (int j = 0; j < QK; j++) {
        float v = seb1[j] + p0*seW1[j] + p1*seW1[QK + j] + p2*seW1[2*QK + j];
        g_t[(size_t)r*QK + j] = fmaxf(v, 0.0f);
    }
}

// ============================================================
// GEMM tile macros: BM=128, BN=64, BK=32, 256 threads,
// per-thread 8(M)x4(N) via f32x2 (4 packed M-pairs x 4 N).
// As stored TRANSPOSED: As[k][m] (132-float rows, 16B aligned).
// ============================================================
#define GEMM_DECL                                                    \
    __shared__ float As[32][132];                                    \
    __shared__ float Bs[32][68];                                     \
    const int tid = threadIdx.x;                                     \
    const int ty = tid >> 4, tx = tid & 15;                          \
    const int m0 = ty * 8, n0 = tx * 4;                              \
    const int am = tid & 127, kh = (tid >> 7) * 16;                  \
    ull acc[4][4];                                                   \
    _Pragma("unroll") for (int i = 0; i < 4; i++)                    \
    _Pragma("unroll") for (int j = 0; j < 4; j++) acc[i][j] = 0ULL;

#define GEMM_LOAD_A(Aptr, lda, kc)                                   \
    {                                                                \
        const float* p = (Aptr) + (size_t)(bm + am) * (lda) + (kc) + kh; \
        float4 v0 = *(const float4*)p;                               \
        float4 v1 = *(const float4*)(p + 4);                         \
        float4 v2 = *(const float4*)(p + 8);                         \
        float4 v3 = *(const float4*)(p + 12);                        \
        As[kh+ 0][am]=v0.x; As[kh+ 1][am]=v0.y; As[kh+ 2][am]=v0.z; As[kh+ 3][am]=v0.w; \
        As[kh+ 4][am]=v1.x; As[kh+ 5][am]=v1.y; As[kh+ 6][am]=v1.z; As[kh+ 7][am]=v1.w; \
        As[kh+ 8][am]=v2.x; As[kh+ 9][am]=v2.y; As[kh+10][am]=v2.z; As[kh+11][am]=v2.w; \
        As[kh+12][am]=v3.x; As[kh+13][am]=v3.y; As[kh+14][am]=v3.z; As[kh+15][am]=v3.w; \
    }

#define GEMM_LOAD_B(Bptr, ldb, bk)                                   \
    {                                                                \
        int k  = tid >> 3;                                           \
        int c0 = (tid & 7) * 8;                                      \
        const float* p = (Bptr) + (size_t)((bk) + k) * (ldb) + bn + c0; \
        float4 v0 = *(const float4*)p;                               \
        float4 v1 = *(const float4*)(p + 4);                         \
        float* d = &Bs[k][c0];                                       \
        d[0]=v0.x; d[1]=v0.y; d[2]=v0.z; d[3]=v0.w;                  \
        d[4]=v1.x; d[5]=v1.y; d[6]=v1.z; d[7]=v1.w;                  \
    }

#define GEMM_MAIN                                                    \
    _Pragma("unroll")                                                \
    for (int k = 0; k < 32; k++) {                                   \
        ulonglong2 aA = *(const ulonglong2*)&As[k][m0];              \
        ulonglong2 aB = *(const ulonglong2*)&As[k][m0 + 4];          \
        float4 bv = *(const float4*)&Bs[k][n0];                      \
        ull b0 = pk2(bv.x, bv.x), b1 = pk2(bv.y, bv.y);              \
        ull b2 = pk2(bv.z, bv.z), b3 = pk2(bv.w, bv.w);              \
        acc[0][0]=ff2(aA.x,b0,acc[0][0]); acc[0][1]=ff2(aA.x,b1,acc[0][1]); \
        acc[0][2]=ff2(aA.x,b2,acc[0][2]); acc[0][3]=ff2(aA.x,b3,acc[0][3]); \
        acc[1][0]=ff2(aA.y,b0,acc[1][0]); acc[1][1]=ff2(aA.y,b1,acc[1][1]); \
        acc[1][2]=ff2(aA.y,b2,acc[1][2]); acc[1][3]=ff2(aA.y,b3,acc[1][3]); \
        acc[2][0]=ff2(aB.x,b0,acc[2][0]); acc[2][1]=ff2(aB.x,b1,acc[2][1]); \
        acc[2][2]=ff2(aB.x,b2,acc[2][2]); acc[2][3]=ff2(aB.x,b3,acc[2][3]); \
        acc[3][0]=ff2(aB.y,b0,acc[3][0]); acc[3][1]=ff2(aB.y,b1,acc[3][1]); \
        acc[3][2]=ff2(aB.y,b2,acc[3][2]); acc[3][3]=ff2(aB.y,b3,acc[3][3]); \
    }

// ============================================================
// K1: fused QKV projection GEMM (4096 x 1536, K=256; q adds
// extra chunk t(4096x32)@se_W2 + se_b2)
// ============================================================
__global__ void __launch_bounds__(256) k_qkv(
    const float* __restrict__ x,
    const float* __restrict__ Wq, const float* __restrict__ Wk,
    const float* __restrict__ Wv,
    const float* __restrict__ seW2, const float* __restrict__ seb2)
{
    const int bm = blockIdx.x * 128;
    const int gcol = blockIdx.y * 64;
    const int mat = gcol / QKH;              // 0=q 1=k 2=v
    const int bn = gcol - mat * QKH;
    const float* W = (mat == 0) ? Wq : (mat == 1) ? Wk : Wv;

    GEMM_DECL

    const int nchunks = (mat == 0) ? 9 : 8;
    for (int ch = 0; ch < nchunks; ch++) {
        if (ch < 8) { GEMM_LOAD_A(x, DD, ch*32) }
        else        { GEMM_LOAD_A(g_t, QK, 0) }
        if (ch < 8) { GEMM_LOAD_B(W, QKH, ch*32) }
        else        { GEMM_LOAD_B(seW2, QKH, 0) }
        __syncthreads();
        GEMM_MAIN
        __syncthreads();
    }

    float* dst = (mat == 0) ? g_q : (mat == 1) ? g_k : g_v;
    float4 qb = make_float4(0.f, 0.f, 0.f, 0.f);
    if (mat == 0) qb = *(const float4*)&seb2[bn + n0];
#pragma unroll
    for (int mp = 0; mp < 4; mp++) {
        float2 c0 = up2(acc[mp][0]), c1 = up2(acc[mp][1]);
        float2 c2 = up2(acc[mp][2]), c3 = up2(acc[mp][3]);
        int r0 = bm + m0 + 2*mp;
        float4 v0 = make_float4(c0.x + qb.x, c1.x + qb.y, c2.x + qb.z, c3.x + qb.w);
        float4 v1 = make_float4(c0.y + qb.x, c1.y + qb.y, c2.y + qb.z, c3.y + qb.w);
        *(float4*)&dst[(size_t)r0*QKH + bn + n0]     = v0;
        *(float4*)&dst[(size_t)(r0+1)*QKH + bn + n0] = v1;
    }
}

// ============================================================
// K2: attention per (b,h). 512 threads = one query row each.
// f32x2 packed dot + alpha*V; no max-subtraction (logits O(1)).
// ============================================================
__global__ void __launch_bounds__(512, 1) k_attn(
    const float* __restrict__ posCA,
    const float* __restrict__ posCB,
    const float* __restrict__ frame,
    const int*   __restrict__ mask)
{
    extern __shared__ float sm[];
    float* ks   = sm;                      // [512][32]
    float* vs   = sm + 512*32;             // [512][32]
    float* pcb4 = sm + 2*512*32;           // [512][4] (xy pair 8B-aligned)
    int*   mk   = (int*)(sm + 2*512*32 + 512*4);  // [512]

    const int h = blockIdx.x;
    const int b = blockIdx.y;
    const int tid = threadIdx.x;

    const size_t base = ((size_t)b * LL) * QKH + h * QK;
    for (int e = tid; e < 512*32; e += 512) {
        int j = e >> 5, d = e & 31;
        ks[e] = g_k[base + (size_t)j * QKH + d];
        vs[e] = g_v[base + (size_t)j * QKH + d];
    }
    {
        const float* pb = posCB + (size_t)b*LL*3 + tid*3;
        pcb4[tid*4+0] = pb[0]; pcb4[tid*4+1] = pb[1];
        pcb4[tid*4+2] = pb[2]; pcb4[tid*4+3] = 0.0f;
        mk[tid] = mask[b*LL + tid];
    }
    __syncthreads();

    const int row = tid;
    const size_t grow = (size_t)b * LL + row;

    // q row as 16 packed pairs
    ull q2[16];
    {
        const ulonglong2* qp = (const ulonglong2*)(g_q + grow * QKH + h * QK);
#pragma unroll
        for (int t = 0; t < 8; t++) {
            ulonglong2 v = qp[t];
            q2[2*t] = v.x; q2[2*t+1] = v.y;
        }
    }

    float s = 0.0f;
    ull av2[16];
#pragma unroll
    for (int d = 0; d < 16; d++) av2[d] = 0ULL;
    ull ap01 = 0ULL;
    float ap2 = 0.0f;

    for (int j = 0; j < LL; j++) {
        if (!mk[j]) continue;
        const ulonglong2* k4 = (const ulonglong2*)(ks + j*32);
        ull d0 = 0ULL, d1 = 0ULL, d2 = 0ULL, d3 = 0ULL;
#pragma unroll
        for (int t = 0; t < 8; t += 2) {
            ulonglong2 ka = k4[t];
            ulonglong2 kb = k4[t+1];
            d0 = ff2(q2[2*t],   ka.x, d0);
            d1 = ff2(q2[2*t+1], ka.y, d1);
            d2 = ff2(q2[2*t+2], kb.x, d2);
            d3 = ff2(q2[2*t+3], kb.y, d3);
        }
        ull dd = add2(add2(d0, d2), add2(d1, d3));
        float2 df = up2(dd);
        float p = __expf(df.x + df.y);
        s += p;
        ull p2 = pk2(p, p);
        const ulonglong2* v4 = (const ulonglong2*)(vs + j*32);
#pragma unroll
        for (int t = 0; t < 8; t++) {
            ulonglong2 vv = v4[t];
            av2[2*t]   = ff2(p2, vv.x, av2[2*t]);
            av2[2*t+1] = ff2(p2, vv.y, av2[2*t+1]);
        }
        ull pxy = *(const ull*)&pcb4[j*4];
        ap01 = ff2(p2, pxy, ap01);
        ap2 += p * pcb4[j*4+2];
    }

    float* fr = g_feat + grow * FEAT;
    const bool ok = (mk[row] != 0) && (s > 0.0f);
    if (!ok) {
#pragma unroll
        for (int d = 0; d < 32; d++) fr[h*32 + d] = 0.0f;
        fr[512 + h*3+0] = 0.0f; fr[512 + h*3+1] = 0.0f; fr[512 + h*3+2] = 0.0f;
        fr[560 + h] = 0.0f;
        fr[576 + h*3+0] = 0.0f; fr[576 + h*3+1] = 0.0f; fr[576 + h*3+2] = 0.0f;
        fr[624 + h] = 0.0f;
        return;
    }
    const float inv = 1.0f / s;
    float2 apxy = up2(ap01);
    float a0 = apxy.x * inv - posCA[grow*3+0];
    float a1 = apxy.y * inv - posCA[grow*3+1];
    float a2 = ap2    * inv - posCA[grow*3+2];

    const float* F = frame + grow * 9;
    float pt0 = F[0]*a0 + F[1]*a1 + F[2]*a2;
    float pt1 = F[3]*a0 + F[4]*a1 + F[5]*a2;
    float pt2 = F[6]*a0 + F[7]*a1 + F[8]*a2;

    float dist = sqrtf(a0*a0 + a1*a1 + a2*a2);
    float pn   = sqrtf(pt0*pt0 + pt1*pt1 + pt2*pt2);
    float id   = 1.0f / (pn + 1e-10f);
    float ang  = atan2f(pt1, pt0);

#pragma unroll
    for (int t = 0; t < 16; t++) {
        float2 v = up2(av2[t]);
        fr[h*32 + 2*t]   = v.x * inv;
        fr[h*32 + 2*t+1] = v.y * inv;
    }
    fr[512 + h*3+0] = pt0; fr[512 + h*3+1] = pt1; fr[512 + h*3+2] = pt2;
    fr[560 + h] = dist;
    fr[576 + h*3+0] = pt0*id; fr[576 + h*3+1] = pt1*id; fr[576 + h*3+2] = pt2*id;
    fr[624 + h] = ang;
}

// ============================================================
// K3a: h1 = relu(feat @ W1 + b1)   (4096x512, K=640)
// ============================================================
__global__ void __launch_bounds__(256) k_mlp1(
    const float* __restrict__ W1, const float* __restrict__ b1)
{
    const int bm = blockIdx.x * 128;
    const int bn = blockIdx.y * 64;

    GEMM_DECL

    for (int ch = 0; ch < FEAT/32; ch++) {
        GEMM_LOAD_A(g_feat, FEAT, ch*32)
        GEMM_LOAD_B(W1, HID, ch*32)
        __syncthreads();
        GEMM_MAIN
        __syncthreads();
    }

    const float4 bb = *(const float4*)&b1[bn + n0];
#pragma unroll
    for (int mp = 0; mp < 4; mp++) {
        float2 c0 = up2(acc[mp][0]), c1 = up2(acc[mp][1]);
        float2 c2 = up2(acc[mp][2]), c3 = up2(acc[mp][3]);
        int r0 = bm + m0 + 2*mp;
        float4 v0 = make_float4(fmaxf(c0.x + bb.x, 0.f), fmaxf(c1.x + bb.y, 0.f),
                                fmaxf(c2.x + bb.z, 0.f), fmaxf(c3.x + bb.w, 0.f));
        float4 v1 = make_float4(fmaxf(c0.y + bb.x, 0.f), fmaxf(c1.y + bb.y, 0.f),
                                fmaxf(c2.y + bb.z, 0.f), fmaxf(c3.y + bb.w, 0.f));
        *(float4*)&g_h1[(size_t)r0*HID + bn + n0]     = v0;
        *(float4*)&g_h1[(size_t)(r0+1)*HID + bn + n0] = v1;
    }
}

// ============================================================
// K3b: y = x + mask*(h1 @ W2 + b2)   (4096x256, K=512)
// ============================================================
__global__ void __launch_bounds__(256) k_mlp2(
    const float* __restrict__ x,
    const float* __restrict__ W2, const float* __restrict__ b2,
    const int*   __restrict__ mask)
{
    const int bm = blockIdx.x * 128;
    const int bn = blockIdx.y * 64;

    GEMM_DECL

    for (int ch = 0; ch < HID/32; ch++) {
        GEMM_LOAD_A(g_h1, HID, ch*32)
        GEMM_LOAD_B(W2, OUTD, ch*32)
        __syncthreads();
        GEMM_MAIN
        __syncthreads();
    }

    const float4 bb = *(const float4*)&b2[bn + n0];
#pragma unroll
    for (int mp = 0; mp < 4; mp++) {
        float2 c0 = up2(acc[mp][0]), c1 = up2(acc[mp][1]);
        float2 c2 = up2(acc[mp][2]), c3 = up2(acc[mp][3]);
        int r0 = bm + m0 + 2*mp;
#pragma unroll
        for (int rr = 0; rr < 2; rr++) {
            int r = r0 + rr;
            const float4 xv = *(const float4*)&x[(size_t)r*OUTD + bn + n0];
            float4 v;
            if (mask[r]) {
                float o0 = rr ? c0.y : c0.x, o1 = rr ? c1.y : c1.x;
                float o2 = rr ? c2.y : c2.x, o3 = rr ? c3.y : c3.x;
                v = make_float4(xv.x + o0 + bb.x, xv.y + o1 + bb.y,
                                xv.z + o2 + bb.z, xv.w + o3 + bb.w);
            } else {
                v = xv;
            }
            *(float4*)&g_y[(size_t)r*OUTD + bn + n0] = v;
        }
    }
}

// ============================================================
// K4: LayerNorm. One warp per row (256 cols, 8 per lane).
// ============================================================
__global__ void __launch_bounds__(256) k_ln(
    const float* __restrict__ lng, const float* __restrict__ lnb,
    float* __restrict__ out)
{
    const int wid  = threadIdx.x >> 5;
    const int lane = threadIdx.x & 31;
    const int row  = blockIdx.x * 8 + wid;

    const float* yr = g_y + (size_t)row * OUTD;
    float yv[8];
    float ssum = 0.0f, ssq = 0.0f;
#pragma unroll
    for (int t = 0; t < 2; t++) {
        float4 v = *(const float4*)&yr[lane*4 + t*128];
        yv[t*4+0]=v.x; yv[t*4+1]=v.y; yv[t*4+2]=v.z; yv[t*4+3]=v.w;
        ssum += v.x+v.y+v.z+v.w;
        ssq  += v.x*v.x+v.y*v.y+v.z*v.z+v.w*v.w;
    }
#pragma unroll
    for (int off = 16; off > 0; off >>= 1) {
        ssum += __shfl_xor_sync(0xFFFFFFFF, ssum, off);
        ssq  += __shfl_xor_sync(0xFFFFFFFF, ssq,  off);
    }
    float mu  = ssum * (1.0f / OUTD);
    float var = ssq * (1.0f / OUTD) - mu * mu;
    float rs  = rsqrtf(var + 1e-5f);
#pragma unroll
    for (int t = 0; t < 2; t++) {
        int c = lane*4 + t*128;
        float4 g = *(const float4*)&lng[c];
        float4 bb = *(const float4*)&lnb[c];
        float4 o;
        o.x = (yv[t*4+0]-mu)*rs*g.x + bb.x;
        o.y = (yv[t*4+1]-mu)*rs*g.y + bb.y;
        o.z = (yv[t*4+2]-mu)*rs*g.z + bb.z;
        o.w = (yv[t*4+3]-mu)*rs*g.w + bb.w;
        *(float4*)&out[(size_t)row*OUTD + c] = o;
    }
}

// ============================================================
extern "C" void kernel_launch(void* const* d_in, const int* in_sizes, int n_in,
                              void* d_out, int out_size)
{
    const float* x     = (const float*)d_in[0];
    const float* posCA = (const float*)d_in[1];
    const float* posCB = (const float*)d_in[2];
    const float* frame = (const float*)d_in[3];
    const int*   mask  = (const int*)  d_in[4];
    const float* Wq    = (const float*)d_in[5];
    const float* Wk    = (const float*)d_in[6];
    const float* Wv    = (const float*)d_in[7];
    const float* seW1  = (const float*)d_in[8];
    const float* seb1  = (const float*)d_in[9];
    const float* seW2  = (const float*)d_in[10];
    const float* seb2  = (const float*)d_in[11];
    const float* otW1  = (const float*)d_in[12];
    const float* otb1  = (const float*)d_in[13];
    const float* otW2  = (const float*)d_in[14];
    const float* otb2  = (const float*)d_in[15];
    const float* lng   = (const float*)d_in[16];
    const float* lnb   = (const float*)d_in[17];
    float* out = (float*)d_out;

    const int smem_attn = (2*512*32 + 512*4) * 4 + 512*4;   // 141312
    cudaFuncSetAttribute(k_attn, cudaFuncAttributeMaxDynamicSharedMemorySize, smem_attn);

    k_spat<<<NL/128, 128>>>(posCA, seW1, seb1);
    k_qkv<<<dim3(NL/128, (3*QKH)/64), 256>>>(x, Wq, Wk, Wv, seW2, seb2);
    k_attn<<<dim3(HH, NB), 512, smem_attn>>>(posCA, posCB, frame, mask);
    k_mlp1<<<dim3(NL/128, HID/64),  256>>>(otW1, otb1);
    k_mlp2<<<dim3(NL/128, OUTD/64), 256>>>(x, otW2, otb2, mask);
    k_ln<<<NL/8, 256>>>(lng, lnb, out);
}

// round 4
// speedup vs baseline: 2.0169x; 1.3541x over previous
#include <cuda_runtime.h>
#include <math.h>
#include <stdint.h>

// ---------------- problem constants ----------------
#define NB   8
#define LL   512
#define DD   256
#define HH   16
#define QK   32
#define VD   32
#define OUTD 256
#define NL   (NB*LL)          // 4096
#define QKH  (QK*HH)          // 512
#define FEAT 640              // 512 node + 128 spatial
#define HID  512              // OUT*2

typedef unsigned long long ull;

// ---------------- f32x2 helpers (attention kernel) ----------------
__device__ __forceinline__ ull ff2(ull a, ull b, ull c) {
    ull d;
    asm("fma.rn.f32x2 %0, %1, %2, %3;" : "=l"(d) : "l"(a), "l"(b), "l"(c));
    return d;
}
__device__ __forceinline__ ull add2(ull a, ull b) {
    ull d;
    asm("add.rn.f32x2 %0, %1, %2;" : "=l"(d) : "l"(a), "l"(b));
    return d;
}
__device__ __forceinline__ ull pk2(float lo, float hi) {
    ull d;
    asm("mov.b64 %0, {%1, %2};" : "=l"(d) : "f"(lo), "f"(hi));
    return d;
}
__device__ __forceinline__ float2 up2(ull v) {
    float lo, hi;
    asm("mov.b64 {%0, %1}, %2;" : "=f"(lo), "=f"(hi) : "l"(v));
    return make_float2(lo, hi);
}

// ---------------- tf32 helpers ----------------
__device__ __forceinline__ uint32_t to_tf32(float f) {
    uint32_t u;
    asm("cvt.rna.tf32.f32 %0, %1;" : "=r"(u) : "f"(f));
    return u;
}
__device__ __forceinline__ void mma_tf32(float c[4],
                                         uint32_t a0, uint32_t a1, uint32_t a2, uint32_t a3,
                                         uint32_t b0, uint32_t b1) {
    asm volatile("mma.sync.aligned.m16n8k8.row.col.f32.tf32.tf32.f32 "
                 "{%0,%1,%2,%3}, {%4,%5,%6,%7}, {%8,%9}, {%0,%1,%2,%3};"
                 : "+f"(c[0]), "+f"(c[1]), "+f"(c[2]), "+f"(c[3])
                 : "r"(a0), "r"(a1), "r"(a2), "r"(a3), "r"(b0), "r"(b1));
}

// ---------------- scratch (no allocs allowed) ----------------
__device__ float g_q[(size_t)NL*QKH];
__device__ float g_k[(size_t)NL*QKH];
__device__ float g_v[(size_t)NL*QKH];
__device__ float g_t[(size_t)NL*QK];
__device__ float g_feat[(size_t)NL*FEAT];
__device__ float g_h1[(size_t)NL*HID];
__device__ float g_y[(size_t)NL*OUTD];

// ============================================================
// K0: t = relu(pos_CA @ se_W1 + se_b1)   (4096 x 32)
// ============================================================
__global__ void k_spat(const float* __restrict__ posCA,
                       const float* __restrict__ seW1,
                       const float* __restrict__ seb1)
{
    int r = blockIdx.x * blockDim.x + threadIdx.x;
    if (r >= NL) return;
    float p0 = posCA[r*3+0], p1 = posCA[r*3+1], p2 = posCA[r*3+2];
#pragma unroll
    for (int j = 0; j < QK; j++) {
        float v = seb1[j] + p0*seW1[j] + p1*seW1[QK + j] + p2*seW1[2*QK + j];
        g_t[(size_t)r*QK + j] = fmaxf(v, 0.0f);
    }
}

// ============================================================
// tf32 warp-MMA GEMM building blocks.
// Block tile 128x64, BK=32, 256 threads = 8 warps (2M x 4N),
// warp tile 64x16 = 4 m16-tiles x 2 n8-tiles.
// As: [128][36] tf32 bits  (stride 36 -> frag loads conflict-free)
// Bs: [32][68]  tf32 bits  (natural [k][n]; coalesced store)
// ============================================================
__device__ __forceinline__ void load_chunkA(uint32_t (*As)[36], const float* A,
                                            int lda, int bm, int kc, int tid)
{
    int r  = tid >> 1;
    int c0 = (tid & 1) * 16;
    const float* p = A + (size_t)(bm + r) * lda + kc + c0;
    float4 v0 = *(const float4*)p;
    float4 v1 = *(const float4*)(p + 4);
    float4 v2 = *(const float4*)(p + 8);
    float4 v3 = *(const float4*)(p + 12);
    uint32_t* d = &As[r][c0];
    d[0]=to_tf32(v0.x); d[1]=to_tf32(v0.y); d[2]=to_tf32(v0.z); d[3]=to_tf32(v0.w);
    d[4]=to_tf32(v1.x); d[5]=to_tf32(v1.y); d[6]=to_tf32(v1.z); d[7]=to_tf32(v1.w);
    d[8]=to_tf32(v2.x); d[9]=to_tf32(v2.y); d[10]=to_tf32(v2.z); d[11]=to_tf32(v2.w);
    d[12]=to_tf32(v3.x); d[13]=to_tf32(v3.y); d[14]=to_tf32(v3.z); d[15]=to_tf32(v3.w);
}

__device__ __forceinline__ void load_chunkB(uint32_t (*Bs)[68], const float* B,
                                            int ldb, int bn, int kc, int tid)
{
    int kk = tid >> 3;
    int c0 = (tid & 7) * 8;
    const float* p = B + (size_t)(kc + kk) * ldb + bn + c0;
    float4 v0 = *(const float4*)p;
    float4 v1 = *(const float4*)(p + 4);
    uint32_t* d = &Bs[kk][c0];
    d[0]=to_tf32(v0.x); d[1]=to_tf32(v0.y); d[2]=to_tf32(v0.z); d[3]=to_tf32(v0.w);
    d[4]=to_tf32(v1.x); d[5]=to_tf32(v1.y); d[6]=to_tf32(v1.z); d[7]=to_tf32(v1.w);
}

__device__ __forceinline__ void mma_chunk(const uint32_t (*As)[36], const uint32_t (*Bs)[68],
                                          float acc[4][2][4], int warpM, int warpN,
                                          int g, int t4)
{
#pragma unroll
    for (int ks = 0; ks < 4; ks++) {
        const int k0 = ks * 8;
        uint32_t b[2][2];
#pragma unroll
        for (int nt = 0; nt < 2; nt++) {
            int nc = warpN * 16 + nt * 8 + g;
            b[nt][0] = Bs[k0 + t4][nc];
            b[nt][1] = Bs[k0 + t4 + 4][nc];
        }
#pragma unroll
        for (int mt = 0; mt < 4; mt++) {
            int mr = warpM * 64 + mt * 16;
            uint32_t a0 = As[mr + g][k0 + t4];
            uint32_t a1 = As[mr + g + 8][k0 + t4];
            uint32_t a2 = As[mr + g][k0 + t4 + 4];
            uint32_t a3 = As[mr + g + 8][k0 + t4 + 4];
#pragma unroll
            for (int nt = 0; nt < 2; nt++)
                mma_tf32(acc[mt][nt], a0, a1, a2, a3, b[nt][0], b[nt][1]);
        }
    }
}

#define GEMM_PROLOG                                                  \
    __shared__ uint32_t As[128][36];                                 \
    __shared__ uint32_t Bs[32][68];                                  \
    const int tid  = threadIdx.x;                                    \
    const int wid  = tid >> 5;                                       \
    const int lane = tid & 31;                                       \
    const int g    = lane >> 2, t4 = lane & 3;                       \
    const int warpM = wid >> 2, warpN = wid & 3;                     \
    float acc[4][2][4];                                              \
    _Pragma("unroll") for (int i = 0; i < 4; i++)                    \
    _Pragma("unroll") for (int j = 0; j < 2; j++)                    \
    _Pragma("unroll") for (int q = 0; q < 4; q++) acc[i][j][q] = 0.0f;

// ============================================================
// K1: fused QKV projection (4096 x 1536, K=256; q adds
// t(4096x32)@se_W2 + se_b2)
// ============================================================
__global__ void __launch_bounds__(256) k_qkv(
    const float* __restrict__ x,
    const float* __restrict__ Wq, const float* __restrict__ Wk,
    const float* __restrict__ Wv,
    const float* __restrict__ seW2, const float* __restrict__ seb2)
{
    const int bm  = blockIdx.x * 128;
    const int mat = blockIdx.y >> 3;           // 0=q 1=k 2=v
    const int bn  = (blockIdx.y & 7) * 64;
    const float* W = (mat == 0) ? Wq : (mat == 1) ? Wk : Wv;

    GEMM_PROLOG

    const int nchunks = (mat == 0) ? 9 : 8;
    for (int ch = 0; ch < nchunks; ch++) {
        if (ch < 8) { load_chunkA(As, x,   DD, bm, ch*32, tid); load_chunkB(Bs, W,    QKH, bn, ch*32, tid); }
        else        { load_chunkA(As, g_t, QK, bm, 0,     tid); load_chunkB(Bs, seW2, QKH, bn, 0,     tid); }
        __syncthreads();
        mma_chunk(As, Bs, acc, warpM, warpN, g, t4);
        __syncthreads();
    }

    float* dst = (mat == 0) ? g_q : (mat == 1) ? g_k : g_v;
#pragma unroll
    for (int mt = 0; mt < 4; mt++) {
#pragma unroll
        for (int nt = 0; nt < 2; nt++) {
            int R0 = bm + warpM*64 + mt*16 + g;
            int C  = bn + warpN*16 + nt*8 + 2*t4;
            float bx = 0.f, by = 0.f;
            if (mat == 0) { bx = seb2[C]; by = seb2[C+1]; }
            float2 v0 = make_float2(acc[mt][nt][0] + bx, acc[mt][nt][1] + by);
            float2 v1 = make_float2(acc[mt][nt][2] + bx, acc[mt][nt][3] + by);
            *(float2*)&dst[(size_t)R0*QKH + C]       = v0;
            *(float2*)&dst[(size_t)(R0+8)*QKH + C]   = v1;
        }
    }
}

// ============================================================
// K2: attention per (b,h). 512 threads = one query row each.
// (unchanged from R3 — fp32, proven)
// ============================================================
__global__ void __launch_bounds__(512, 1) k_attn(
    const float* __restrict__ posCA,
    const float* __restrict__ posCB,
    const float* __restrict__ frame,
    const int*   __restrict__ mask)
{
    extern __shared__ float sm[];
    float* ks   = sm;                      // [512][32]
    float* vs   = sm + 512*32;             // [512][32]
    float* pcb4 = sm + 2*512*32;           // [512][4]
    int*   mk   = (int*)(sm + 2*512*32 + 512*4);  // [512]

    const int h = blockIdx.x;
    const int b = blockIdx.y;
    const int tid = threadIdx.x;

    const size_t base = ((size_t)b * LL) * QKH + h * QK;
    for (int e = tid; e < 512*32; e += 512) {
        int j = e >> 5, d = e & 31;
        ks[e] = g_k[base + (size_t)j * QKH + d];
        vs[e] = g_v[base + (size_t)j * QKH + d];
    }
    {
        const float* pb = posCB + (size_t)b*LL*3 + tid*3;
        pcb4[tid*4+0] = pb[0]; pcb4[tid*4+1] = pb[1];
        pcb4[tid*4+2] = pb[2]; pcb4[tid*4+3] = 0.0f;
        mk[tid] = mask[b*LL + tid];
    }
    __syncthreads();

    const int row = tid;
    const size_t grow = (size_t)b * LL + row;

    ull q2[16];
    {
        const ulonglong2* qp = (const ulonglong2*)(g_q + grow * QKH + h * QK);
#pragma unroll
        for (int t = 0; t < 8; t++) {
            ulonglong2 v = qp[t];
            q2[2*t] = v.x; q2[2*t+1] = v.y;
        }
    }

    float s = 0.0f;
    ull av2[16];
#pragma unroll
    for (int d = 0; d < 16; d++) av2[d] = 0ULL;
    ull ap01 = 0ULL;
    float ap2 = 0.0f;

    for (int j = 0; j < LL; j++) {
        if (!mk[j]) continue;
        const ulonglong2* k4 = (const ulonglong2*)(ks + j*32);
        ull d0 = 0ULL, d1 = 0ULL, d2 = 0ULL, d3 = 0ULL;
#pragma unroll
        for (int t = 0; t < 8; t += 2) {
            ulonglong2 ka = k4[t];
            ulonglong2 kb = k4[t+1];
            d0 = ff2(q2[2*t],   ka.x, d0);
            d1 = ff2(q2[2*t+1], ka.y, d1);
            d2 = ff2(q2[2*t+2], kb.x, d2);
            d3 = ff2(q2[2*t+3], kb.y, d3);
        }
        ull dd = add2(add2(d0, d2), add2(d1, d3));
        float2 df = up2(dd);
        float p = __expf(df.x + df.y);
        s += p;
        ull p2 = pk2(p, p);
        const ulonglong2* v4 = (const ulonglong2*)(vs + j*32);
#pragma unroll
        for (int t = 0; t < 8; t++) {
            ulonglong2 vv = v4[t];
            av2[2*t]   = ff2(p2, vv.x, av2[2*t]);
            av2[2*t+1] = ff2(p2, vv.y, av2[2*t+1]);
        }
        ull pxy = *(const ull*)&pcb4[j*4];
        ap01 = ff2(p2, pxy, ap01);
        ap2 += p * pcb4[j*4+2];
    }

    float* fr = g_feat + grow * FEAT;
    const bool ok = (mk[row] != 0) && (s > 0.0f);
    if (!ok) {
#pragma unroll
        for (int d = 0; d < 32; d++) fr[h*32 + d] = 0.0f;
        fr[512 + h*3+0] = 0.0f; fr[512 + h*3+1] = 0.0f; fr[512 + h*3+2] = 0.0f;
        fr[560 + h] = 0.0f;
        fr[576 + h*3+0] = 0.0f; fr[576 + h*3+1] = 0.0f; fr[576 + h*3+2] = 0.0f;
        fr[624 + h] = 0.0f;
        return;
    }
    const float inv = 1.0f / s;
    float2 apxy = up2(ap01);
    float a0 = apxy.x * inv - posCA[grow*3+0];
    float a1 = apxy.y * inv - posCA[grow*3+1];
    float a2 = ap2    * inv - posCA[grow*3+2];

    const float* F = frame + grow * 9;
    float pt0 = F[0]*a0 + F[1]*a1 + F[2]*a2;
    float pt1 = F[3]*a0 + F[4]*a1 + F[5]*a2;
    float pt2 = F[6]*a0 + F[7]*a1 + F[8]*a2;

    float dist = sqrtf(a0*a0 + a1*a1 + a2*a2);
    float pn   = sqrtf(pt0*pt0 + pt1*pt1 + pt2*pt2);
    float id   = 1.0f / (pn + 1e-10f);
    float ang  = atan2f(pt1, pt0);

#pragma unroll
    for (int t = 0; t < 16; t++) {
        float2 v = up2(av2[t]);
        fr[h*32 + 2*t]   = v.x * inv;
        fr[h*32 + 2*t+1] = v.y * inv;
    }
    fr[512 + h*3+0] = pt0; fr[512 + h*3+1] = pt1; fr[512 + h*3+2] = pt2;
    fr[560 + h] = dist;
    fr[576 + h*3+0] = pt0*id; fr[576 + h*3+1] = pt1*id; fr[576 + h*3+2] = pt2*id;
    fr[624 + h] = ang;
}

// ============================================================
// K3a: h1 = relu(feat @ W1 + b1)   (4096x512, K=640)
// ============================================================
__global__ void __launch_bounds__(256) k_mlp1(
    const float* __restrict__ W1, const float* __restrict__ b1)
{
    const int bm = blockIdx.x * 128;
    const int bn = blockIdx.y * 64;

    GEMM_PROLOG

    for (int ch = 0; ch < FEAT/32; ch++) {
        load_chunkA(As, g_feat, FEAT, bm, ch*32, tid);
        load_chunkB(Bs, W1, HID, bn, ch*32, tid);
        __syncthreads();
        mma_chunk(As, Bs, acc, warpM, warpN, g, t4);
        __syncthreads();
    }

#pragma unroll
    for (int mt = 0; mt < 4; mt++) {
#pragma unroll
        for (int nt = 0; nt < 2; nt++) {
            int R0 = bm + warpM*64 + mt*16 + g;
            int C  = bn + warpN*16 + nt*8 + 2*t4;
            float bx = b1[C], by = b1[C+1];
            float2 v0 = make_float2(fmaxf(acc[mt][nt][0] + bx, 0.f), fmaxf(acc[mt][nt][1] + by, 0.f));
            float2 v1 = make_float2(fmaxf(acc[mt][nt][2] + bx, 0.f), fmaxf(acc[mt][nt][3] + by, 0.f));
            *(float2*)&g_h1[(size_t)R0*HID + C]     = v0;
            *(float2*)&g_h1[(size_t)(R0+8)*HID + C] = v1;
        }
    }
}

// ============================================================
// K3b: y = x + mask*(h1 @ W2 + b2)   (4096x256, K=512)
// ============================================================
__global__ void __launch_bounds__(256) k_mlp2(
    const float* __restrict__ x,
    const float* __restrict__ W2, const float* __restrict__ b2,
    const int*   __restrict__ mask)
{
    const int bm = blockIdx.x * 128;
    const int bn = blockIdx.y * 64;

    GEMM_PROLOG

    for (int ch = 0; ch < HID/32; ch++) {
        load_chunkA(As, g_h1, HID, bm, ch*32, tid);
        load_chunkB(Bs, W2, OUTD, bn, ch*32, tid);
        __syncthreads();
        mma_chunk(As, Bs, acc, warpM, warpN, g, t4);
        __syncthreads();
    }

#pragma unroll
    for (int mt = 0; mt < 4; mt++) {
#pragma unroll
        for (int nt = 0; nt < 2; nt++) {
            int R0 = bm + warpM*64 + mt*16 + g;
            int C  = bn + warpN*16 + nt*8 + 2*t4;
            float bx = b2[C], by = b2[C+1];
#pragma unroll
            for (int half = 0; half < 2; half++) {
                int R = R0 + half*8;
                float2 xv = *(const float2*)&x[(size_t)R*OUTD + C];
                float2 v;
                if (mask[R]) {
                    v.x = xv.x + acc[mt][nt][2*half+0] + bx;
                    v.y = xv.y + acc[mt][nt][2*half+1] + by;
                } else {
                    v = xv;
                }
                *(float2*)&g_y[(size_t)R*OUTD + C] = v;
            }
        }
    }
}

// ============================================================
// K4: LayerNorm. One warp per row (256 cols, 8 per lane).
// ============================================================
__global__ void __launch_bounds__(256) k_ln(
    const float* __restrict__ lng, const float* __restrict__ lnb,
    float* __restrict__ out)
{
    const int wid  = threadIdx.x >> 5;
    const int lane = threadIdx.x & 31;
    const int row  = blockIdx.x * 8 + wid;

    const float* yr = g_y + (size_t)row * OUTD;
    float yv[8];
    float ssum = 0.0f, ssq = 0.0f;
#pragma unroll
    for (int t = 0; t < 2; t++) {
        float4 v = *(const float4*)&yr[lane*4 + t*128];
        yv[t*4+0]=v.x; yv[t*4+1]=v.y; yv[t*4+2]=v.z; yv[t*4+3]=v.w;
        ssum += v.x+v.y+v.z+v.w;
        ssq  += v.x*v.x+v.y*v.y+v.z*v.z+v.w*v.w;
    }
#pragma unroll
    for (int off = 16; off > 0; off >>= 1) {
        ssum += __shfl_xor_sync(0xFFFFFFFF, ssum, off);
        ssq  += __shfl_xor_sync(0xFFFFFFFF, ssq,  off);
    }
    float mu  = ssum * (1.0f / OUTD);
    float var = ssq * (1.0f / OUTD) - mu * mu;
    float rs  = rsqrtf(var + 1e-5f);
#pragma unroll
    for (int t = 0; t < 2; t++) {
        int c = lane*4 + t*128;
        float4 g = *(const float4*)&lng[c];
        float4 bb = *(const float4*)&lnb[c];
        float4 o;
        o.x = (yv[t*4+0]-mu)*rs*g.x + bb.x;
        o.y = (yv[t*4+1]-mu)*rs*g.y + bb.y;
        o.z = (yv[t*4+2]-mu)*rs*g.z + bb.z;
        o.w = (yv[t*4+3]-mu)*rs*g.w + bb.w;
        *(float4*)&out[(size_t)row*OUTD + c] = o;
    }
}

// ============================================================
extern "C" void kernel_launch(void* const* d_in, const int* in_sizes, int n_in,
                              void* d_out, int out_size)
{
    const float* x     = (const float*)d_in[0];
    const float* posCA = (const float*)d_in[1];
    const float* posCB = (const float*)d_in[2];
    const float* frame = (const float*)d_in[3];
    const int*   mask  = (const int*)  d_in[4];
    const float* Wq    = (const float*)d_in[5];
    const float* Wk    = (const float*)d_in[6];
    const float* Wv    = (const float*)d_in[7];
    const float* seW1  = (const float*)d_in[8];
    const float* seb1  = (const float*)d_in[9];
    const float* seW2  = (const float*)d_in[10];
    const float* seb2  = (const float*)d_in[11];
    const float* otW1  = (const float*)d_in[12];
    const float* otb1  = (const float*)d_in[13];
    const float* otW2  = (const float*)d_in[14];
    const float* otb2  = (const float*)d_in[15];
    const float* lng   = (const float*)d_in[16];
    const float* lnb   = (const float*)d_in[17];
    float* out = (float*)d_out;

    const int smem_attn = (2*512*32 + 512*4) * 4 + 512*4;   // 141312
    cudaFuncSetAttribute(k_attn, cudaFuncAttributeMaxDynamicSharedMemorySize, smem_attn);

    k_spat<<<NL/128, 128>>>(posCA, seW1, seb1);
    k_qkv<<<dim3(NL/128, 24), 256>>>(x, Wq, Wk, Wv, seW2, seb2);
    k_attn<<<dim3(HH, NB), 512, smem_attn>>>(posCA, posCB, frame, mask);
    k_mlp1<<<dim3(NL/128, HID/64),  256>>>(otW1, otb1);
    k_mlp2<<<dim3(NL/128, OUTD/64), 256>>>(x, otW2, otb2, mask);
    k_ln<<<NL/8, 256>>>(lng, lnb, out);
}

// round 5
// speedup vs baseline: 2.9942x; 1.4845x over previous
#include <cuda_runtime.h>
#include <math.h>
#include <stdint.h>

// ---------------- problem constants ----------------
#define NB   8
#define LL   512
#define DD   256
#define HH   16
#define QK   32
#define VD   32
#define OUTD 256
#define NL   (NB*LL)          // 4096
#define QKH  (QK*HH)          // 512
#define FEAT 640              // 512 node + 128 spatial
#define HID  512              // OUT*2

// ---------------- tf32 helpers ----------------
__device__ __forceinline__ uint32_t to_tf32(float f) {
    uint32_t u;
    asm("cvt.rna.tf32.f32 %0, %1;" : "=r"(u) : "f"(f));
    return u;
}
__device__ __forceinline__ void mma_tf32(float c[4],
                                         uint32_t a0, uint32_t a1, uint32_t a2, uint32_t a3,
                                         uint32_t b0, uint32_t b1) {
    asm volatile("mma.sync.aligned.m16n8k8.row.col.f32.tf32.tf32.f32 "
                 "{%0,%1,%2,%3}, {%4,%5,%6,%7}, {%8,%9}, {%0,%1,%2,%3};"
                 : "+f"(c[0]), "+f"(c[1]), "+f"(c[2]), "+f"(c[3])
                 : "r"(a0), "r"(a1), "r"(a2), "r"(a3), "r"(b0), "r"(b1));
}

// FMA-only exp (no MUFU). |rel err| ~3e-6 — far below tf32 noise.
__device__ __forceinline__ float fexp(float x) {
    float y = x * 1.4426950408889634f;            // x*log2(e)
    float r = y + 12582912.0f;                    // round-to-nearest int (1.5*2^23)
    int   n = __float_as_int(r) - 0x4B400000;
    float f = y - (r - 12582912.0f);              // f in [-0.5, 0.5]
    // 2^f = e^{f ln2}: degree-5 Taylor
    float p = 1.3333558146e-3f;
    p = fmaf(p, f, 9.6181291076e-3f);
    p = fmaf(p, f, 5.5504108665e-2f);
    p = fmaf(p, f, 2.4022650696e-1f);
    p = fmaf(p, f, 6.9314718056e-1f);
    p = fmaf(p, f, 1.0f);
    return __int_as_float(__float_as_int(p) + (n << 23));
}

// ---------------- scratch (no allocs allowed) ----------------
__device__ float g_q[(size_t)NL*QKH];
__device__ float g_k[(size_t)NL*QKH];
__device__ float g_v[(size_t)NL*QKH];
__device__ float g_t[(size_t)NL*QK];
__device__ float g_feat[(size_t)NL*FEAT];
__device__ float g_h1[(size_t)NL*HID];
__device__ float g_y[(size_t)NL*OUTD];

// ============================================================
// K0: t = relu(pos_CA @ se_W1 + se_b1)   (4096 x 32)
// ============================================================
__global__ void k_spat(const float* __restrict__ posCA,
                       const float* __restrict__ seW1,
                       const float* __restrict__ seb1)
{
    int r = blockIdx.x * blockDim.x + threadIdx.x;
    if (r >= NL) return;
    float p0 = posCA[r*3+0], p1 = posCA[r*3+1], p2 = posCA[r*3+2];
#pragma unroll
    for (int j = 0; j < QK; j++) {
        float v = seb1[j] + p0*seW1[j] + p1*seW1[QK + j] + p2*seW1[2*QK + j];
        g_t[(size_t)r*QK + j] = fmaxf(v, 0.0f);
    }
}

// ============================================================
// tf32 warp-MMA GEMM building blocks (validated R4).
// Block 128x64, BK=32, 8 warps (2M x 4N), warp tile 64x16.
// ============================================================
__device__ __forceinline__ void load_chunkA(uint32_t (*As)[36], const float* A,
                                            int lda, int bm, int kc, int tid)
{
    int r  = tid >> 1;
    int c0 = (tid & 1) * 16;
    const float* p = A + (size_t)(bm + r) * lda + kc + c0;
    float4 v0 = *(const float4*)p;
    float4 v1 = *(const float4*)(p + 4);
    float4 v2 = *(const float4*)(p + 8);
    float4 v3 = *(const float4*)(p + 12);
    uint32_t* d = &As[r][c0];
    d[0]=to_tf32(v0.x); d[1]=to_tf32(v0.y); d[2]=to_tf32(v0.z); d[3]=to_tf32(v0.w);
    d[4]=to_tf32(v1.x); d[5]=to_tf32(v1.y); d[6]=to_tf32(v1.z); d[7]=to_tf32(v1.w);
    d[8]=to_tf32(v2.x); d[9]=to_tf32(v2.y); d[10]=to_tf32(v2.z); d[11]=to_tf32(v2.w);
    d[12]=to_tf32(v3.x); d[13]=to_tf32(v3.y); d[14]=to_tf32(v3.z); d[15]=to_tf32(v3.w);
}

__device__ __forceinline__ void load_chunkB(uint32_t (*Bs)[68], const float* B,
                                            int ldb, int bn, int kc, int tid)
{
    int kk = tid >> 3;
    int c0 = (tid & 7) * 8;
    const float* p = B + (size_t)(kc + kk) * ldb + bn + c0;
    float4 v0 = *(const float4*)p;
    float4 v1 = *(const float4*)(p + 4);
    uint32_t* d = &Bs[kk][c0];
    d[0]=to_tf32(v0.x); d[1]=to_tf32(v0.y); d[2]=to_tf32(v0.z); d[3]=to_tf32(v0.w);
    d[4]=to_tf32(v1.x); d[5]=to_tf32(v1.y); d[6]=to_tf32(v1.z); d[7]=to_tf32(v1.w);
}

__device__ __forceinline__ void mma_chunk(const uint32_t (*As)[36], const uint32_t (*Bs)[68],
                                          float acc[4][2][4], int warpM, int warpN,
                                          int g, int t4)
{
#pragma unroll
    for (int ks = 0; ks < 4; ks++) {
        const int k0 = ks * 8;
        uint32_t b[2][2];
#pragma unroll
        for (int nt = 0; nt < 2; nt++) {
            int nc = warpN * 16 + nt * 8 + g;
            b[nt][0] = Bs[k0 + t4][nc];
            b[nt][1] = Bs[k0 + t4 + 4][nc];
        }
#pragma unroll
        for (int mt = 0; mt < 4; mt++) {
            int mr = warpM * 64 + mt * 16;
            uint32_t a0 = As[mr + g][k0 + t4];
            uint32_t a1 = As[mr + g + 8][k0 + t4];
            uint32_t a2 = As[mr + g][k0 + t4 + 4];
            uint32_t a3 = As[mr + g + 8][k0 + t4 + 4];
#pragma unroll
            for (int nt = 0; nt < 2; nt++)
                mma_tf32(acc[mt][nt], a0, a1, a2, a3, b[nt][0], b[nt][1]);
        }
    }
}

#define GEMM_PROLOG                                                  \
    __shared__ uint32_t As[128][36];                                 \
    __shared__ uint32_t Bs[32][68];                                  \
    const int tid  = threadIdx.x;                                    \
    const int wid  = tid >> 5;                                       \
    const int lane = tid & 31;                                       \
    const int g    = lane >> 2, t4 = lane & 3;                       \
    const int warpM = wid >> 2, warpN = wid & 3;                     \
    float acc[4][2][4];                                              \
    _Pragma("unroll") for (int i = 0; i < 4; i++)                    \
    _Pragma("unroll") for (int j = 0; j < 2; j++)                    \
    _Pragma("unroll") for (int q = 0; q < 4; q++) acc[i][j][q] = 0.0f;

// ============================================================
// K1: fused QKV projection (4096 x 1536, K=256)
// ============================================================
__global__ void __launch_bounds__(256) k_qkv(
    const float* __restrict__ x,
    const float* __restrict__ Wq, const float* __restrict__ Wk,
    const float* __restrict__ Wv,
    const float* __restrict__ seW2, const float* __restrict__ seb2)
{
    const int bm  = blockIdx.x * 128;
    const int mat = blockIdx.y >> 3;           // 0=q 1=k 2=v
    const int bn  = (blockIdx.y & 7) * 64;
    const float* W = (mat == 0) ? Wq : (mat == 1) ? Wk : Wv;

    GEMM_PROLOG

    const int nchunks = (mat == 0) ? 9 : 8;
    for (int ch = 0; ch < nchunks; ch++) {
        if (ch < 8) { load_chunkA(As, x,   DD, bm, ch*32, tid); load_chunkB(Bs, W,    QKH, bn, ch*32, tid); }
        else        { load_chunkA(As, g_t, QK, bm, 0,     tid); load_chunkB(Bs, seW2, QKH, bn, 0,     tid); }
        __syncthreads();
        mma_chunk(As, Bs, acc, warpM, warpN, g, t4);
        __syncthreads();
    }

    float* dst = (mat == 0) ? g_q : (mat == 1) ? g_k : g_v;
#pragma unroll
    for (int mt = 0; mt < 4; mt++) {
#pragma unroll
        for (int nt = 0; nt < 2; nt++) {
            int R0 = bm + warpM*64 + mt*16 + g;
            int C  = bn + warpN*16 + nt*8 + 2*t4;
            float bx = 0.f, by = 0.f;
            if (mat == 0) { bx = seb2[C]; by = seb2[C+1]; }
            float2 v0 = make_float2(acc[mt][nt][0] + bx, acc[mt][nt][1] + by);
            float2 v1 = make_float2(acc[mt][nt][2] + bx, acc[mt][nt][3] + by);
            *(float2*)&dst[(size_t)R0*QKH + C]       = v0;
            *(float2*)&dst[(size_t)(R0+8)*QKH + C]   = v1;
        }
    }
}

// ============================================================
// K2: tensor-core attention. One block per (b,h), 8 warps.
// Each warp owns 64 q-rows. 16 K-chunks of 32.
//   S = Q@K^T (tf32 MMA), P = mask*fexp(S) -> smem tf32,
//   O += P @ [V | posCB | ones | pad]  (row-sum s via ones col)
// Smem: Qs[512][36] Ps[512][36] Ks[32][36] Vs[32][40] mkf[512]
// ============================================================
__global__ void __launch_bounds__(256, 1) k_attn(
    const float* __restrict__ posCA,
    const float* __restrict__ posCB,
    const float* __restrict__ frame,
    const int*   __restrict__ mask)
{
    extern __shared__ float smf[];
    uint32_t* Qs = (uint32_t*)smf;                          // [512][36]
    uint32_t* Ps = (uint32_t*)(smf + 512*36);               // [512][36]
    uint32_t* Ks = (uint32_t*)(smf + 2*512*36);             // [32][36]
    uint32_t* Vs = (uint32_t*)(smf + 2*512*36 + 32*36);     // [32][40]
    float*   mkf = smf + 2*512*36 + 32*36 + 32*40;          // [512]

    const int h = blockIdx.x;
    const int b = blockIdx.y;
    const int tid = threadIdx.x;
    const int w = tid >> 5, lane = tid & 31;
    const int g = lane >> 2, t4 = lane & 3;

    // ---- load Q (512x32) -> Qs tf32 ----
#pragma unroll
    for (int it = 0; it < 16; it++) {
        int idx = tid + 256*it;
        int r = idx >> 3, seg = idx & 7;
        const float4 v = *(const float4*)(g_q + ((size_t)b*LL + r)*QKH + h*QK + seg*4);
        uint32_t* d = &Qs[r*36 + seg*4];
        d[0]=to_tf32(v.x); d[1]=to_tf32(v.y); d[2]=to_tf32(v.z); d[3]=to_tf32(v.w);
    }
    mkf[tid]       = mask[b*LL + tid]       ? 1.0f : 0.0f;
    mkf[tid + 256] = mask[b*LL + tid + 256] ? 1.0f : 0.0f;

    float acc[4][5][4];
#pragma unroll
    for (int i = 0; i < 4; i++)
#pragma unroll
        for (int j = 0; j < 5; j++)
#pragma unroll
            for (int q = 0; q < 4; q++) acc[i][j][q] = 0.0f;

    for (int ch = 0; ch < 16; ch++) {
        __syncthreads();   // protects Ks/Vs vs previous chunk's consumers
        const int j0 = ch * 32;
        {   // K and V chunk (natural [j][d] layout), coalesced
            int j = tid >> 3, seg = tid & 7;
            size_t roff = ((size_t)b*LL + j0 + j)*QKH + h*QK + seg*4;
            float4 kv = *(const float4*)(g_k + roff);
            float4 vv = *(const float4*)(g_v + roff);
            uint32_t* dk = &Ks[j*36 + seg*4];
            dk[0]=to_tf32(kv.x); dk[1]=to_tf32(kv.y); dk[2]=to_tf32(kv.z); dk[3]=to_tf32(kv.w);
            uint32_t* dv = &Vs[j*40 + seg*4];
            dv[0]=to_tf32(vv.x); dv[1]=to_tf32(vv.y); dv[2]=to_tf32(vv.z); dv[3]=to_tf32(vv.w);
        }
        if (tid < 32) {   // augment columns: posCB, ones, pad
            int j = tid;
            const float* pp = posCB + ((size_t)b*LL + j0 + j)*3;
            Vs[j*40+32] = to_tf32(pp[0]);
            Vs[j*40+33] = to_tf32(pp[1]);
            Vs[j*40+34] = to_tf32(pp[2]);
            Vs[j*40+35] = to_tf32(1.0f);
            Vs[j*40+36] = 0; Vs[j*40+37] = 0; Vs[j*40+38] = 0; Vs[j*40+39] = 0;
        }
        __syncthreads();

        // ---- S phase: S = Q@K^T ; P = mask * fexp(S) -> Ps ----
        uint32_t kb[4][4][2];
#pragma unroll
        for (int nt = 0; nt < 4; nt++)
#pragma unroll
            for (int ks = 0; ks < 4; ks++) {
                kb[nt][ks][0] = Ks[(8*nt+g)*36 + ks*8 + t4];
                kb[nt][ks][1] = Ks[(8*nt+g)*36 + ks*8 + t4 + 4];
            }
#pragma unroll
        for (int mt = 0; mt < 4; mt++) {
            const int rb = w*64 + mt*16;
            float S[4][4];
#pragma unroll
            for (int nt = 0; nt < 4; nt++)
#pragma unroll
                for (int q = 0; q < 4; q++) S[nt][q] = 0.0f;
#pragma unroll
            for (int ks = 0; ks < 4; ks++) {
                const int k0 = ks*8;
                uint32_t a0 = Qs[(rb+g)*36   + k0+t4];
                uint32_t a1 = Qs[(rb+g+8)*36 + k0+t4];
                uint32_t a2 = Qs[(rb+g)*36   + k0+t4+4];
                uint32_t a3 = Qs[(rb+g+8)*36 + k0+t4+4];
#pragma unroll
                for (int nt = 0; nt < 4; nt++)
                    mma_tf32(S[nt], a0, a1, a2, a3, kb[nt][ks][0], kb[nt][ks][1]);
            }
#pragma unroll
            for (int nt = 0; nt < 4; nt++) {
                const int col = 8*nt + 2*t4;
                float m0 = mkf[j0 + col], m1 = mkf[j0 + col + 1];
                uint2 lo, hi;
                lo.x = to_tf32(m0 * fexp(S[nt][0]));
                lo.y = to_tf32(m1 * fexp(S[nt][1]));
                hi.x = to_tf32(m0 * fexp(S[nt][2]));
                hi.y = to_tf32(m1 * fexp(S[nt][3]));
                *(uint2*)&Ps[(rb+g)*36   + col] = lo;
                *(uint2*)&Ps[(rb+g+8)*36 + col] = hi;
            }
        }
        __syncwarp();   // warp reads only its own Ps rows

        // ---- O phase: O += P @ Vaug ----
        uint32_t vb[5][4][2];
#pragma unroll
        for (int nt = 0; nt < 5; nt++)
#pragma unroll
            for (int ks = 0; ks < 4; ks++) {
                vb[nt][ks][0] = Vs[(ks*8+t4)*40   + 8*nt+g];
                vb[nt][ks][1] = Vs[(ks*8+t4+4)*40 + 8*nt+g];
            }
#pragma unroll
        for (int mt = 0; mt < 4; mt++) {
            const int rb = w*64 + mt*16;
#pragma unroll
            for (int ks = 0; ks < 4; ks++) {
                const int k0 = ks*8;
                uint32_t a0 = Ps[(rb+g)*36   + k0+t4];
                uint32_t a1 = Ps[(rb+g+8)*36 + k0+t4];
                uint32_t a2 = Ps[(rb+g)*36   + k0+t4+4];
                uint32_t a3 = Ps[(rb+g+8)*36 + k0+t4+4];
#pragma unroll
                for (int nt = 0; nt < 5; nt++)
                    mma_tf32(acc[mt][nt], a0, a1, a2, a3, vb[nt][ks][0], vb[nt][ks][1]);
            }
        }
    }

    // ---- epilogue ----
#pragma unroll
    for (int mt = 0; mt < 4; mt++) {
#pragma unroll
        for (int half = 0; half < 2; half++) {
            const int rloc = w*64 + mt*16 + g + half*8;
            const size_t grow = (size_t)b*LL + rloc;
            float c_lo = half ? acc[mt][4][2] : acc[mt][4][0];
            float c_hi = half ? acc[mt][4][3] : acc[mt][4][1];
            const int qb = lane & ~3;
            float ap0 = __shfl_sync(0xffffffffu, c_lo, qb + 0);
            float ap1 = __shfl_sync(0xffffffffu, c_hi, qb + 0);
            float ap2 = __shfl_sync(0xffffffffu, c_lo, qb + 1);
            float s   = __shfl_sync(0xffffffffu, c_hi, qb + 1);
            const bool ok = (mkf[rloc] != 0.0f) && (s > 0.0f);
            const float inv = ok ? 1.0f / s : 0.0f;
            float* fr = g_feat + grow * FEAT;
#pragma unroll
            for (int nt = 0; nt < 4; nt++) {
                float v0 = half ? acc[mt][nt][2] : acc[mt][nt][0];
                float v1 = half ? acc[mt][nt][3] : acc[mt][nt][1];
                *(float2*)&fr[h*32 + 8*nt + 2*t4] = make_float2(v0*inv, v1*inv);
            }
            if (t4 == 0) {
                if (!ok) {
                    fr[512 + h*3+0] = 0.0f; fr[512 + h*3+1] = 0.0f; fr[512 + h*3+2] = 0.0f;
                    fr[560 + h] = 0.0f;
                    fr[576 + h*3+0] = 0.0f; fr[576 + h*3+1] = 0.0f; fr[576 + h*3+2] = 0.0f;
                    fr[624 + h] = 0.0f;
                } else {
                    float a0 = ap0*inv - posCA[grow*3+0];
                    float a1 = ap1*inv - posCA[grow*3+1];
                    float a2 = ap2*inv - posCA[grow*3+2];
                    const float* F = frame + grow * 9;
                    float pt0 = F[0]*a0 + F[1]*a1 + F[2]*a2;
                    float pt1 = F[3]*a0 + F[4]*a1 + F[5]*a2;
                    float pt2 = F[6]*a0 + F[7]*a1 + F[8]*a2;
                    float dist = sqrtf(a0*a0 + a1*a1 + a2*a2);
                    float pn   = sqrtf(pt0*pt0 + pt1*pt1 + pt2*pt2);
                    float id   = 1.0f / (pn + 1e-10f);
                    float ang  = atan2f(pt1, pt0);
                    fr[512 + h*3+0] = pt0; fr[512 + h*3+1] = pt1; fr[512 + h*3+2] = pt2;
                    fr[560 + h] = dist;
                    fr[576 + h*3+0] = pt0*id; fr[576 + h*3+1] = pt1*id; fr[576 + h*3+2] = pt2*id;
                    fr[624 + h] = ang;
                }
            }
        }
    }
}

// ============================================================
// K3a: h1 = relu(feat @ W1 + b1)   (4096x512, K=640)
// ============================================================
__global__ void __launch_bounds__(256) k_mlp1(
    const float* __restrict__ W1, const float* __restrict__ b1)
{
    const int bm = blockIdx.x * 128;
    const int bn = blockIdx.y * 64;

    GEMM_PROLOG

    for (int ch = 0; ch < FEAT/32; ch++) {
        load_chunkA(As, g_feat, FEAT, bm, ch*32, tid);
        load_chunkB(Bs, W1, HID, bn, ch*32, tid);
        __syncthreads();
        mma_chunk(As, Bs, acc, warpM, warpN, g, t4);
        __syncthreads();
    }

#pragma unroll
    for (int mt = 0; mt < 4; mt++) {
#pragma unroll
        for (int nt = 0; nt < 2; nt++) {
            int R0 = bm + warpM*64 + mt*16 + g;
            int C  = bn + warpN*16 + nt*8 + 2*t4;
            float bx = b1[C], by = b1[C+1];
            float2 v0 = make_float2(fmaxf(acc[mt][nt][0] + bx, 0.f), fmaxf(acc[mt][nt][1] + by, 0.f));
            float2 v1 = make_float2(fmaxf(acc[mt][nt][2] + bx, 0.f), fmaxf(acc[mt][nt][3] + by, 0.f));
            *(float2*)&g_h1[(size_t)R0*HID + C]     = v0;
            *(float2*)&g_h1[(size_t)(R0+8)*HID + C] = v1;
        }
    }
}

// ============================================================
// K3b: y = x + mask*(h1 @ W2 + b2)   (4096x256, K=512)
// ============================================================
__global__ void __launch_bounds__(256) k_mlp2(
    const float* __restrict__ x,
    const float* __restrict__ W2, const float* __restrict__ b2,
    const int*   __restrict__ mask)
{
    const int bm = blockIdx.x * 128;
    const int bn = blockIdx.y * 64;

    GEMM_PROLOG

    for (int ch = 0; ch < HID/32; ch++) {
        load_chunkA(As, g_h1, HID, bm, ch*32, tid);
        load_chunkB(Bs, W2, OUTD, bn, ch*32, tid);
        __syncthreads();
        mma_chunk(As, Bs, acc, warpM, warpN, g, t4);
        __syncthreads();
    }

#pragma unroll
    for (int mt = 0; mt < 4; mt++) {
#pragma unroll
        for (int nt = 0; nt < 2; nt++) {
            int R0 = bm + warpM*64 + mt*16 + g;
            int C  = bn + warpN*16 + nt*8 + 2*t4;
            float bx = b2[C], by = b2[C+1];
#pragma unroll
            for (int half = 0; half < 2; half++) {
                int R = R0 + half*8;
                float2 xv = *(const float2*)&x[(size_t)R*OUTD + C];
                float2 v;
                if (mask[R]) {
                    v.x = xv.x + acc[mt][nt][2*half+0] + bx;
                    v.y = xv.y + acc[mt][nt][2*half+1] + by;
                } else {
                    v = xv;
                }
                *(float2*)&g_y[(size_t)R*OUTD + C] = v;
            }
        }
    }
}

// ============================================================
// K4: LayerNorm. One warp per row.
// ============================================================
__global__ void __launch_bounds__(256) k_ln(
    const float* __restrict__ lng, const float* __restrict__ lnb,
    float* __restrict__ out)
{
    const int wid  = threadIdx.x >> 5;
    const int lane = threadIdx.x & 31;
    const int row  = blockIdx.x * 8 + wid;

    const float* yr = g_y + (size_t)row * OUTD;
    float yv[8];
    float ssum = 0.0f, ssq = 0.0f;
#pragma unroll
    for (int t = 0; t < 2; t++) {
        float4 v = *(const float4*)&yr[lane*4 + t*128];
        yv[t*4+0]=v.x; yv[t*4+1]=v.y; yv[t*4+2]=v.z; yv[t*4+3]=v.w;
        ssum += v.x+v.y+v.z+v.w;
        ssq  += v.x*v.x+v.y*v.y+v.z*v.z+v.w*v.w;
    }
#pragma unroll
    for (int off = 16; off > 0; off >>= 1) {
        ssum += __shfl_xor_sync(0xFFFFFFFF, ssum, off);
        ssq  += __shfl_xor_sync(0xFFFFFFFF, ssq,  off);
    }
    float mu  = ssum * (1.0f / OUTD);
    float var = ssq * (1.0f / OUTD) - mu * mu;
    float rs  = rsqrtf(var + 1e-5f);
#pragma unroll
    for (int t = 0; t < 2; t++) {
        int c = lane*4 + t*128;
        float4 g = *(const float4*)&lng[c];
        float4 bb = *(const float4*)&lnb[c];
        float4 o;
        o.x = (yv[t*4+0]-mu)*rs*g.x + bb.x;
        o.y = (yv[t*4+1]-mu)*rs*g.y + bb.y;
        o.z = (yv[t*4+2]-mu)*rs*g.z + bb.z;
        o.w = (yv[t*4+3]-mu)*rs*g.w + bb.w;
        *(float4*)&out[(size_t)row*OUTD + c] = o;
    }
}

// ============================================================
extern "C" void kernel_launch(void* const* d_in, const int* in_sizes, int n_in,
                              void* d_out, int out_size)
{
    const float* x     = (const float*)d_in[0];
    const float* posCA = (const float*)d_in[1];
    const float* posCB = (const float*)d_in[2];
    const float* frame = (const float*)d_in[3];
    const int*   mask  = (const int*)  d_in[4];
    const float* Wq    = (const float*)d_in[5];
    const float* Wk    = (const float*)d_in[6];
    const float* Wv    = (const float*)d_in[7];
    const float* seW1  = (const float*)d_in[8];
    const float* seb1  = (const float*)d_in[9];
    const float* seW2  = (const float*)d_in[10];
    const float* seb2  = (const float*)d_in[11];
    const float* otW1  = (const float*)d_in[12];
    const float* otb1  = (const float*)d_in[13];
    const float* otW2  = (const float*)d_in[14];
    const float* otb2  = (const float*)d_in[15];
    const float* lng   = (const float*)d_in[16];
    const float* lnb   = (const float*)d_in[17];
    float* out = (float*)d_out;

    const int smem_attn = (2*512*36 + 32*36 + 32*40 + 512) * 4;   // 159232
    cudaFuncSetAttribute(k_attn, cudaFuncAttributeMaxDynamicSharedMemorySize, smem_attn);

    k_spat<<<NL/128, 128>>>(posCA, seW1, seb1);
    k_qkv<<<dim3(NL/128, 24), 256>>>(x, Wq, Wk, Wv, seW2, seb2);
    k_attn<<<dim3(HH, NB), 256, smem_attn>>>(posCA, posCB, frame, mask);
    k_mlp1<<<dim3(NL/128, HID/64),  256>>>(otW1, otb1);
    k_mlp2<<<dim3(NL/128, OUTD/64), 256>>>(x, otW2, otb2, mask);
    k_ln<<<NL/8, 256>>>(lng, lnb, out);
}

// round 6
// speedup vs baseline: 3.4550x; 1.1539x over previous
#include <cuda_runtime.h>
#include <cuda_bf16.h>
#include <math.h>
#include <stdint.h>

// ---------------- problem constants ----------------
#define NB   8
#define LL   512
#define DD   256
#define HH   16
#define QK   32
#define VD   32
#define OUTD 256
#define NL   (NB*LL)          // 4096
#define QKH  (QK*HH)          // 512
#define FEAT 640              // 512 node + 128 spatial
#define HID  512              // OUT*2

// ---------------- bf16 helpers ----------------
// pack two floats -> bf16x2 (lo = first arg)
__device__ __forceinline__ uint32_t bf2(float lo, float hi) {
    uint32_t d;
    asm("cvt.rn.bf16x2.f32 %0, %1, %2;" : "=r"(d) : "f"(hi), "f"(lo));
    return d;
}
__device__ __forceinline__ void mma_bf16(float c[4],
                                         uint32_t a0, uint32_t a1, uint32_t a2, uint32_t a3,
                                         uint32_t b0, uint32_t b1) {
    asm volatile("mma.sync.aligned.m16n8k16.row.col.f32.bf16.bf16.f32 "
                 "{%0,%1,%2,%3}, {%4,%5,%6,%7}, {%8,%9}, {%0,%1,%2,%3};"
                 : "+f"(c[0]), "+f"(c[1]), "+f"(c[2]), "+f"(c[3])
                 : "r"(a0), "r"(a1), "r"(a2), "r"(a3), "r"(b0), "r"(b1));
}

// FMA-only exp (no MUFU). |rel err| ~3e-6.
__device__ __forceinline__ float fexp(float x) {
    float y = x * 1.4426950408889634f;
    float r = y + 12582912.0f;
    int   n = __float_as_int(r) - 0x4B400000;
    float f = y - (r - 12582912.0f);
    float p = 1.3333558146e-3f;
    p = fmaf(p, f, 9.6181291076e-3f);
    p = fmaf(p, f, 5.5504108665e-2f);
    p = fmaf(p, f, 2.4022650696e-1f);
    p = fmaf(p, f, 6.9314718056e-1f);
    p = fmaf(p, f, 1.0f);
    return __int_as_float(__float_as_int(p) + (n << 23));
}

// ---------------- scratch (no allocs allowed) ----------------
__device__ uint32_t g_qb[(size_t)NL*QKH/2];   // bf16x2 packed
__device__ uint32_t g_kb[(size_t)NL*QKH/2];
__device__ uint32_t g_vb[(size_t)NL*QKH/2];
__device__ uint32_t g_h1b[(size_t)NL*HID/2];
__device__ float    g_t[(size_t)NL*QK];
__device__ float    g_feat[(size_t)NL*FEAT];
__device__ float    g_y[(size_t)NL*OUTD];

// ============================================================
// K0: t = relu(pos_CA @ se_W1 + se_b1)   (4096 x 32)
// ============================================================
__global__ void k_spat(const float* __restrict__ posCA,
                       const float* __restrict__ seW1,
                       const float* __restrict__ seb1)
{
    int r = blockIdx.x * blockDim.x + threadIdx.x;
    if (r >= NL) return;
    float p0 = posCA[r*3+0], p1 = posCA[r*3+1], p2 = posCA[r*3+2];
#pragma unroll
    for (int j = 0; j < QK; j++) {
        float v = seb1[j] + p0*seW1[j] + p1*seW1[QK + j] + p2*seW1[2*QK + j];
        g_t[(size_t)r*QK + j] = fmaxf(v, 0.0f);
    }
}

// ============================================================
// bf16 warp-MMA GEMM blocks: BM=128, BN=64, BK=32 (=16 pairs),
// 8 warps (2M x 4N), warp tile 64x16, m16n8k16.
// As: [128][20] uint32 pairs (16 kp + pad) — pitch 20 conflict-free
// Bs: [64][20]  uint32 pairs, stored TRANSPOSED [n][kp]
// ============================================================
__device__ __forceinline__ void load_chunkA_bf(uint32_t (*As)[20], const float* A,
                                               int lda, int bm, int kc, int tid)
{
    int r = tid >> 1;
    int h = (tid & 1) * 8;      // pair offset 0 or 8
    const float* p = A + (size_t)(bm + r) * lda + kc + h*2;
    float4 v0 = *(const float4*)p;
    float4 v1 = *(const float4*)(p + 4);
    float4 v2 = *(const float4*)(p + 8);
    float4 v3 = *(const float4*)(p + 12);
    uint4 w0, w1;
    w0.x = bf2(v0.x, v0.y); w0.y = bf2(v0.z, v0.w);
    w0.z = bf2(v1.x, v1.y); w0.w = bf2(v1.z, v1.w);
    w1.x = bf2(v2.x, v2.y); w1.y = bf2(v2.z, v2.w);
    w1.z = bf2(v3.x, v3.y); w1.w = bf2(v3.z, v3.w);
    *(uint4*)&As[r][h]     = w0;
    *(uint4*)&As[r][h + 4] = w1;
}

// packed-bf16 source (g_h1b): raw copy
__device__ __forceinline__ void load_chunkA_pk(uint32_t (*As)[20], const uint32_t* A,
                                               int ldp, int bm, int kcp, int tid)
{
    int r = tid >> 1;
    int h = (tid & 1) * 8;
    const uint4* p = (const uint4*)(A + (size_t)(bm + r) * ldp + kcp + h);
    *(uint4*)&As[r][h]     = p[0];
    *(uint4*)&As[r][h + 4] = p[1];
}

// B: global [k][n] row-major -> smem transposed [n][kp] bf16
__device__ __forceinline__ void load_chunkB_bf(uint32_t (*Bs)[20], const float* B,
                                               int ldb, int bn, int kc, int tid)
{
    int kk = tid >> 3;           // 0..31 (k within chunk)
    int c0 = (tid & 7) * 8;      // 8 n values
    const float* p = B + (size_t)(kc + kk) * ldb + bn + c0;
    float4 v0 = *(const float4*)p;
    float4 v1 = *(const float4*)(p + 4);
    __nv_bfloat16* b16 = (__nv_bfloat16*)Bs;   // row pitch 40 halves
    b16[(c0+0)*40 + kk] = __float2bfloat16(v0.x);
    b16[(c0+1)*40 + kk] = __float2bfloat16(v0.y);
    b16[(c0+2)*40 + kk] = __float2bfloat16(v0.z);
    b16[(c0+3)*40 + kk] = __float2bfloat16(v0.w);
    b16[(c0+4)*40 + kk] = __float2bfloat16(v1.x);
    b16[(c0+5)*40 + kk] = __float2bfloat16(v1.y);
    b16[(c0+6)*40 + kk] = __float2bfloat16(v1.z);
    b16[(c0+7)*40 + kk] = __float2bfloat16(v1.w);
}

__device__ __forceinline__ void mma_chunk_bf(const uint32_t (*As)[20], const uint32_t (*Bs)[20],
                                             float acc[4][2][4], int warpM, int warpN,
                                             int g, int t4)
{
#pragma unroll
    for (int s = 0; s < 2; s++) {
        const int k0 = s * 8;
        uint32_t b[2][2];
#pragma unroll
        for (int nt = 0; nt < 2; nt++) {
            int nc = warpN * 16 + nt * 8 + g;
            b[nt][0] = Bs[nc][k0 + t4];
            b[nt][1] = Bs[nc][k0 + t4 + 4];
        }
#pragma unroll
        for (int mt = 0; mt < 4; mt++) {
            int mr = warpM * 64 + mt * 16;
            uint32_t a0 = As[mr + g][k0 + t4];
            uint32_t a1 = As[mr + g + 8][k0 + t4];
            uint32_t a2 = As[mr + g][k0 + t4 + 4];
            uint32_t a3 = As[mr + g + 8][k0 + t4 + 4];
#pragma unroll
            for (int nt = 0; nt < 2; nt++)
                mma_bf16(acc[mt][nt], a0, a1, a2, a3, b[nt][0], b[nt][1]);
        }
    }
}

#define GEMM_PROLOG                                                  \
    __shared__ __align__(16) uint32_t As[128][20];                   \
    __shared__ __align__(16) uint32_t Bs[64][20];                    \
    const int tid  = threadIdx.x;                                    \
    const int wid  = tid >> 5;                                       \
    const int lane = tid & 31;                                       \
    const int g    = lane >> 2, t4 = lane & 3;                       \
    const int warpM = wid >> 2, warpN = wid & 3;                     \
    float acc[4][2][4];                                              \
    _Pragma("unroll") for (int i = 0; i < 4; i++)                    \
    _Pragma("unroll") for (int j = 0; j < 2; j++)                    \
    _Pragma("unroll") for (int q = 0; q < 4; q++) acc[i][j][q] = 0.0f;

// ============================================================
// K1: fused QKV projection (4096 x 1536, K=256; q adds
// t@se_W2 + se_b2). Output: packed bf16.
// ============================================================
__global__ void __launch_bounds__(256) k_qkv(
    const float* __restrict__ x,
    const float* __restrict__ Wq, const float* __restrict__ Wk,
    const float* __restrict__ Wv,
    const float* __restrict__ seW2, const float* __restrict__ seb2)
{
    const int bm  = blockIdx.x * 128;
    const int mat = blockIdx.y >> 3;           // 0=q 1=k 2=v
    const int bn  = (blockIdx.y & 7) * 64;
    const float* W = (mat == 0) ? Wq : (mat == 1) ? Wk : Wv;

    GEMM_PROLOG

    const int nchunks = (mat == 0) ? 9 : 8;
    for (int ch = 0; ch < nchunks; ch++) {
        if (ch < 8) { load_chunkA_bf(As, x,   DD, bm, ch*32, tid); load_chunkB_bf(Bs, W,    QKH, bn, ch*32, tid); }
        else        { load_chunkA_bf(As, g_t, QK, bm, 0,     tid); load_chunkB_bf(Bs, seW2, QKH, bn, 0,     tid); }
        __syncthreads();
        mma_chunk_bf(As, Bs, acc, warpM, warpN, g, t4);
        __syncthreads();
    }

    uint32_t* dst = (mat == 0) ? g_qb : (mat == 1) ? g_kb : g_vb;
#pragma unroll
    for (int mt = 0; mt < 4; mt++) {
#pragma unroll
        for (int nt = 0; nt < 2; nt++) {
            int R0 = bm + warpM*64 + mt*16 + g;
            int C  = bn + warpN*16 + nt*8 + 2*t4;
            float bx = 0.f, by = 0.f;
            if (mat == 0) { bx = seb2[C]; by = seb2[C+1]; }
            dst[(size_t)R0*(QKH/2)     + C/2] = bf2(acc[mt][nt][0] + bx, acc[mt][nt][1] + by);
            dst[(size_t)(R0+8)*(QKH/2) + C/2] = bf2(acc[mt][nt][2] + bx, acc[mt][nt][3] + by);
        }
    }
}

// ============================================================
// K2: bf16 tensor-core attention. One block per (b,h), 8 warps,
// warp = 64 q-rows. 16 chunks of 32 keys.
//   S = Q@K^T (m16n8k16), P = mask*fexp(S) -> Ps bf16 pairs,
//   O += P @ [V | posCB | ones | 0pad]^T   (s via ones column)
// Smem (uint32 pairs, pitch 20): Qs[512] Ps[512] Ks[32] Vs[40rows]
// ============================================================
__global__ void __launch_bounds__(256, 1) k_attn(
    const float* __restrict__ posCA,
    const float* __restrict__ posCB,
    const float* __restrict__ frame,
    const int*   __restrict__ mask)
{
    extern __shared__ __align__(16) uint32_t smu[];
    uint32_t (*Qs)[20] = (uint32_t (*)[20])smu;                  // [512][20]
    uint32_t (*Ps)[20] = (uint32_t (*)[20])(smu + 512*20);       // [512][20]
    uint32_t (*Ks)[20] = (uint32_t (*)[20])(smu + 2*512*20);     // [32][20]
    uint32_t (*Vs)[20] = (uint32_t (*)[20])(smu + 2*512*20 + 32*20); // [40][20] (n=vdim rows)
    float*   mkf = (float*)(smu + 2*512*20 + 32*20 + 40*20);     // [512]
    __nv_bfloat16* Vs16 = (__nv_bfloat16*)Vs;                    // [40][40]

    const int h = blockIdx.x;
    const int b = blockIdx.y;
    const int tid = threadIdx.x;
    const int w = tid >> 5, lane = tid & 31;
    const int g = lane >> 2, t4 = lane & 3;

    // ---- load Q (512 x 16 pairs) : raw packed copy ----
#pragma unroll
    for (int it = 0; it < 8; it++) {
        int idx = tid + 256*it;          // 2048 uint4
        int r = idx >> 2, c4 = idx & 3;
        uint4 wv = *(const uint4*)(g_qb + ((size_t)b*LL + r)*(QKH/2) + h*(QK/2) + c4*4);
        *(uint4*)&Qs[r][c4*4] = wv;
    }
    mkf[tid]       = mask[b*LL + tid]       ? 1.0f : 0.0f;
    mkf[tid + 256] = mask[b*LL + tid + 256] ? 1.0f : 0.0f;

    float acc[4][5][4];
#pragma unroll
    for (int i = 0; i < 4; i++)
#pragma unroll
        for (int j = 0; j < 5; j++)
#pragma unroll
            for (int q = 0; q < 4; q++) acc[i][j][q] = 0.0f;

    for (int ch = 0; ch < 16; ch++) {
        __syncthreads();   // Ks/Vs safe to overwrite
        const int j0 = ch * 32;
        if (tid < 128) {
            // V chunk -> transposed Vs16[d][j]
            int j = tid >> 2, c4 = tid & 3;
            uint4 wv = *(const uint4*)(g_vb + ((size_t)b*LL + j0 + j)*(QKH/2) + h*(QK/2) + c4*4);
            uint32_t ws[4] = {wv.x, wv.y, wv.z, wv.w};
#pragma unroll
            for (int p = 0; p < 4; p++) {
                __nv_bfloat162 bb = *(__nv_bfloat162*)&ws[p];
                int d = c4*8 + 2*p;
                Vs16[d*40 + j]     = bb.x;
                Vs16[(d+1)*40 + j] = bb.y;
            }
        } else {
            // K chunk -> natural Ks[j][pairs]
            int t = tid - 128;
            int j = t >> 2, c4 = t & 3;
            uint4 wv = *(const uint4*)(g_kb + ((size_t)b*LL + j0 + j)*(QKH/2) + h*(QK/2) + c4*4);
            *(uint4*)&Ks[j][c4*4] = wv;
        }
        if (tid < 32) {   // augment rows 32..39 of Vs16
            int j = tid;
            const float* pp = posCB + ((size_t)b*LL + j0 + j)*3;
            Vs16[32*40 + j] = __float2bfloat16(pp[0]);
            Vs16[33*40 + j] = __float2bfloat16(pp[1]);
            Vs16[34*40 + j] = __float2bfloat16(pp[2]);
            Vs16[35*40 + j] = __float2bfloat16(1.0f);
            Vs16[36*40 + j] = __float2bfloat16(0.0f);
            Vs16[37*40 + j] = __float2bfloat16(0.0f);
            Vs16[38*40 + j] = __float2bfloat16(0.0f);
            Vs16[39*40 + j] = __float2bfloat16(0.0f);
        }
        __syncthreads();

        // ---- S phase ----
        uint32_t kb[4][2][2];
#pragma unroll
        for (int nt = 0; nt < 4; nt++)
#pragma unroll
            for (int s = 0; s < 2; s++) {
                kb[nt][s][0] = Ks[8*nt + g][s*8 + t4];
                kb[nt][s][1] = Ks[8*nt + g][s*8 + t4 + 4];
            }
#pragma unroll
        for (int mt = 0; mt < 4; mt++) {
            const int rb = w*64 + mt*16;
            float S[4][4];
#pragma unroll
            for (int nt = 0; nt < 4; nt++)
#pragma unroll
                for (int q = 0; q < 4; q++) S[nt][q] = 0.0f;
#pragma unroll
            for (int s = 0; s < 2; s++) {
                const int k0 = s*8;
                uint32_t a0 = Qs[rb+g][k0+t4];
                uint32_t a1 = Qs[rb+g+8][k0+t4];
                uint32_t a2 = Qs[rb+g][k0+t4+4];
                uint32_t a3 = Qs[rb+g+8][k0+t4+4];
#pragma unroll
                for (int nt = 0; nt < 4; nt++)
                    mma_bf16(S[nt], a0, a1, a2, a3, kb[nt][s][0], kb[nt][s][1]);
            }
#pragma unroll
            for (int nt = 0; nt < 4; nt++) {
                const int col = 8*nt + 2*t4;
                float m0 = mkf[j0 + col], m1 = mkf[j0 + col + 1];
                Ps[rb+g][nt*4 + t4]   = bf2(m0 * fexp(S[nt][0]), m1 * fexp(S[nt][1]));
                Ps[rb+g+8][nt*4 + t4] = bf2(m0 * fexp(S[nt][2]), m1 * fexp(S[nt][3]));
            }
        }
        __syncwarp();   // warp reads only its own Ps rows

        // ---- O phase ----
        uint32_t vb[5][2][2];
#pragma unroll
        for (int nt = 0; nt < 5; nt++)
#pragma unroll
            for (int s = 0; s < 2; s++) {
                vb[nt][s][0] = Vs[8*nt + g][s*8 + t4];
                vb[nt][s][1] = Vs[8*nt + g][s*8 + t4 + 4];
            }
#pragma unroll
        for (int mt = 0; mt < 4; mt++) {
            const int rb = w*64 + mt*16;
#pragma unroll
            for (int s = 0; s < 2; s++) {
                const int k0 = s*8;
                uint32_t a0 = Ps[rb+g][k0+t4];
                uint32_t a1 = Ps[rb+g+8][k0+t4];
                uint32_t a2 = Ps[rb+g][k0+t4+4];
                uint32_t a3 = Ps[rb+g+8][k0+t4+4];
#pragma unroll
                for (int nt = 0; nt < 5; nt++)
                    mma_bf16(acc[mt][nt], a0, a1, a2, a3, vb[nt][s][0], vb[nt][s][1]);
            }
        }
    }

    // ---- epilogue (fp32) ----
#pragma unroll
    for (int mt = 0; mt < 4; mt++) {
#pragma unroll
        for (int half = 0; half < 2; half++) {
            const int rloc = w*64 + mt*16 + g + half*8;
            const size_t grow = (size_t)b*LL + rloc;
            float c_lo = half ? acc[mt][4][2] : acc[mt][4][0];
            float c_hi = half ? acc[mt][4][3] : acc[mt][4][1];
            const int qb = lane & ~3;
            float ap0 = __shfl_sync(0xffffffffu, c_lo, qb + 0);
            float ap1 = __shfl_sync(0xffffffffu, c_hi, qb + 0);
            float ap2 = __shfl_sync(0xffffffffu, c_lo, qb + 1);
            float s   = __shfl_sync(0xffffffffu, c_hi, qb + 1);
            const bool ok = (mkf[rloc] != 0.0f) && (s > 0.0f);
            const float inv = ok ? 1.0f / s : 0.0f;
            float* fr = g_feat + grow * FEAT;
#pragma unroll
            for (int nt = 0; nt < 4; nt++) {
                float v0 = half ? acc[mt][nt][2] : acc[mt][nt][0];
                float v1 = half ? acc[mt][nt][3] : acc[mt][nt][1];
                *(float2*)&fr[h*32 + 8*nt + 2*t4] = make_float2(v0*inv, v1*inv);
            }
            if (t4 == 0) {
                if (!ok) {
                    fr[512 + h*3+0] = 0.0f; fr[512 + h*3+1] = 0.0f; fr[512 + h*3+2] = 0.0f;
                    fr[560 + h] = 0.0f;
                    fr[576 + h*3+0] = 0.0f; fr[576 + h*3+1] = 0.0f; fr[576 + h*3+2] = 0.0f;
                    fr[624 + h] = 0.0f;
                } else {
                    float a0 = ap0*inv - posCA[grow*3+0];
                    float a1 = ap1*inv - posCA[grow*3+1];
                    float a2 = ap2*inv - posCA[grow*3+2];
                    const float* F = frame + grow * 9;
                    float pt0 = F[0]*a0 + F[1]*a1 + F[2]*a2;
                    float pt1 = F[3]*a0 + F[4]*a1 + F[5]*a2;
                    float pt2 = F[6]*a0 + F[7]*a1 + F[8]*a2;
                    float dist = sqrtf(a0*a0 + a1*a1 + a2*a2);
                    float pn   = sqrtf(pt0*pt0 + pt1*pt1 + pt2*pt2);
                    float id   = 1.0f / (pn + 1e-10f);
                    float ang  = atan2f(pt1, pt0);
                    fr[512 + h*3+0] = pt0; fr[512 + h*3+1] = pt1; fr[512 + h*3+2] = pt2;
                    fr[560 + h] = dist;
                    fr[576 + h*3+0] = pt0*id; fr[576 + h*3+1] = pt1*id; fr[576 + h*3+2] = pt2*id;
                    fr[624 + h] = ang;
                }
            }
        }
    }
}

// ============================================================
// K3a: h1 = relu(feat @ W1 + b1) -> packed bf16 (4096x512,K=640)
// ============================================================
__global__ void __launch_bounds__(256) k_mlp1(
    const float* __restrict__ W1, const float* __restrict__ b1)
{
    const int bm = blockIdx.x * 128;
    const int bn = blockIdx.y * 64;

    GEMM_PROLOG

    for (int ch = 0; ch < FEAT/32; ch++) {
        load_chunkA_bf(As, g_feat, FEAT, bm, ch*32, tid);
        load_chunkB_bf(Bs, W1, HID, bn, ch*32, tid);
        __syncthreads();
        mma_chunk_bf(As, Bs, acc, warpM, warpN, g, t4);
        __syncthreads();
    }

#pragma unroll
    for (int mt = 0; mt < 4; mt++) {
#pragma unroll
        for (int nt = 0; nt < 2; nt++) {
            int R0 = bm + warpM*64 + mt*16 + g;
            int C  = bn + warpN*16 + nt*8 + 2*t4;
            float bx = b1[C], by = b1[C+1];
            g_h1b[(size_t)R0*(HID/2)     + C/2] =
                bf2(fmaxf(acc[mt][nt][0] + bx, 0.f), fmaxf(acc[mt][nt][1] + by, 0.f));
            g_h1b[(size_t)(R0+8)*(HID/2) + C/2] =
                bf2(fmaxf(acc[mt][nt][2] + bx, 0.f), fmaxf(acc[mt][nt][3] + by, 0.f));
        }
    }
}

// ============================================================
// K3b: y = x + mask*(h1 @ W2 + b2)   (4096x256, K=512)
// ============================================================
__global__ void __launch_bounds__(256) k_mlp2(
    const float* __restrict__ x,
    const float* __restrict__ W2, const float* __restrict__ b2,
    const int*   __restrict__ mask)
{
    const int bm = blockIdx.x * 128;
    const int bn = blockIdx.y * 64;

    GEMM_PROLOG

    for (int ch = 0; ch < HID/32; ch++) {
        load_chunkA_pk(As, g_h1b, HID/2, bm, ch*16, tid);
        load_chunkB_bf(Bs, W2, OUTD, bn, ch*32, tid);
        __syncthreads();
        mma_chunk_bf(As, Bs, acc, warpM, warpN, g, t4);
        __syncthreads();
    }

#pragma unroll
    for (int mt = 0; mt < 4; mt++) {
#pragma unroll
        for (int nt = 0; nt < 2; nt++) {
            int R0 = bm + warpM*64 + mt*16 + g;
            int C  = bn + warpN*16 + nt*8 + 2*t4;
            float bx = b2[C], by = b2[C+1];
#pragma unroll
            for (int half = 0; half < 2; half++) {
                int R = R0 + half*8;
                float2 xv = *(const float2*)&x[(size_t)R*OUTD + C];
                float2 v;
                if (mask[R]) {
                    v.x = xv.x + acc[mt][nt][2*half+0] + bx;
                    v.y = xv.y + acc[mt][nt][2*half+1] + by;
                } else {
                    v = xv;
                }
                *(float2*)&g_y[(size_t)R*OUTD + C] = v;
            }
        }
    }
}

// ============================================================
// K4: LayerNorm. One warp per row.
// ============================================================
__global__ void __launch_bounds__(256) k_ln(
    const float* __restrict__ lng, const float* __restrict__ lnb,
    float* __restrict__ out)
{
    const int wid  = threadIdx.x >> 5;
    const int lane = threadIdx.x & 31;
    const int row  = blockIdx.x * 8 + wid;

    const float* yr = g_y + (size_t)row * OUTD;
    float yv[8];
    float ssum = 0.0f, ssq = 0.0f;
#pragma unroll
    for (int t = 0; t < 2; t++) {
        float4 v = *(const float4*)&yr[lane*4 + t*128];
        yv[t*4+0]=v.x; yv[t*4+1]=v.y; yv[t*4+2]=v.z; yv[t*4+3]=v.w;
        ssum += v.x+v.y+v.z+v.w;
        ssq  += v.x*v.x+v.y*v.y+v.z*v.z+v.w*v.w;
    }
#pragma unroll
    for (int off = 16; off > 0; off >>= 1) {
        ssum += __shfl_xor_sync(0xFFFFFFFF, ssum, off);
        ssq  += __shfl_xor_sync(0xFFFFFFFF, ssq,  off);
    }
    float mu  = ssum * (1.0f / OUTD);
    float var = ssq * (1.0f / OUTD) - mu * mu;
    float rs  = rsqrtf(var + 1e-5f);
#pragma unroll
    for (int t = 0; t < 2; t++) {
        int c = lane*4 + t*128;
        float4 gg = *(const float4*)&lng[c];
        float4 bb = *(const float4*)&lnb[c];
        float4 o;
        o.x = (yv[t*4+0]-mu)*rs*gg.x + bb.x;
        o.y = (yv[t*4+1]-mu)*rs*gg.y + bb.y;
        o.z = (yv[t*4+2]-mu)*rs*gg.z + bb.z;
        o.w = (yv[t*4+3]-mu)*rs*gg.w + bb.w;
        *(float4*)&out[(size_t)row*OUTD + c] = o;
    }
}

// ============================================================
extern "C" void kernel_launch(void* const* d_in, const int* in_sizes, int n_in,
                              void* d_out, int out_size)
{
    const float* x     = (const float*)d_in[0];
    const float* posCA = (const float*)d_in[1];
    const float* posCB = (const float*)d_in[2];
    const float* frame = (const float*)d_in[3];
    const int*   mask  = (const int*)  d_in[4];
    const float* Wq    = (const float*)d_in[5];
    const float* Wk    = (const float*)d_in[6];
    const float* Wv    = (const float*)d_in[7];
    const float* seW1  = (const float*)d_in[8];
    const float* seb1  = (const float*)d_in[9];
    const float* seW2  = (const float*)d_in[10];
    const float* seb2  = (const float*)d_in[11];
    const float* otW1  = (const float*)d_in[12];
    const float* otb1  = (const float*)d_in[13];
    const float* otW2  = (const float*)d_in[14];
    const float* otb2  = (const float*)d_in[15];
    const float* lng   = (const float*)d_in[16];
    const float* lnb   = (const float*)d_in[17];
    float* out = (float*)d_out;

    // Qs + Ps + Ks + Vs (uint32) + mkf (float)
    const int smem_attn = (2*512*20 + 32*20 + 40*20) * 4 + 512*4;   // 89728
    cudaFuncSetAttribute(k_attn, cudaFuncAttributeMaxDynamicSharedMemorySize, smem_attn);

    k_spat<<<NL/128, 128>>>(posCA, seW1, seb1);
    k_qkv<<<dim3(NL/128, 24), 256>>>(x, Wq, Wk, Wv, seW2, seb2);
    k_attn<<<dim3(HH, NB), 256, smem_attn>>>(posCA, posCB, frame, mask);
    k_mlp1<<<dim3(NL/128, HID/64),  256>>>(otW1, otb1);
    k_mlp2<<<dim3(NL/128, OUTD/64), 256>>>(x, otW2, otb2, mask);
    k_ln<<<NL/8, 256>>>(lng, lnb, out);
}

// round 7
// speedup vs baseline: 4.3995x; 1.2734x over previous
#include <cuda_runtime.h>
#include <cuda_bf16.h>
#include <math.h>
#include <stdint.h>

// ---------------- problem constants ----------------
#define NB   8
#define LL   512
#define DD   256
#define HH   16
#define QK   32
#define VD   32
#define OUTD 256
#define NL   (NB*LL)          // 4096
#define QKH  (QK*HH)          // 512
#define FEAT 640              // 512 node + 128 spatial
#define HID  512              // OUT*2

// ---------------- bf16 helpers ----------------
__device__ __forceinline__ uint32_t bf2(float lo, float hi) {
    uint32_t d;
    asm("cvt.rn.bf16x2.f32 %0, %1, %2;" : "=r"(d) : "f"(hi), "f"(lo));
    return d;
}
__device__ __forceinline__ void mma_bf16(float c[4],
                                         uint32_t a0, uint32_t a1, uint32_t a2, uint32_t a3,
                                         uint32_t b0, uint32_t b1) {
    asm volatile("mma.sync.aligned.m16n8k16.row.col.f32.bf16.bf16.f32 "
                 "{%0,%1,%2,%3}, {%4,%5,%6,%7}, {%8,%9}, {%0,%1,%2,%3};"
                 : "+f"(c[0]), "+f"(c[1]), "+f"(c[2]), "+f"(c[3])
                 : "r"(a0), "r"(a1), "r"(a2), "r"(a3), "r"(b0), "r"(b1));
}
// ldmatrix x2 transposed: B fragment (k-pairs per n-column) from [k][n] smem
__device__ __forceinline__ uint2 ldsm2t(const void* p) {
    uint32_t a = (uint32_t)__cvta_generic_to_shared(p);
    uint2 r;
    asm volatile("ldmatrix.sync.aligned.m8n8.x2.trans.shared.b16 {%0,%1}, [%2];"
                 : "=r"(r.x), "=r"(r.y) : "r"(a));
    return r;
}

// FMA-only exp (no MUFU). |rel err| ~3e-6.
__device__ __forceinline__ float fexp(float x) {
    float y = x * 1.4426950408889634f;
    float r = y + 12582912.0f;
    int   n = __float_as_int(r) - 0x4B400000;
    float f = y - (r - 12582912.0f);
    float p = 1.3333558146e-3f;
    p = fmaf(p, f, 9.6181291076e-3f);
    p = fmaf(p, f, 5.5504108665e-2f);
    p = fmaf(p, f, 2.4022650696e-1f);
    p = fmaf(p, f, 6.9314718056e-1f);
    p = fmaf(p, f, 1.0f);
    return __int_as_float(__float_as_int(p) + (n << 23));
}

// ---------------- scratch (no allocs allowed) ----------------
__device__ uint32_t g_qb[(size_t)NL*QKH/2];     // bf16x2 packed activations
__device__ uint32_t g_kb[(size_t)NL*QKH/2];
__device__ uint32_t g_vb[(size_t)NL*QKH/2];
__device__ uint32_t g_h1b[(size_t)NL*HID/2];
__device__ uint32_t g_featb[(size_t)NL*FEAT/2];
__device__ float    g_t[(size_t)NL*QK];
__device__ float    g_y[(size_t)NL*OUTD];
// bf16 weights [k][n] (converted once per launch)
__device__ uint32_t g_wq[DD*QKH/2];
__device__ uint32_t g_wk[DD*QKH/2];
__device__ uint32_t g_wv[DD*QKH/2];
__device__ uint32_t g_wse[QK*QKH/2];
__device__ uint32_t g_w1[FEAT*HID/2];
__device__ uint32_t g_w2[HID*OUTD/2];

// ============================================================
// K-1: convert all weights fp32 -> bf16 [k][n]
// ============================================================
__global__ void k_cvtw(const float* __restrict__ Wq, const float* __restrict__ Wk,
                       const float* __restrict__ Wv, const float* __restrict__ seW2,
                       const float* __restrict__ W1, const float* __restrict__ W2)
{
    const int m = blockIdx.y;
    const float* src; uint32_t* dst; int ng;   // groups of 8 elements
    switch (m) {
        case 0: src = Wq;   dst = g_wq;  ng = DD*QKH/8;   break;
        case 1: src = Wk;   dst = g_wk;  ng = DD*QKH/8;   break;
        case 2: src = Wv;   dst = g_wv;  ng = DD*QKH/8;   break;
        case 3: src = seW2; dst = g_wse; ng = QK*QKH/8;   break;
        case 4: src = W1;   dst = g_w1;  ng = FEAT*HID/8; break;
        default:src = W2;   dst = g_w2;  ng = HID*OUTD/8; break;
    }
    int i = blockIdx.x * blockDim.x + threadIdx.x;
    if (i >= ng) return;
    float4 a = ((const float4*)src)[2*i];
    float4 b = ((const float4*)src)[2*i+1];
    uint4 w;
    w.x = bf2(a.x, a.y); w.y = bf2(a.z, a.w);
    w.z = bf2(b.x, b.y); w.w = bf2(b.z, b.w);
    ((uint4*)dst)[i] = w;
}

// ============================================================
// K0: t = relu(pos_CA @ se_W1 + se_b1)   (4096 x 32)
// ============================================================
__global__ void k_spat(const float* __restrict__ posCA,
                       const float* __restrict__ seW1,
                       const float* __restrict__ seb1)
{
    int r = blockIdx.x * blockDim.x + threadIdx.x;
    if (r >= NL) return;
    float p0 = posCA[r*3+0], p1 = posCA[r*3+1], p2 = posCA[r*3+2];
#pragma unroll
    for (int j = 0; j < QK; j++) {
        float v = seb1[j] + p0*seW1[j] + p1*seW1[QK + j] + p2*seW1[2*QK + j];
        g_t[(size_t)r*QK + j] = fmaxf(v, 0.0f);
    }
}

// ============================================================
// GEMM blocks: BM=128, BN=64, BK=32, 8 warps (2M x 4N), m16n8k16.
// As: [128][20] uint32 pairs (scalar frag loads, conflict-free)
// Bs: [32][72] halves natural [k][n], pitch 144B; ldmatrix.trans
// ============================================================
__device__ __forceinline__ void load_chunkA_bf(uint32_t (*As)[20], const float* A,
                                               int lda, int bm, int kc, int tid)
{
    int r = tid >> 1;
    int h = (tid & 1) * 8;
    const float* p = A + (size_t)(bm + r) * lda + kc + h*2;
    float4 v0 = *(const float4*)p;
    float4 v1 = *(const float4*)(p + 4);
    float4 v2 = *(const float4*)(p + 8);
    float4 v3 = *(const float4*)(p + 12);
    uint4 w0, w1;
    w0.x = bf2(v0.x, v0.y); w0.y = bf2(v0.z, v0.w);
    w0.z = bf2(v1.x, v1.y); w0.w = bf2(v1.z, v1.w);
    w1.x = bf2(v2.x, v2.y); w1.y = bf2(v2.z, v2.w);
    w1.z = bf2(v3.x, v3.y); w1.w = bf2(v3.z, v3.w);
    *(uint4*)&As[r][h]     = w0;
    *(uint4*)&As[r][h + 4] = w1;
}

// packed-bf16 activation source: raw copy
__device__ __forceinline__ void load_chunkA_pk(uint32_t (*As)[20], const uint32_t* A,
                                               int ldp, int bm, int kcp, int tid)
{
    int r = tid >> 1;
    int h = (tid & 1) * 8;
    const uint4* p = (const uint4*)(A + (size_t)(bm + r) * ldp + kcp + h);
    *(uint4*)&As[r][h]     = p[0];
    *(uint4*)&As[r][h + 4] = p[1];
}

// B: pre-converted bf16 [k][n] -> raw copy into Bs (pitch 72 halves)
__device__ __forceinline__ void load_chunkB_pk(__nv_bfloat16 (*Bs16)[72], const uint32_t* W,
                                               int ldn, int bn, int kc, int tid)
{
    int k  = tid >> 3;
    int n0 = (tid & 7) * 8;
    uint4 v = *(const uint4*)(W + (size_t)(kc + k) * (ldn/2) + (bn + n0)/2);
    *(uint4*)&Bs16[k][n0] = v;
}

__device__ __forceinline__ void mma_chunk_bf(const uint32_t (*As)[20],
                                             const __nv_bfloat16 (*Bs16)[72],
                                             float acc[4][2][4], int warpM, int warpN,
                                             int g, int t4, int lane)
{
    const int i16 = lane & 15;
#pragma unroll
    for (int s = 0; s < 2; s++) {
        const int k0 = s * 8;   // pair units
        uint2 b[2];
#pragma unroll
        for (int nt = 0; nt < 2; nt++)
            b[nt] = ldsm2t(&Bs16[s*16 + i16][warpN*16 + nt*8]);
#pragma unroll
        for (int mt = 0; mt < 4; mt++) {
            int mr = warpM * 64 + mt * 16;
            uint32_t a0 = As[mr + g][k0 + t4];
            uint32_t a1 = As[mr + g + 8][k0 + t4];
            uint32_t a2 = As[mr + g][k0 + t4 + 4];
            uint32_t a3 = As[mr + g + 8][k0 + t4 + 4];
#pragma unroll
            for (int nt = 0; nt < 2; nt++)
                mma_bf16(acc[mt][nt], a0, a1, a2, a3, b[nt].x, b[nt].y);
        }
    }
}

#define GEMM_PROLOG                                                  \
    __shared__ __align__(16) uint32_t As[128][20];                   \
    __shared__ __align__(16) __nv_bfloat16 Bs16[32][72];             \
    const int tid  = threadIdx.x;                                    \
    const int wid  = tid >> 5;                                       \
    const int lane = tid & 31;                                       \
    const int g    = lane >> 2, t4 = lane & 3;                       \
    const int warpM = wid >> 2, warpN = wid & 3;                     \
    float acc[4][2][4];                                              \
    _Pragma("unroll") for (int i = 0; i < 4; i++)                    \
    _Pragma("unroll") for (int j = 0; j < 2; j++)                    \
    _Pragma("unroll") for (int q = 0; q < 4; q++) acc[i][j][q] = 0.0f;

// ============================================================
// K1: fused QKV projection (4096 x 1536, K=256; q adds t@se_W2+b)
// ============================================================
__global__ void __launch_bounds__(256) k_qkv(
    const float* __restrict__ x, const float* __restrict__ seb2)
{
    const int bm  = blockIdx.x * 128;
    const int mat = blockIdx.y >> 3;           // 0=q 1=k 2=v
    const int bn  = (blockIdx.y & 7) * 64;
    const uint32_t* W = (mat == 0) ? g_wq : (mat == 1) ? g_wk : g_wv;

    GEMM_PROLOG

    const int nchunks = (mat == 0) ? 9 : 8;
    for (int ch = 0; ch < nchunks; ch++) {
        if (ch < 8) { load_chunkA_bf(As, x,   DD, bm, ch*32, tid); load_chunkB_pk(Bs16, W,     QKH, bn, ch*32, tid); }
        else        { load_chunkA_bf(As, g_t, QK, bm, 0,     tid); load_chunkB_pk(Bs16, g_wse, QKH, bn, 0,     tid); }
        __syncthreads();
        mma_chunk_bf(As, Bs16, acc, warpM, warpN, g, t4, lane);
        __syncthreads();
    }

    uint32_t* dst = (mat == 0) ? g_qb : (mat == 1) ? g_kb : g_vb;
#pragma unroll
    for (int mt = 0; mt < 4; mt++) {
#pragma unroll
        for (int nt = 0; nt < 2; nt++) {
            int R0 = bm + warpM*64 + mt*16 + g;
            int C  = bn + warpN*16 + nt*8 + 2*t4;
            float bx = 0.f, by = 0.f;
            if (mat == 0) { bx = seb2[C]; by = seb2[C+1]; }
            dst[(size_t)R0*(QKH/2)     + C/2] = bf2(acc[mt][nt][0] + bx, acc[mt][nt][1] + by);
            dst[(size_t)(R0+8)*(QKH/2) + C/2] = bf2(acc[mt][nt][2] + bx, acc[mt][nt][3] + by);
        }
    }
}

// ============================================================
// K2: bf16 tensor-core attention. Block per (b,h), 8 warps.
// S = Q@K^T ; P = mask*fexp(S) ; O += P @ [V|posCB|1|0]^T
// Vs natural [j][d] pitch 72 halves + ldmatrix.trans fragments.
// ============================================================
__global__ void __launch_bounds__(256, 1) k_attn(
    const float* __restrict__ posCA,
    const float* __restrict__ posCB,
    const float* __restrict__ frame,
    const int*   __restrict__ mask)
{
    extern __shared__ __align__(16) uint32_t smu[];
    uint32_t (*Qs)[20] = (uint32_t (*)[20])smu;                  // [512][20]
    uint32_t (*Ps)[20] = (uint32_t (*)[20])(smu + 512*20);       // [512][20]
    uint32_t (*Ks)[20] = (uint32_t (*)[20])(smu + 2*512*20);     // [32][20]
    __nv_bfloat16 (*Vs16)[72] = (__nv_bfloat16 (*)[72])(smu + 2*512*20 + 32*20); // [32][72]
    float* mkf = (float*)(smu + 2*512*20 + 32*20 + 32*36);       // [512]

    const int h = blockIdx.x;
    const int b = blockIdx.y;
    const int tid = threadIdx.x;
    const int w = tid >> 5, lane = tid & 31;
    const int g = lane >> 2, t4 = lane & 3;
    const int i16 = lane & 15;

    // ---- load Q (raw packed copy) ----
#pragma unroll
    for (int it = 0; it < 8; it++) {
        int idx = tid + 256*it;
        int r = idx >> 2, c4 = idx & 3;
        uint4 wv = *(const uint4*)(g_qb + ((size_t)b*LL + r)*(QKH/2) + h*(QK/2) + c4*4);
        *(uint4*)&Qs[r][c4*4] = wv;
    }
    mkf[tid]       = mask[b*LL + tid]       ? 1.0f : 0.0f;
    mkf[tid + 256] = mask[b*LL + tid + 256] ? 1.0f : 0.0f;

    float acc[4][5][4];
#pragma unroll
    for (int i = 0; i < 4; i++)
#pragma unroll
        for (int j = 0; j < 5; j++)
#pragma unroll
            for (int q = 0; q < 4; q++) acc[i][j][q] = 0.0f;

    for (int ch = 0; ch < 16; ch++) {
        __syncthreads();
        const int j0 = ch * 32;
        if (tid < 128) {       // V raw copy [j][d]
            int j = tid >> 2, c4 = tid & 3;
            uint4 wv = *(const uint4*)(g_vb + ((size_t)b*LL + j0 + j)*(QKH/2) + h*(QK/2) + c4*4);
            *(uint4*)&Vs16[j][c4*8] = wv;
        } else {               // K raw copy [j][pairs]
            int t = tid - 128;
            int j = t >> 2, c4 = t & 3;
            uint4 wv = *(const uint4*)(g_kb + ((size_t)b*LL + j0 + j)*(QKH/2) + h*(QK/2) + c4*4);
            *(uint4*)&Ks[j][c4*4] = wv;
        }
        if (tid < 32) {        // augment columns 32..39 of row j
            int j = tid;
            const float* pp = posCB + ((size_t)b*LL + j0 + j)*3;
            Vs16[j][32] = __float2bfloat16(pp[0]);
            Vs16[j][33] = __float2bfloat16(pp[1]);
            Vs16[j][34] = __float2bfloat16(pp[2]);
            Vs16[j][35] = __float2bfloat16(1.0f);
            Vs16[j][36] = __float2bfloat16(0.0f);
            Vs16[j][37] = __float2bfloat16(0.0f);
            Vs16[j][38] = __float2bfloat16(0.0f);
            Vs16[j][39] = __float2bfloat16(0.0f);
        }
        __syncthreads();

        // ---- S phase ----
        uint32_t kb[4][2][2];
#pragma unroll
        for (int nt = 0; nt < 4; nt++)
#pragma unroll
            for (int s = 0; s < 2; s++) {
                kb[nt][s][0] = Ks[8*nt + g][s*8 + t4];
                kb[nt][s][1] = Ks[8*nt + g][s*8 + t4 + 4];
            }
#pragma unroll
        for (int mt = 0; mt < 4; mt++) {
            const int rb = w*64 + mt*16;
            float S[4][4];
#pragma unroll
            for (int nt = 0; nt < 4; nt++)
#pragma unroll
                for (int q = 0; q < 4; q++) S[nt][q] = 0.0f;
#pragma unroll
            for (int s = 0; s < 2; s++) {
                const int k0 = s*8;
                uint32_t a0 = Qs[rb+g][k0+t4];
                uint32_t a1 = Qs[rb+g+8][k0+t4];
                uint32_t a2 = Qs[rb+g][k0+t4+4];
                uint32_t a3 = Qs[rb+g+8][k0+t4+4];
#pragma unroll
                for (int nt = 0; nt < 4; nt++)
                    mma_bf16(S[nt], a0, a1, a2, a3, kb[nt][s][0], kb[nt][s][1]);
            }
#pragma unroll
            for (int nt = 0; nt < 4; nt++) {
                const int col = 8*nt + 2*t4;
                float m0 = mkf[j0 + col], m1 = mkf[j0 + col + 1];
                Ps[rb+g][nt*4 + t4]   = bf2(m0 * fexp(S[nt][0]), m1 * fexp(S[nt][1]));
                Ps[rb+g+8][nt*4 + t4] = bf2(m0 * fexp(S[nt][2]), m1 * fexp(S[nt][3]));
            }
        }
        __syncwarp();

        // ---- O phase (V fragments via ldmatrix.trans) ----
#pragma unroll
        for (int s = 0; s < 2; s++) {
            uint2 vb[5];
#pragma unroll
            for (int nt = 0; nt < 5; nt++)
                vb[nt] = ldsm2t(&Vs16[s*16 + i16][nt*8]);
            const int k0 = s*8;
#pragma unroll
            for (int mt = 0; mt < 4; mt++) {
                const int rb = w*64 + mt*16;
                uint32_t a0 = Ps[rb+g][k0+t4];
                uint32_t a1 = Ps[rb+g+8][k0+t4];
                uint32_t a2 = Ps[rb+g][k0+t4+4];
                uint32_t a3 = Ps[rb+g+8][k0+t4+4];
#pragma unroll
                for (int nt = 0; nt < 5; nt++)
                    mma_bf16(acc[mt][nt], a0, a1, a2, a3, vb[nt].x, vb[nt].y);
            }
        }
    }

    // ---- epilogue (fp32 math, bf16 feature stores) ----
#pragma unroll
    for (int mt = 0; mt < 4; mt++) {
#pragma unroll
        for (int half = 0; half < 2; half++) {
            const int rloc = w*64 + mt*16 + g + half*8;
            const size_t grow = (size_t)b*LL + rloc;
            float c_lo = half ? acc[mt][4][2] : acc[mt][4][0];
            float c_hi = half ? acc[mt][4][3] : acc[mt][4][1];
            const int qb = lane & ~3;
            float ap0 = __shfl_sync(0xffffffffu, c_lo, qb + 0);
            float ap1 = __shfl_sync(0xffffffffu, c_hi, qb + 0);
            float ap2 = __shfl_sync(0xffffffffu, c_lo, qb + 1);
            float s   = __shfl_sync(0xffffffffu, c_hi, qb + 1);
            const bool ok = (mkf[rloc] != 0.0f) && (s > 0.0f);
            const float inv = ok ? 1.0f / s : 0.0f;
            uint32_t* fr = g_featb + grow * (FEAT/2);
            __nv_bfloat16* fr16 = (__nv_bfloat16*)fr;
#pragma unroll
            for (int nt = 0; nt < 4; nt++) {
                float v0 = half ? acc[mt][nt][2] : acc[mt][nt][0];
                float v1 = half ? acc[mt][nt][3] : acc[mt][nt][1];
                fr[h*16 + nt*4 + t4] = bf2(v0*inv, v1*inv);
            }
            if (t4 == 0) {
                if (!ok) {
                    fr16[512+h*3+0] = __float2bfloat16(0.0f);
                    fr16[512+h*3+1] = __float2bfloat16(0.0f);
                    fr16[512+h*3+2] = __float2bfloat16(0.0f);
                    fr16[560+h]     = __float2bfloat16(0.0f);
                    fr16[576+h*3+0] = __float2bfloat16(0.0f);
                    fr16[576+h*3+1] = __float2bfloat16(0.0f);
                    fr16[576+h*3+2] = __float2bfloat16(0.0f);
                    fr16[624+h]     = __float2bfloat16(0.0f);
                } else {
                    float a0 = ap0*inv - posCA[grow*3+0];
                    float a1 = ap1*inv - posCA[grow*3+1];
                    float a2 = ap2*inv - posCA[grow*3+2];
                    const float* F = frame + grow * 9;
                    float pt0 = F[0]*a0 + F[1]*a1 + F[2]*a2;
                    float pt1 = F[3]*a0 + F[4]*a1 + F[5]*a2;
                    float pt2 = F[6]*a0 + F[7]*a1 + F[8]*a2;
                    float dist = sqrtf(a0*a0 + a1*a1 + a2*a2);
                    float pn   = sqrtf(pt0*pt0 + pt1*pt1 + pt2*pt2);
                    float id   = 1.0f / (pn + 1e-10f);
                    float ang  = atan2f(pt1, pt0);
                    fr16[512+h*3+0] = __float2bfloat16(pt0);
                    fr16[512+h*3+1] = __float2bfloat16(pt1);
                    fr16[512+h*3+2] = __float2bfloat16(pt2);
                    fr16[560+h]     = __float2bfloat16(dist);
                    fr16[576+h*3+0] = __float2bfloat16(pt0*id);
                    fr16[576+h*3+1] = __float2bfloat16(pt1*id);
                    fr16[576+h*3+2] = __float2bfloat16(pt2*id);
                    fr16[624+h]     = __float2bfloat16(ang);
                }
            }
        }
    }
}

// ============================================================
// K3a: h1 = relu(feat @ W1 + b1) -> packed bf16 (4096x512,K=640)
// ============================================================
__global__ void __launch_bounds__(256) k_mlp1(const float* __restrict__ b1)
{
    const int bm = blockIdx.x * 128;
    const int bn = blockIdx.y * 64;

    GEMM_PROLOG

    for (int ch = 0; ch < FEAT/32; ch++) {
        load_chunkA_pk(As, g_featb, FEAT/2, bm, ch*16, tid);
        load_chunkB_pk(Bs16, g_w1, HID, bn, ch*32, tid);
        __syncthreads();
        mma_chunk_bf(As, Bs16, acc, warpM, warpN, g, t4, lane);
        __syncthreads();
    }

#pragma unroll
    for (int mt = 0; mt < 4; mt++) {
#pragma unroll
        for (int nt = 0; nt < 2; nt++) {
            int R0 = bm + warpM*64 + mt*16 + g;
            int C  = bn + warpN*16 + nt*8 + 2*t4;
            float bx = b1[C], by = b1[C+1];
            g_h1b[(size_t)R0*(HID/2)     + C/2] =
                bf2(fmaxf(acc[mt][nt][0] + bx, 0.f), fmaxf(acc[mt][nt][1] + by, 0.f));
            g_h1b[(size_t)(R0+8)*(HID/2) + C/2] =
                bf2(fmaxf(acc[mt][nt][2] + bx, 0.f), fmaxf(acc[mt][nt][3] + by, 0.f));
        }
    }
}

// ============================================================
// K3b: y = x + mask*(h1 @ W2 + b2)   (4096x256, K=512)
// ============================================================
__global__ void __launch_bounds__(256) k_mlp2(
    const float* __restrict__ x, const float* __restrict__ b2,
    const int* __restrict__ mask)
{
    const int bm = blockIdx.x * 128;
    const int bn = blockIdx.y * 64;

    GEMM_PROLOG

    for (int ch = 0; ch < HID/32; ch++) {
        load_chunkA_pk(As, g_h1b, HID/2, bm, ch*16, tid);
        load_chunkB_pk(Bs16, g_w2, OUTD, bn, ch*32, tid);
        __syncthreads();
        mma_chunk_bf(As, Bs16, acc, warpM, warpN, g, t4, lane);
        __syncthreads();
    }

#pragma unroll
    for (int mt = 0; mt < 4; mt++) {
#pragma unroll
        for (int nt = 0; nt < 2; nt++) {
            int R0 = bm + warpM*64 + mt*16 + g;
            int C  = bn + warpN*16 + nt*8 + 2*t4;
            float bx = b2[C], by = b2[C+1];
#pragma unroll
            for (int half = 0; half < 2; half++) {
                int R = R0 + half*8;
                float2 xv = *(const float2*)&x[(size_t)R*OUTD + C];
                float2 v;
                if (mask[R]) {
                    v.x = xv.x + acc[mt][nt][2*half+0] + bx;
                    v.y = xv.y + acc[mt][nt][2*half+1] + by;
                } else {
                    v = xv;
                }
                *(float2*)&g_y[(size_t)R*OUTD + C] = v;
            }
        }
    }
}

// ============================================================
// K4: LayerNorm. One warp per row.
// ============================================================
__global__ void __launch_bounds__(256) k_ln(
    const float* __restrict__ lng, const float* __restrict__ lnb,
    float* __restrict__ out)
{
    const int wid  = threadIdx.x >> 5;
    const int lane = threadIdx.x & 31;
    const int row  = blockIdx.x * 8 + wid;

    const float* yr = g_y + (size_t)row * OUTD;
    float yv[8];
    float ssum = 0.0f, ssq = 0.0f;
#pragma unroll
    for (int t = 0; t < 2; t++) {
        float4 v = *(const float4*)&yr[lane*4 + t*128];
        yv[t*4+0]=v.x; yv[t*4+1]=v.y; yv[t*4+2]=v.z; yv[t*4+3]=v.w;
        ssum += v.x+v.y+v.z+v.w;
        ssq  += v.x*v.x+v.y*v.y+v.z*v.z+v.w*v.w;
    }
#pragma unroll
    for (int off = 16; off > 0; off >>= 1) {
        ssum += __shfl_xor_sync(0xFFFFFFFF, ssum, off);
        ssq  += __shfl_xor_sync(0xFFFFFFFF, ssq,  off);
    }
    float mu  = ssum * (1.0f / OUTD);
    float var = ssq * (1.0f / OUTD) - mu * mu;
    float rs  = rsqrtf(var + 1e-5f);
#pragma unroll
    for (int t = 0; t < 2; t++) {
        int c = lane*4 + t*128;
        float4 gg = *(const float4*)&lng[c];
        float4 bb = *(const float4*)&lnb[c];
        float4 o;
        o.x = (yv[t*4+0]-mu)*rs*gg.x + bb.x;
        o.y = (yv[t*4+1]-mu)*rs*gg.y + bb.y;
        o.z = (yv[t*4+2]-mu)*rs*gg.z + bb.z;
        o.w = (yv[t*4+3]-mu)*rs*gg.w + bb.w;
        *(float4*)&out[(size_t)row*OUTD + c] = o;
    }
}

// ============================================================
extern "C" void kernel_launch(void* const* d_in, const int* in_sizes, int n_in,
                              void* d_out, int out_size)
{
    const float* x     = (const float*)d_in[0];
    const float* posCA = (const float*)d_in[1];
    const float* posCB = (const float*)d_in[2];
    const float* frame = (const float*)d_in[3];
    const int*   mask  = (const int*)  d_in[4];
    const float* Wq    = (const float*)d_in[5];
    const float* Wk    = (const float*)d_in[6];
    const float* Wv    = (const float*)d_in[7];
    const float* seW1  = (const float*)d_in[8];
    const float* seb1  = (const float*)d_in[9];
    const float* seW2  = (const float*)d_in[10];
    const float* seb2  = (const float*)d_in[11];
    const float* otW1  = (const float*)d_in[12];
    const float* otb1  = (const float*)d_in[13];
    const float* otW2  = (const float*)d_in[14];
    const float* otb2  = (const float*)d_in[15];
    const float* lng   = (const float*)d_in[16];
    const float* lnb   = (const float*)d_in[17];
    float* out = (float*)d_out;

    // Qs + Ps + Ks (uint32) + Vs16 (halves) + mkf (float)
    const int smem_attn = (2*512*20 + 32*20 + 32*36) * 4 + 512*4;   // ~91KB
    cudaFuncSetAttribute(k_attn, cudaFuncAttributeMaxDynamicSharedMemorySize, smem_attn);

    k_cvtw<<<dim3(160, 6), 256>>>(Wq, Wk, Wv, seW2, otW1, otW2);
    k_spat<<<NL/128, 128>>>(posCA, seW1, seb1);
    k_qkv<<<dim3(NL/128, 24), 256>>>(x, seb2);
    k_attn<<<dim3(HH, NB), 256, smem_attn>>>(posCA, posCB, frame, mask);
    k_mlp1<<<dim3(NL/128, HID/64),  256>>>(otb1);
    k_mlp2<<<dim3(NL/128, OUTD/64), 256>>>(x, otb2, mask);
    k_ln<<<NL/8, 256>>>(lng, lnb, out);
}

// round 9
// speedup vs baseline: 4.5370x; 1.0312x over previous
#include <cuda_runtime.h>
#include <cuda_bf16.h>
#include <math.h>
#include <stdint.h>

// ---------------- problem constants ----------------
#define NB   8
#define LL   512
#define DD   256
#define HH   16
#define QK   32
#define VD   32
#define OUTD 256
#define NL   (NB*LL)          // 4096
#define QKH  (QK*HH)          // 512
#define FEAT 640              // 512 node + 128 spatial
#define HID  512              // OUT*2

// ---------------- bf16 helpers ----------------
__device__ __forceinline__ uint32_t bf2(float lo, float hi) {
    uint32_t d;
    asm("cvt.rn.bf16x2.f32 %0, %1, %2;" : "=r"(d) : "f"(hi), "f"(lo));
    return d;
}
__device__ __forceinline__ void mma_bf16(float c[4],
                                         uint32_t a0, uint32_t a1, uint32_t a2, uint32_t a3,
                                         uint32_t b0, uint32_t b1) {
    asm volatile("mma.sync.aligned.m16n8k16.row.col.f32.bf16.bf16.f32 "
                 "{%0,%1,%2,%3}, {%4,%5,%6,%7}, {%8,%9}, {%0,%1,%2,%3};"
                 : "+f"(c[0]), "+f"(c[1]), "+f"(c[2]), "+f"(c[3])
                 : "r"(a0), "r"(a1), "r"(a2), "r"(a3), "r"(b0), "r"(b1));
}
// ldmatrix x2 transposed: B fragment (k-pairs per n-column) from [k][n] smem
__device__ __forceinline__ uint2 ldsm2t(const void* p) {
    uint32_t a = (uint32_t)__cvta_generic_to_shared(p);
    uint2 r;
    asm volatile("ldmatrix.sync.aligned.m8n8.x2.trans.shared.b16 {%0,%1}, [%2];"
                 : "=r"(r.x), "=r"(r.y) : "r"(a));
    return r;
}

// FMA-only exp (no MUFU). |rel err| ~3e-6.
__device__ __forceinline__ float fexp(float x) {
    float y = x * 1.4426950408889634f;
    float r = y + 12582912.0f;
    int   n = __float_as_int(r) - 0x4B400000;
    float f = y - (r - 12582912.0f);
    float p = 1.3333558146e-3f;
    p = fmaf(p, f, 9.6181291076e-3f);
    p = fmaf(p, f, 5.5504108665e-2f);
    p = fmaf(p, f, 2.4022650696e-1f);
    p = fmaf(p, f, 6.9314718056e-1f);
    p = fmaf(p, f, 1.0f);
    return __int_as_float(__float_as_int(p) + (n << 23));
}

// ---------------- scratch (no allocs allowed) ----------------
__device__ uint32_t g_qb[(size_t)NL*QKH/2];     // bf16x2 packed activations
__device__ uint32_t g_kb[(size_t)NL*QKH/2];
__device__ uint32_t g_vb[(size_t)NL*QKH/2];
__device__ uint32_t g_h1b[(size_t)NL*HID/2];
__device__ uint32_t g_featb[(size_t)NL*FEAT/2];
__device__ float    g_t[(size_t)NL*QK];
__device__ float    g_y[(size_t)NL*OUTD];
// bf16 weights [k][n] (converted once per launch)
__device__ uint32_t g_wq[DD*QKH/2];
__device__ uint32_t g_wk[DD*QKH/2];
__device__ uint32_t g_wv[DD*QKH/2];
__device__ uint32_t g_wse[QK*QKH/2];
__device__ uint32_t g_w1[FEAT*HID/2];
__device__ uint32_t g_w2[HID*OUTD/2];

// ============================================================
// K-1: convert all weights fp32 -> bf16 [k][n]
// ============================================================
__global__ void k_cvtw(const float* __restrict__ Wq, const float* __restrict__ Wk,
                       const float* __restrict__ Wv, const float* __restrict__ seW2,
                       const float* __restrict__ W1, const float* __restrict__ W2)
{
    const int m = blockIdx.y;
    const float* src; uint32_t* dst; int ng;   // groups of 8 elements
    switch (m) {
        case 0: src = Wq;   dst = g_wq;  ng = DD*QKH/8;   break;
        case 1: src = Wk;   dst = g_wk;  ng = DD*QKH/8;   break;
        case 2: src = Wv;   dst = g_wv;  ng = DD*QKH/8;   break;
        case 3: src = seW2; dst = g_wse; ng = QK*QKH/8;   break;
        case 4: src = W1;   dst = g_w1;  ng = FEAT*HID/8; break;
        default:src = W2;   dst = g_w2;  ng = HID*OUTD/8; break;
    }
    int i = blockIdx.x * blockDim.x + threadIdx.x;
    if (i >= ng) return;
    float4 a = ((const float4*)src)[2*i];
    float4 b = ((const float4*)src)[2*i+1];
    uint4 w;
    w.x = bf2(a.x, a.y); w.y = bf2(a.z, a.w);
    w.z = bf2(b.x, b.y); w.w = bf2(b.z, b.w);
    ((uint4*)dst)[i] = w;
}

// ============================================================
// K0: t = relu(pos_CA @ se_W1 + se_b1)   (4096 x 32)
// ============================================================
__global__ void k_spat(const float* __restrict__ posCA,
                       const float* __restrict__ seW1,
                       const float* __restrict__ seb1)
{
    int r = blockIdx.x * blockDim.x + threadIdx.x;
    if (r >= NL) return;
    float p0 = posCA[r*3+0], p1 = posCA[r*3+1], p2 = posCA[r*3+2];
#pragma unroll
    for (int j = 0; j < QK; j++) {
        float v = seb1[j] + p0*seW1[j] + p1*seW1[QK + j] + p2*seW1[2*QK + j];
        g_t[(size_t)r*QK + j] = fmaxf(v, 0.0f);
    }
}

// ============================================================
// GEMM blocks: BM=128, BN=64, BK=32, 8 warps (2M x 4N), m16n8k16.
// As: [128][20] uint32 pairs; Bs: [32][72] halves natural [k][n]
// ============================================================
__device__ __forceinline__ void load_chunkA_bf(uint32_t (*As)[20], const float* A,
                                               int lda, int bm, int kc, int tid)
{
    int r = tid >> 1;
    int h = (tid & 1) * 8;
    const float* p = A + (size_t)(bm + r) * lda + kc + h*2;
    float4 v0 = *(const float4*)p;
    float4 v1 = *(const float4*)(p + 4);
    float4 v2 = *(const float4*)(p + 8);
    float4 v3 = *(const float4*)(p + 12);
    uint4 w0, w1;
    w0.x = bf2(v0.x, v0.y); w0.y = bf2(v0.z, v0.w);
    w0.z = bf2(v1.x, v1.y); w0.w = bf2(v1.z, v1.w);
    w1.x = bf2(v2.x, v2.y); w1.y = bf2(v2.z, v2.w);
    w1.z = bf2(v3.x, v3.y); w1.w = bf2(v3.z, v3.w);
    *(uint4*)&As[r][h]     = w0;
    *(uint4*)&As[r][h + 4] = w1;
}

__device__ __forceinline__ void load_chunkA_pk(uint32_t (*As)[20], const uint32_t* A,
                                               int ldp, int bm, int kcp, int tid)
{
    int r = tid >> 1;
    int h = (tid & 1) * 8;
    const uint4* p = (const uint4*)(A + (size_t)(bm + r) * ldp + kcp + h);
    *(uint4*)&As[r][h]     = p[0];
    *(uint4*)&As[r][h + 4] = p[1];
}

__device__ __forceinline__ void load_chunkB_pk(__nv_bfloat16 (*Bs16)[72], const uint32_t* W,
                                               int ldn, int bn, int kc, int tid)
{
    int k  = tid >> 3;
    int n0 = (tid & 7) * 8;
    uint4 v = *(const uint4*)(W + (size_t)(kc + k) * (ldn/2) + (bn + n0)/2);
    *(uint4*)&Bs16[k][n0] = v;
}

__device__ __forceinline__ void mma_chunk_bf(const uint32_t (*As)[20],
                                             const __nv_bfloat16 (*Bs16)[72],
                                             float acc[4][2][4], int warpM, int warpN,
                                             int g, int t4, int lane)
{
    const int i16 = lane & 15;
#pragma unroll
    for (int s = 0; s < 2; s++) {
        const int k0 = s * 8;   // pair units
        uint2 b[2];
#pragma unroll
        for (int nt = 0; nt < 2; nt++)
            b[nt] = ldsm2t(&Bs16[s*16 + i16][warpN*16 + nt*8]);
#pragma unroll
        for (int mt = 0; mt < 4; mt++) {
            int mr = warpM * 64 + mt * 16;
            uint32_t a0 = As[mr + g][k0 + t4];
            uint32_t a1 = As[mr + g + 8][k0 + t4];
            uint32_t a2 = As[mr + g][k0 + t4 + 4];
            uint32_t a3 = As[mr + g + 8][k0 + t4 + 4];
#pragma unroll
            for (int nt = 0; nt < 2; nt++)
                mma_bf16(acc[mt][nt], a0, a1, a2, a3, b[nt].x, b[nt].y);
        }
    }
}

#define GEMM_PROLOG                                                  \
    __shared__ __align__(16) uint32_t As[128][20];                   \
    __shared__ __align__(16) __nv_bfloat16 Bs16[32][72];             \
    const int tid  = threadIdx.x;                                    \
    const int wid  = tid >> 5;                                       \
    const int lane = tid & 31;                                       \
    const int g    = lane >> 2, t4 = lane & 3;                       \
    const int warpM = wid >> 2, warpN = wid & 3;                     \
    float acc[4][2][4];                                              \
    _Pragma("unroll") for (int i = 0; i < 4; i++)                    \
    _Pragma("unroll") for (int j = 0; j < 2; j++)                    \
    _Pragma("unroll") for (int q = 0; q < 4; q++) acc[i][j][q] = 0.0f;

// ============================================================
// K1: fused QKV projection (4096 x 1536, K=256; q adds t@se_W2+b)
// ============================================================
__global__ void __launch_bounds__(256) k_qkv(
    const float* __restrict__ x, const float* __restrict__ seb2)
{
    const int bm  = blockIdx.x * 128;
    const int mat = blockIdx.y >> 3;           // 0=q 1=k 2=v
    const int bn  = (blockIdx.y & 7) * 64;
    const uint32_t* W = (mat == 0) ? g_wq : (mat == 1) ? g_wk : g_wv;

    GEMM_PROLOG

    const int nchunks = (mat == 0) ? 9 : 8;
    for (int ch = 0; ch < nchunks; ch++) {
        if (ch < 8) { load_chunkA_bf(As, x,   DD, bm, ch*32, tid); load_chunkB_pk(Bs16, W,     QKH, bn, ch*32, tid); }
        else        { load_chunkA_bf(As, g_t, QK, bm, 0,     tid); load_chunkB_pk(Bs16, g_wse, QKH, bn, 0,     tid); }
        __syncthreads();
        mma_chunk_bf(As, Bs16, acc, warpM, warpN, g, t4, lane);
        __syncthreads();
    }

    uint32_t* dst = (mat == 0) ? g_qb : (mat == 1) ? g_kb : g_vb;
#pragma unroll
    for (int mt = 0; mt < 4; mt++) {
#pragma unroll
        for (int nt = 0; nt < 2; nt++) {
            int R0 = bm + warpM*64 + mt*16 + g;
            int C  = bn + warpN*16 + nt*8 + 2*t4;
            float bx = 0.f, by = 0.f;
            if (mat == 0) { bx = seb2[C]; by = seb2[C+1]; }
            dst[(size_t)R0*(QKH/2)     + C/2] = bf2(acc[mt][nt][0] + bx, acc[mt][nt][1] + by);
            dst[(size_t)(R0+8)*(QKH/2) + C/2] = bf2(acc[mt][nt][2] + bx, acc[mt][nt][3] + by);
        }
    }
}

// ============================================================
// K2: bf16 tensor-core attention, q-split for occupancy.
// Grid (HH, NB, 2): each block = 256 q-rows of one (b,h).
// 8 warps x 32 rows. S = Q@K^T ; P = mask*fexp(S) ;
// O += P @ [V|posCB|1|0]^T. 2 CTAs/SM (50KB smem, <=128 regs).
// ============================================================
__global__ void __launch_bounds__(256, 2) k_attn(
    const float* __restrict__ posCA,
    const float* __restrict__ posCB,
    const float* __restrict__ frame,
    const int*   __restrict__ mask)
{
    extern __shared__ __align__(16) uint32_t smu[];
    uint32_t (*Qs)[20] = (uint32_t (*)[20])smu;                  // [256][20]
    uint32_t (*Ps)[20] = (uint32_t (*)[20])(smu + 256*20);       // [256][20]
    uint32_t (*Ks)[20] = (uint32_t (*)[20])(smu + 2*256*20);     // [32][20]
    __nv_bfloat16 (*Vs16)[72] = (__nv_bfloat16 (*)[72])(smu + 2*256*20 + 32*20); // [32][72]
    float* mkf = (float*)(smu + 2*256*20 + 32*20 + 32*36);       // [512]

    const int h  = blockIdx.x;
    const int b  = blockIdx.y;
    const int qh = blockIdx.z;            // q-half: rows qh*256 ..
    const int tid = threadIdx.x;
    const int w = tid >> 5, lane = tid & 31;
    const int g = lane >> 2, t4 = lane & 3;
    const int i16 = lane & 15;
    const int qbase = qh * 256;

    // ---- load Q half (raw packed copy): 256 rows x 4 uint4 ----
#pragma unroll
    for (int it = 0; it < 4; it++) {
        int idx = tid + 256*it;
        int r = idx >> 2, c4 = idx & 3;
        uint4 wv = *(const uint4*)(g_qb + ((size_t)b*LL + qbase + r)*(QKH/2) + h*(QK/2) + c4*4);
        *(uint4*)&Qs[r][c4*4] = wv;
    }
    mkf[tid]       = mask[b*LL + tid]       ? 1.0f : 0.0f;
    mkf[tid + 256] = mask[b*LL + tid + 256] ? 1.0f : 0.0f;

    float acc[2][5][4];
#pragma unroll
    for (int i = 0; i < 2; i++)
#pragma unroll
        for (int j = 0; j < 5; j++)
#pragma unroll
            for (int q = 0; q < 4; q++) acc[i][j][q] = 0.0f;

    for (int ch = 0; ch < 16; ch++) {
        __syncthreads();
        const int j0 = ch * 32;
        if (tid < 128) {       // V raw copy [j][d]
            int j = tid >> 2, c4 = tid & 3;
            uint4 wv = *(const uint4*)(g_vb + ((size_t)b*LL + j0 + j)*(QKH/2) + h*(QK/2) + c4*4);
            *(uint4*)&Vs16[j][c4*8] = wv;
        } else {               // K raw copy [j][pairs]
            int t = tid - 128;
            int j = t >> 2, c4 = t & 3;
            uint4 wv = *(const uint4*)(g_kb + ((size_t)b*LL + j0 + j)*(QKH/2) + h*(QK/2) + c4*4);
            *(uint4*)&Ks[j][c4*4] = wv;
        }
        if (tid < 32) {        // augment columns 32..39 of row j
            int j = tid;
            const float* pp = posCB + ((size_t)b*LL + j0 + j)*3;
            Vs16[j][32] = __float2bfloat16(pp[0]);
            Vs16[j][33] = __float2bfloat16(pp[1]);
            Vs16[j][34] = __float2bfloat16(pp[2]);
            Vs16[j][35] = __float2bfloat16(1.0f);
            Vs16[j][36] = __float2bfloat16(0.0f);
            Vs16[j][37] = __float2bfloat16(0.0f);
            Vs16[j][38] = __float2bfloat16(0.0f);
            Vs16[j][39] = __float2bfloat16(0.0f);
        }
        __syncthreads();

        // ---- S phase ----
        uint32_t kb[4][2][2];
#pragma unroll
        for (int nt = 0; nt < 4; nt++)
#pragma unroll
            for (int s = 0; s < 2; s++) {
                kb[nt][s][0] = Ks[8*nt + g][s*8 + t4];
                kb[nt][s][1] = Ks[8*nt + g][s*8 + t4 + 4];
            }
#pragma unroll
        for (int mt = 0; mt < 2; mt++) {
            const int rb = w*32 + mt*16;
            float S[4][4];
#pragma unroll
            for (int nt = 0; nt < 4; nt++)
#pragma unroll
                for (int q = 0; q < 4; q++) S[nt][q] = 0.0f;
#pragma unroll
            for (int s = 0; s < 2; s++) {
                const int k0 = s*8;
                uint32_t a0 = Qs[rb+g][k0+t4];
                uint32_t a1 = Qs[rb+g+8][k0+t4];
                uint32_t a2 = Qs[rb+g][k0+t4+4];
                uint32_t a3 = Qs[rb+g+8][k0+t4+4];
#pragma unroll
                for (int nt = 0; nt < 4; nt++)
                    mma_bf16(S[nt], a0, a1, a2, a3, kb[nt][s][0], kb[nt][s][1]);
            }
#pragma unroll
            for (int nt = 0; nt < 4; nt++) {
                const int col = 8*nt + 2*t4;
                float m0 = mkf[j0 + col], m1 = mkf[j0 + col + 1];
                Ps[rb+g][nt*4 + t4]   = bf2(m0 * fexp(S[nt][0]), m1 * fexp(S[nt][1]));
                Ps[rb+g+8][nt*4 + t4] = bf2(m0 * fexp(S[nt][2]), m1 * fexp(S[nt][3]));
            }
        }
        __syncwarp();

        // ---- O phase (V fragments via ldmatrix.trans) ----
#pragma unroll
        for (int s = 0; s < 2; s++) {
            uint2 vb[5];
#pragma unroll
            for (int nt = 0; nt < 5; nt++)
                vb[nt] = ldsm2t(&Vs16[s*16 + i16][nt*8]);
            const int k0 = s*8;
#pragma unroll
            for (int mt = 0; mt < 2; mt++) {
                const int rb = w*32 + mt*16;
                uint32_t a0 = Ps[rb+g][k0+t4];
                uint32_t a1 = Ps[rb+g+8][k0+t4];
                uint32_t a2 = Ps[rb+g][k0+t4+4];
                uint32_t a3 = Ps[rb+g+8][k0+t4+4];
#pragma unroll
                for (int nt = 0; nt < 5; nt++)
                    mma_bf16(acc[mt][nt], a0, a1, a2, a3, vb[nt].x, vb[nt].y);
            }
        }
    }

    // ---- epilogue (fp32 math, bf16 feature stores) ----
#pragma unroll
    for (int mt = 0; mt < 2; mt++) {
#pragma unroll
        for (int half = 0; half < 2; half++) {
            const int rloc = w*32 + mt*16 + g + half*8;
            const size_t grow = (size_t)b*LL + qbase + rloc;
            float c_lo = half ? acc[mt][4][2] : acc[mt][4][0];
            float c_hi = half ? acc[mt][4][3] : acc[mt][4][1];
            const int qb = lane & ~3;
            float ap0 = __shfl_sync(0xffffffffu, c_lo, qb + 0);
            float ap1 = __shfl_sync(0xffffffffu, c_hi, qb + 0);
            float ap2 = __shfl_sync(0xffffffffu, c_lo, qb + 1);
            float s   = __shfl_sync(0xffffffffu, c_hi, qb + 1);
            const bool ok = (mkf[qbase + rloc] != 0.0f) && (s > 0.0f);
            const float inv = ok ? 1.0f / s : 0.0f;
            uint32_t* fr = g_featb + grow * (FEAT/2);
            __nv_bfloat16* fr16 = (__nv_bfloat16*)fr;
#pragma unroll
            for (int nt = 0; nt < 4; nt++) {
                float v0 = half ? acc[mt][nt][2] : acc[mt][nt][0];
                float v1 = half ? acc[mt][nt][3] : acc[mt][nt][1];
                fr[h*16 + nt*4 + t4] = bf2(v0*inv, v1*inv);
            }
            if (t4 == 0) {
                if (!ok) {
                    fr16[512+h*3+0] = __float2bfloat16(0.0f);
                    fr16[512+h*3+1] = __float2bfloat16(0.0f);
                    fr16[512+h*3+2] = __float2bfloat16(0.0f);
                    fr16[560+h]     = __float2bfloat16(0.0f);
                    fr16[576+h*3+0] = __float2bfloat16(0.0f);
                    fr16[576+h*3+1] = __float2bfloat16(0.0f);
                    fr16[576+h*3+2] = __float2bfloat16(0.0f);
                    fr16[624+h]     = __float2bfloat16(0.0f);
                } else {
                    float a0 = ap0*inv - posCA[grow*3+0];
                    float a1 = ap1*inv - posCA[grow*3+1];
                    float a2 = ap2*inv - posCA[grow*3+2];
                    const float* F = frame + grow * 9;
                    float pt0 = F[0]*a0 + F[1]*a1 + F[2]*a2;
                    float pt1 = F[3]*a0 + F[4]*a1 + F[5]*a2;
                    float pt2 = F[6]*a0 + F[7]*a1 + F[8]*a2;
                    float dist = sqrtf(a0*a0 + a1*a1 + a2*a2);
                    float pn   = sqrtf(pt0*pt0 + pt1*pt1 + pt2*pt2);
                    float id   = 1.0f / (pn + 1e-10f);
                    float ang  = atan2f(pt1, pt0);
                    fr16[512+h*3+0] = __float2bfloat16(pt0);
                    fr16[512+h*3+1] = __float2bfloat16(pt1);
                    fr16[512+h*3+2] = __float2bfloat16(pt2);
                    fr16[560+h]     = __float2bfloat16(dist);
                    fr16[576+h*3+0] = __float2bfloat16(pt0*id);
                    fr16[576+h*3+1] = __float2bfloat16(pt1*id);
                    fr16[576+h*3+2] = __float2bfloat16(pt2*id);
                    fr16[624+h]     = __float2bfloat16(ang);
                }
            }
        }
    }
}

// ============================================================
// K3a: h1 = relu(feat @ W1 + b1) -> packed bf16 (4096x512,K=640)
// ============================================================
__global__ void __launch_bounds__(256) k_mlp1(const float* __restrict__ b1)
{
    const int bm = blockIdx.x * 128;
    const int bn = blockIdx.y * 64;

    GEMM_PROLOG

    for (int ch = 0; ch < FEAT/32; ch++) {
        load_chunkA_pk(As, g_featb, FEAT/2, bm, ch*16, tid);
        load_chunkB_pk(Bs16, g_w1, HID, bn, ch*32, tid);
        __syncthreads();
        mma_chunk_bf(As, Bs16, acc, warpM, warpN, g, t4, lane);
        __syncthreads();
    }

#pragma unroll
    for (int mt = 0; mt < 4; mt++) {
#pragma unroll
        for (int nt = 0; nt < 2; nt++) {
            int R0 = bm + warpM*64 + mt*16 + g;
            int C  = bn + warpN*16 + nt*8 + 2*t4;
            float bx = b1[C], by = b1[C+1];
            g_h1b[(size_t)R0*(HID/2)     + C/2] =
                bf2(fmaxf(acc[mt][nt][0] + bx, 0.f), fmaxf(acc[mt][nt][1] + by, 0.f));
            g_h1b[(size_t)(R0+8)*(HID/2) + C/2] =
                bf2(fmaxf(acc[mt][nt][2] + bx, 0.f), fmaxf(acc[mt][nt][3] + by, 0.f));
        }
    }
}

// ============================================================
// K3b: y = x + mask*(h1 @ W2 + b2)   (4096x256, K=512)
// ============================================================
__global__ void __launch_bounds__(256) k_mlp2(
    const float* __restrict__ x, const float* __restrict__ b2,
    const int* __restrict__ mask)
{
    const int bm = blockIdx.x * 128;
    const int bn = blockIdx.y * 64;

    GEMM_PROLOG

    for (int ch = 0; ch < HID/32; ch++) {
        load_chunkA_pk(As, g_h1b, HID/2, bm, ch*16, tid);
        load_chunkB_pk(Bs16, g_w2, OUTD, bn, ch*32, tid);
        __syncthreads();
        mma_chunk_bf(As, Bs16, acc, warpM, warpN, g, t4, lane);
        __syncthreads();
    }

#pragma unroll
    for (int mt = 0; mt < 4; mt++) {
#pragma unroll
        for (int nt = 0; nt < 2; nt++) {
            int R0 = bm + warpM*64 + mt*16 + g;
            int C  = bn + warpN*16 + nt*8 + 2*t4;
            float bx = b2[C], by = b2[C+1];
#pragma unroll
            for (int half = 0; half < 2; half++) {
                int R = R0 + half*8;
                float2 xv = *(const float2*)&x[(size_t)R*OUTD + C];
                float2 v;
                if (mask[R]) {
                    v.x = xv.x + acc[mt][nt][2*half+0] + bx;
                    v.y = xv.y + acc[mt][nt][2*half+1] + by;
                } else {
                    v = xv;
                }
                *(float2*)&g_y[(size_t)R*OUTD + C] = v;
            }
        }
    }
}

// ============================================================
// K4: LayerNorm. One warp per row.
// ============================================================
__global__ void __launch_bounds__(256) k_ln(
    const float* __restrict__ lng, const float* __restrict__ lnb,
    float* __restrict__ out)
{
    const int wid  = threadIdx.x >> 5;
    const int lane = threadIdx.x & 31;
    const int row  = blockIdx.x * 8 + wid;

    const float* yr = g_y + (size_t)row * OUTD;
    float yv[8];
    float ssum = 0.0f, ssq = 0.0f;
#pragma unroll
    for (int t = 0; t < 2; t++) {
        float4 v = *(const float4*)&yr[lane*4 + t*128];
        yv[t*4+0]=v.x; yv[t*4+1]=v.y; yv[t*4+2]=v.z; yv[t*4+3]=v.w;
        ssum += v.x+v.y+v.z+v.w;
        ssq  += v.x*v.x+v.y*v.y+v.z*v.z+v.w*v.w;
    }
#pragma unroll
    for (int off = 16; off > 0; off >>= 1) {
        ssum += __shfl_xor_sync(0xFFFFFFFF, ssum, off);
        ssq  += __shfl_xor_sync(0xFFFFFFFF, ssq,  off);
    }
    float mu  = ssum * (1.0f / OUTD);
    float var = ssq * (1.0f / OUTD) - mu * mu;
    float rs  = rsqrtf(var + 1e-5f);
#pragma unroll
    for (int t = 0; t < 2; t++) {
        int c = lane*4 + t*128;
        float4 gg = *(const float4*)&lng[c];
        float4 bb = *(const float4*)&lnb[c];
        float4 o;
        o.x = (yv[t*4+0]-mu)*rs*gg.x + bb.x;
        o.y = (yv[t*4+1]-mu)*rs*gg.y + bb.y;
        o.z = (yv[t*4+2]-mu)*rs*gg.z + bb.z;
        o.w = (yv[t*4+3]-mu)*rs*gg.w + bb.w;
        *(float4*)&out[(size_t)row*OUTD + c] = o;
    }
}

// ============================================================
extern "C" void kernel_launch(void* const* d_in, const int* in_sizes, int n_in,
                              void* d_out, int out_size)
{
    const float* x     = (const float*)d_in[0];
    const float* posCA = (const float*)d_in[1];
    const float* posCB = (const float*)d_in[2];
    const float* frame = (const float*)d_in[3];
    const int*   mask  = (const int*)  d_in[4];
    const float* Wq    = (const float*)d_in[5];
    const float* Wk    = (const float*)d_in[6];
    const float* Wv    = (const float*)d_in[7];
    const float* seW1  = (const float*)d_in[8];
    const float* seb1  = (const float*)d_in[9];
    const float* seW2  = (const float*)d_in[10];
    const float* seb2  = (const float*)d_in[11];
    const float* otW1  = (const float*)d_in[12];
    const float* otb1  = (const float*)d_in[13];
    const float* otW2  = (const float*)d_in[14];
    const float* otb2  = (const float*)d_in[15];
    const float* lng   = (const float*)d_in[16];
    const float* lnb   = (const float*)d_in[17];
    float* out = (float*)d_out;

    // Qs + Ps + Ks (uint32) + Vs16 (halves) + mkf (float)
    const int smem_attn = (2*256*20 + 32*20 + 32*36) * 4 + 512*4;   // 50176
    cudaFuncSetAttribute(k_attn, cudaFuncAttributeMaxDynamicSharedMemorySize, smem_attn);

    k_cvtw<<<dim3(160, 6), 256>>>(Wq, Wk, Wv, seW2, otW1, otW2);
    k_spat<<<NL/128, 128>>>(posCA, seW1, seb1);
    k_qkv<<<dim3(NL/128, 24), 256>>>(x, seb2);
    k_attn<<<dim3(HH, NB, 2), 256, smem_attn>>>(posCA, posCB, frame, mask);
    k_mlp1<<<dim3(NL/128, HID/64),  256>>>(otb1);
    k_mlp2<<<dim3(NL/128, OUTD/64), 256>>>(x, otb2, mask);
    k_ln<<<NL/8, 256>>>(lng, lnb, out);
}

// round 11
// speedup vs baseline: 5.2732x; 1.1623x over previous
#include <cuda_runtime.h>
#include <cuda_bf16.h>
#include <math.h>
#include <stdint.h>

// ---------------- problem constants ----------------
#define NB   8
#define LL   512
#define DD   256
#define HH   16
#define QK   32
#define VD   32
#define OUTD 256
#define NL   (NB*LL)          // 4096
#define QKH  (QK*HH)          // 512
#define FEAT 640              // 512 node + 128 spatial
#define HID  512              // OUT*2

// ---------------- bf16 / async helpers ----------------
__device__ __forceinline__ uint32_t bf2(float lo, float hi) {
    uint32_t d;
    asm("cvt.rn.bf16x2.f32 %0, %1, %2;" : "=r"(d) : "f"(hi), "f"(lo));
    return d;
}
__device__ __forceinline__ void mma_bf16(float c[4],
                                         uint32_t a0, uint32_t a1, uint32_t a2, uint32_t a3,
                                         uint32_t b0, uint32_t b1) {
    asm volatile("mma.sync.aligned.m16n8k16.row.col.f32.bf16.bf16.f32 "
                 "{%0,%1,%2,%3}, {%4,%5,%6,%7}, {%8,%9}, {%0,%1,%2,%3};"
                 : "+f"(c[0]), "+f"(c[1]), "+f"(c[2]), "+f"(c[3])
                 : "r"(a0), "r"(a1), "r"(a2), "r"(a3), "r"(b0), "r"(b1));
}
__device__ __forceinline__ uint2 ldsm2t(const void* p) {
    uint32_t a = (uint32_t)__cvta_generic_to_shared(p);
    uint2 r;
    asm volatile("ldmatrix.sync.aligned.m8n8.x2.trans.shared.b16 {%0,%1}, [%2];"
                 : "=r"(r.x), "=r"(r.y) : "r"(a));
    return r;
}
__device__ __forceinline__ void cpa16(void* s, const void* g) {
    uint32_t a = (uint32_t)__cvta_generic_to_shared(s);
    asm volatile("cp.async.ca.shared.global [%0], [%1], 16;" :: "r"(a), "l"(g));
}
#define CP_COMMIT asm volatile("cp.async.commit_group;" ::: "memory")
#define CP_WAIT0  asm volatile("cp.async.wait_group 0;" ::: "memory")
#define CP_WAIT1  asm volatile("cp.async.wait_group 1;" ::: "memory")

// FMA-only exp (no MUFU). |rel err| ~3e-6.
__device__ __forceinline__ float fexp(float x) {
    float y = x * 1.4426950408889634f;
    float r = y + 12582912.0f;
    int   n = __float_as_int(r) - 0x4B400000;
    float f = y - (r - 12582912.0f);
    float p = 1.3333558146e-3f;
    p = fmaf(p, f, 9.6181291076e-3f);
    p = fmaf(p, f, 5.5504108665e-2f);
    p = fmaf(p, f, 2.4022650696e-1f);
    p = fmaf(p, f, 6.9314718056e-1f);
    p = fmaf(p, f, 1.0f);
    return __int_as_float(__float_as_int(p) + (n << 23));
}

// ---------------- scratch (no allocs allowed) ----------------
__device__ uint32_t g_qb[(size_t)NL*QKH/2];     // bf16x2 packed activations
__device__ uint32_t g_kb[(size_t)NL*QKH/2];
__device__ uint32_t g_vb[(size_t)NL*QKH/2];
__device__ uint32_t g_h1b[(size_t)NL*HID/2];
__device__ uint32_t g_featb[(size_t)NL*FEAT/2];
__device__ uint32_t g_xb[(size_t)NL*DD/2];
__device__ uint32_t g_tb[(size_t)NL*QK/2];
__device__ float    g_y[(size_t)NL*OUTD];
// bf16 weights [k][n] (converted once per launch)
__device__ uint32_t g_wq[DD*QKH/2];
__device__ uint32_t g_wk[DD*QKH/2];
__device__ uint32_t g_wv[DD*QKH/2];
__device__ uint32_t g_wse[QK*QKH/2];
__device__ uint32_t g_w1[FEAT*HID/2];
__device__ uint32_t g_w2[HID*OUTD/2];

// ============================================================
// K-1: convert weights + x  fp32 -> packed bf16
// ============================================================
__global__ void k_cvtw(const float* __restrict__ Wq, const float* __restrict__ Wk,
                       const float* __restrict__ Wv, const float* __restrict__ seW2,
                       const float* __restrict__ W1, const float* __restrict__ W2,
                       const float* __restrict__ x)
{
    const int m = blockIdx.y;
    const float* src; uint32_t* dst; int ng;   // groups of 8 elements
    switch (m) {
        case 0: src = Wq;   dst = g_wq;  ng = DD*QKH/8;   break;
        case 1: src = Wk;   dst = g_wk;  ng = DD*QKH/8;   break;
        case 2: src = Wv;   dst = g_wv;  ng = DD*QKH/8;   break;
        case 3: src = seW2; dst = g_wse; ng = QK*QKH/8;   break;
        case 4: src = W1;   dst = g_w1;  ng = FEAT*HID/8; break;
        case 5: src = W2;   dst = g_w2;  ng = HID*OUTD/8; break;
        default:src = x;    dst = g_xb;  ng = NL*DD/8;    break;
    }
    int i = blockIdx.x * blockDim.x + threadIdx.x;
    if (i >= ng) return;
    float4 a = ((const float4*)src)[2*i];
    float4 b = ((const float4*)src)[2*i+1];
    uint4 w;
    w.x = bf2(a.x, a.y); w.y = bf2(a.z, a.w);
    w.z = bf2(b.x, b.y); w.w = bf2(b.z, b.w);
    ((uint4*)dst)[i] = w;
}

// ============================================================
// K0: t = relu(pos_CA @ se_W1 + se_b1) -> packed bf16 (4096x32)
// ============================================================
__global__ void k_spat(const float* __restrict__ posCA,
                       const float* __restrict__ seW1,
                       const float* __restrict__ seb1)
{
    int r = blockIdx.x * blockDim.x + threadIdx.x;
    if (r >= NL) return;
    float p0 = posCA[r*3+0], p1 = posCA[r*3+1], p2 = posCA[r*3+2];
#pragma unroll
    for (int j = 0; j < QK/2; j++) {
        int c0 = 2*j, c1 = 2*j+1;
        float v0 = seb1[c0] + p0*seW1[c0] + p1*seW1[QK + c0] + p2*seW1[2*QK + c0];
        float v1 = seb1[c1] + p0*seW1[c1] + p1*seW1[QK + c1] + p2*seW1[2*QK + c1];
        g_tb[(size_t)r*(QK/2) + j] = bf2(fmaxf(v0, 0.0f), fmaxf(v1, 0.0f));
    }
}

// ============================================================
// GEMM: BM=128, BN=64, BK=32, 8 warps (2M x 4N), m16n8k16.
// cp.async double-buffered. A: packed pairs [128][20]x2.
// B: bf16 [32][72]x2 natural [k][n]; ldmatrix.trans fragments.
// ============================================================
__device__ __forceinline__ void loadA_async(uint32_t (*As)[20], const uint32_t* A,
                                            int ldp, int bm, int kcp, int tid)
{
    int r = tid >> 1;
    int h = (tid & 1) * 8;
    const uint32_t* p = A + (size_t)(bm + r) * ldp + kcp + h;
    cpa16(&As[r][h],     p);
    cpa16(&As[r][h + 4], p + 4);
}
__device__ __forceinline__ void loadB_async(__nv_bfloat16 (*Bs16)[72], const uint32_t* W,
                                            int ldn2, int bn, int kc, int tid)
{
    int k  = tid >> 3;
    int n0 = (tid & 7) * 8;
    cpa16(&Bs16[k][n0], W + (size_t)(kc + k) * ldn2 + (bn + n0)/2);
}

__device__ __forceinline__ void mma_chunk_bf(const uint32_t (*As)[20],
                                             const __nv_bfloat16 (*Bs16)[72],
                                             float acc[4][2][4], int warpM, int warpN,
                                             int g, int t4, int lane)
{
    const int i16 = lane & 15;
#pragma unroll
    for (int s = 0; s < 2; s++) {
        const int k0 = s * 8;   // pair units
        uint2 b[2];
#pragma unroll
        for (int nt = 0; nt < 2; nt++)
            b[nt] = ldsm2t(&Bs16[s*16 + i16][warpN*16 + nt*8]);
#pragma unroll
        for (int mt = 0; mt < 4; mt++) {
            int mr = warpM * 64 + mt * 16;
            uint32_t a0 = As[mr + g][k0 + t4];
            uint32_t a1 = As[mr + g + 8][k0 + t4];
            uint32_t a2 = As[mr + g][k0 + t4 + 4];
            uint32_t a3 = As[mr + g + 8][k0 + t4 + 4];
#pragma unroll
            for (int nt = 0; nt < 2; nt++)
                mma_bf16(acc[mt][nt], a0, a1, a2, a3, b[nt].x, b[nt].y);
        }
    }
}

#define GEMM_PROLOG                                                  \
    __shared__ __align__(16) uint32_t AsB[2][128][20];               \
    __shared__ __align__(16) __nv_bfloat16 BsB[2][32][72];           \
    const int tid  = threadIdx.x;                                    \
    const int wid  = tid >> 5;                                       \
    const int lane = tid & 31;                                       \
    const int g    = lane >> 2, t4 = lane & 3;                       \
    const int warpM = wid >> 2, warpN = wid & 3;                     \
    float acc[4][2][4];                                              \
    _Pragma("unroll") for (int i = 0; i < 4; i++)                    \
    _Pragma("unroll") for (int j = 0; j < 2; j++)                    \
    _Pragma("unroll") for (int q = 0; q < 4; q++) acc[i][j][q] = 0.0f;

// ============================================================
// K1: fused QKV projection (4096 x 1536, K=256; q adds t@se_W2+b)
// ============================================================
__global__ void __launch_bounds__(256) k_qkv(const float* __restrict__ seb2)
{
    const int bm  = blockIdx.x * 128;
    const int mat = blockIdx.y >> 3;           // 0=q 1=k 2=v
    const int bn  = (blockIdx.y & 7) * 64;
    const uint32_t* W = (mat == 0) ? g_wq : (mat == 1) ? g_wk : g_wv;

    GEMM_PROLOG

    const int nchunks = (mat == 0) ? 9 : 8;
    // prefetch chunk 0
    loadA_async(AsB[0], g_xb, DD/2, bm, 0, tid);
    loadB_async(BsB[0], W, QKH/2, bn, 0, tid);
    CP_COMMIT;
    for (int ch = 0; ch < nchunks; ch++) {
        if (ch + 1 < nchunks) {
            int nb = (ch + 1) & 1;
            if (ch + 1 < 8) {
                loadA_async(AsB[nb], g_xb, DD/2, bm, (ch+1)*16, tid);
                loadB_async(BsB[nb], W, QKH/2, bn, (ch+1)*32, tid);
            } else {
                loadA_async(AsB[nb], g_tb, QK/2, bm, 0, tid);
                loadB_async(BsB[nb], g_wse, QKH/2, bn, 0, tid);
            }
            CP_COMMIT;
            CP_WAIT1;
        } else {
            CP_WAIT0;
        }
        __syncthreads();
        mma_chunk_bf(AsB[ch & 1], BsB[ch & 1], acc, warpM, warpN, g, t4, lane);
        __syncthreads();
    }

    uint32_t* dst = (mat == 0) ? g_qb : (mat == 1) ? g_kb : g_vb;
#pragma unroll
    for (int mt = 0; mt < 4; mt++) {
#pragma unroll
        for (int nt = 0; nt < 2; nt++) {
            int R0 = bm + warpM*64 + mt*16 + g;
            int C  = bn + warpN*16 + nt*8 + 2*t4;
            float bx = 0.f, by = 0.f;
            if (mat == 0) { bx = seb2[C]; by = seb2[C+1]; }
            dst[(size_t)R0*(QKH/2)     + C/2] = bf2(acc[mt][nt][0] + bx, acc[mt][nt][1] + by);
            dst[(size_t)(R0+8)*(QKH/2) + C/2] = bf2(acc[mt][nt][2] + bx, acc[mt][nt][3] + by);
        }
    }
}

// ============================================================
// K2: bf16 tensor-core attention, q-split, cp.async K/V pipeline.
// Grid (HH, NB, 2): block = 256 q-rows of one (b,h), 8 warps.
// ============================================================
__global__ void __launch_bounds__(256, 2) k_attn(
    const float* __restrict__ posCA,
    const float* __restrict__ posCB,
    const float* __restrict__ frame,
    const int*   __restrict__ mask)
{
    extern __shared__ __align__(16) uint32_t smu[];
    uint32_t (*Qs)[20] = (uint32_t (*)[20])smu;                      // [256][20]
    uint32_t (*Ps)[20] = (uint32_t (*)[20])(smu + 256*20);           // [256][20]
    uint32_t (*KsB)[32][20] = (uint32_t (*)[32][20])(smu + 2*256*20);        // [2][32][20]
    __nv_bfloat16 (*VsB)[32][72] = (__nv_bfloat16 (*)[32][72])(smu + 2*256*20 + 2*32*20); // [2][32][72]
    float* mkf = (float*)(smu + 2*256*20 + 2*32*20 + 2*32*36);       // [512]

    const int h  = blockIdx.x;
    const int b  = blockIdx.y;
    const int qh = blockIdx.z;
    const int tid = threadIdx.x;
    const int w = tid >> 5, lane = tid & 31;
    const int g = lane >> 2, t4 = lane & 3;
    const int i16 = lane & 15;
    const int qbase = qh * 256;

    // ---- Q via cp.async (group 0, together with chunk 0 K/V) ----
#pragma unroll
    for (int it = 0; it < 4; it++) {
        int idx = tid + 256*it;
        int r = idx >> 2, c4 = idx & 3;
        cpa16(&Qs[r][c4*4], g_qb + ((size_t)b*LL + qbase + r)*(QKH/2) + h*(QK/2) + c4*4);
    }
    // ---- prefetch K/V chunk 0 ----
    {
        if (tid < 128) {
            int j = tid >> 2, c4 = tid & 3;
            cpa16(&VsB[0][j][c4*8], g_vb + ((size_t)b*LL + j)*(QKH/2) + h*(QK/2) + c4*4);
        } else {
            int t = tid - 128;
            int j = t >> 2, c4 = t & 3;
            cpa16(&KsB[0][j][c4*4], g_kb + ((size_t)b*LL + j)*(QKH/2) + h*(QK/2) + c4*4);
        }
    }
    CP_COMMIT;
    if (tid < 32) {   // augment chunk 0
        int j = tid;
        const float* pp = posCB + ((size_t)b*LL + j)*3;
        VsB[0][j][32] = __float2bfloat16(pp[0]);
        VsB[0][j][33] = __float2bfloat16(pp[1]);
        VsB[0][j][34] = __float2bfloat16(pp[2]);
        VsB[0][j][35] = __float2bfloat16(1.0f);
        VsB[0][j][36] = __float2bfloat16(0.0f);
        VsB[0][j][37] = __float2bfloat16(0.0f);
        VsB[0][j][38] = __float2bfloat16(0.0f);
        VsB[0][j][39] = __float2bfloat16(0.0f);
    }
    mkf[tid]       = mask[b*LL + tid]       ? 1.0f : 0.0f;
    mkf[tid + 256] = mask[b*LL + tid + 256] ? 1.0f : 0.0f;

    float acc[2][5][4];
#pragma unroll
    for (int i = 0; i < 2; i++)
#pragma unroll
        for (int j = 0; j < 5; j++)
#pragma unroll
            for (int q = 0; q < 4; q++) acc[i][j][q] = 0.0f;

    for (int ch = 0; ch < 16; ch++) {
        const int cb = ch & 1;
        if (ch + 1 < 16) {
            const int nb = cb ^ 1;
            const int j1 = (ch + 1) * 32;
            if (tid < 128) {
                int j = tid >> 2, c4 = tid & 3;
                cpa16(&VsB[nb][j][c4*8], g_vb + ((size_t)b*LL + j1 + j)*(QKH/2) + h*(QK/2) + c4*4);
            } else {
                int t = tid - 128;
                int j = t >> 2, c4 = t & 3;
                cpa16(&KsB[nb][j][c4*4], g_kb + ((size_t)b*LL + j1 + j)*(QKH/2) + h*(QK/2) + c4*4);
            }
            CP_COMMIT;
            if (tid < 32) {
                int j = tid;
                const float* pp = posCB + ((size_t)b*LL + j1 + j)*3;
                VsB[nb][j][32] = __float2bfloat16(pp[0]);
                VsB[nb][j][33] = __float2bfloat16(pp[1]);
                VsB[nb][j][34] = __float2bfloat16(pp[2]);
                VsB[nb][j][35] = __float2bfloat16(1.0f);
                VsB[nb][j][36] = __float2bfloat16(0.0f);
                VsB[nb][j][37] = __float2bfloat16(0.0f);
                VsB[nb][j][38] = __float2bfloat16(0.0f);
                VsB[nb][j][39] = __float2bfloat16(0.0f);
            }
            CP_WAIT1;
        } else {
            CP_WAIT0;
        }
        __syncthreads();

        const int j0 = ch * 32;
        // ---- S phase ----
        uint32_t kb[4][2][2];
#pragma unroll
        for (int nt = 0; nt < 4; nt++)
#pragma unroll
            for (int s = 0; s < 2; s++) {
                kb[nt][s][0] = KsB[cb][8*nt + g][s*8 + t4];
                kb[nt][s][1] = KsB[cb][8*nt + g][s*8 + t4 + 4];
            }
#pragma unroll
        for (int mt = 0; mt < 2; mt++) {
            const int rb = w*32 + mt*16;
            float S[4][4];
#pragma unroll
            for (int nt = 0; nt < 4; nt++)
#pragma unroll
                for (int q = 0; q < 4; q++) S[nt][q] = 0.0f;
#pragma unroll
            for (int s = 0; s < 2; s++) {
                const int k0 = s*8;
                uint32_t a0 = Qs[rb+g][k0+t4];
                uint32_t a1 = Qs[rb+g+8][k0+t4];
                uint32_t a2 = Qs[rb+g][k0+t4+4];
                uint32_t a3 = Qs[rb+g+8][k0+t4+4];
#pragma unroll
                for (int nt = 0; nt < 4; nt++)
                    mma_bf16(S[nt], a0, a1, a2, a3, kb[nt][s][0], kb[nt][s][1]);
            }
#pragma unroll
            for (int nt = 0; nt < 4; nt++) {
                const int col = 8*nt + 2*t4;
                float m0 = mkf[j0 + col], m1 = mkf[j0 + col + 1];
                Ps[rb+g][nt*4 + t4]   = bf2(m0 * fexp(S[nt][0]), m1 * fexp(S[nt][1]));
                Ps[rb+g+8][nt*4 + t4] = bf2(m0 * fexp(S[nt][2]), m1 * fexp(S[nt][3]));
            }
        }
        __syncwarp();

        // ---- O phase ----
#pragma unroll
        for (int s = 0; s < 2; s++) {
            uint2 vb[5];
#pragma unroll
            for (int nt = 0; nt < 5; nt++)
                vb[nt] = ldsm2t(&VsB[cb][s*16 + i16][nt*8]);
            const int k0 = s*8;
#pragma unroll
            for (int mt = 0; mt < 2; mt++) {
                const int rb = w*32 + mt*16;
                uint32_t a0 = Ps[rb+g][k0+t4];
                uint32_t a1 = Ps[rb+g+8][k0+t4];
                uint32_t a2 = Ps[rb+g][k0+t4+4];
                uint32_t a3 = Ps[rb+g+8][k0+t4+4];
#pragma unroll
                for (int nt = 0; nt < 5; nt++)
                    mma_bf16(acc[mt][nt], a0, a1, a2, a3, vb[nt].x, vb[nt].y);
            }
        }
        __syncthreads();
    }

    // ---- epilogue (fp32 math, bf16 feature stores) ----
#pragma unroll
    for (int mt = 0; mt < 2; mt++) {
#pragma unroll
        for (int half = 0; half < 2; half++) {
            const int rloc = w*32 + mt*16 + g + half*8;
            const size_t grow = (size_t)b*LL + qbase + rloc;
            float c_lo = half ? acc[mt][4][2] : acc[mt][4][0];
            float c_hi = half ? acc[mt][4][3] : acc[mt][4][1];
            const int qb = lane & ~3;
            float ap0 = __shfl_sync(0xffffffffu, c_lo, qb + 0);
            float ap1 = __shfl_sync(0xffffffffu, c_hi, qb + 0);
            float ap2 = __shfl_sync(0xffffffffu, c_lo, qb + 1);
            float s   = __shfl_sync(0xffffffffu, c_hi, qb + 1);
            const bool ok = (mkf[qbase + rloc] != 0.0f) && (s > 0.0f);
            const float inv = ok ? 1.0f / s : 0.0f;
            uint32_t* fr = g_featb + grow * (FEAT/2);
            __nv_bfloat16* fr16 = (__nv_bfloat16*)fr;
#pragma unroll
            for (int nt = 0; nt < 4; nt++) {
                float v0 = half ? acc[mt][nt][2] : acc[mt][nt][0];
                float v1 = half ? acc[mt][nt][3] : acc[mt][nt][1];
                fr[h*16 + nt*4 + t4] = bf2(v0*inv, v1*inv);
            }
            if (t4 == 0) {
                if (!ok) {
                    fr16[512+h*3+0] = __float2bfloat16(0.0f);
                    fr16[512+h*3+1] = __float2bfloat16(0.0f);
                    fr16[512+h*3+2] = __float2bfloat16(0.0f);
                    fr16[560+h]     = __float2bfloat16(0.0f);
                    fr16[576+h*3+0] = __float2bfloat16(0.0f);
                    fr16[576+h*3+1] = __float2bfloat16(0.0f);
                    fr16[576+h*3+2] = __float2bfloat16(0.0f);
                    fr16[624+h]     = __float2bfloat16(0.0f);
                } else {
                    float a0 = ap0*inv - posCA[grow*3+0];
                    float a1 = ap1*inv - posCA[grow*3+1];
                    float a2 = ap2*inv - posCA[grow*3+2];
                    const float* F = frame + grow * 9;
                    float pt0 = F[0]*a0 + F[1]*a1 + F[2]*a2;
                    float pt1 = F[3]*a0 + F[4]*a1 + F[5]*a2;
                    float pt2 = F[6]*a0 + F[7]*a1 + F[8]*a2;
                    float dist = sqrtf(a0*a0 + a1*a1 + a2*a2);
                    float pn   = sqrtf(pt0*pt0 + pt1*pt1 + pt2*pt2);
                    float id   = 1.0f / (pn + 1e-10f);
                    float ang  = atan2f(pt1, pt0);
                    fr16[512+h*3+0] = __float2bfloat16(pt0);
                    fr16[512+h*3+1] = __float2bfloat16(pt1);
                    fr16[512+h*3+2] = __float2bfloat16(pt2);
                    fr16[560+h]     = __float2bfloat16(dist);
                    fr16[576+h*3+0] = __float2bfloat16(pt0*id);
                    fr16[576+h*3+1] = __float2bfloat16(pt1*id);
                    fr16[576+h*3+2] = __float2bfloat16(pt2*id);
                    fr16[624+h]     = __float2bfloat16(ang);
                }
            }
        }
    }
}

// ============================================================
// K3a: h1 = relu(feat @ W1 + b1) -> packed bf16 (4096x512,K=640)
// ============================================================
__global__ void __launch_bounds__(256) k_mlp1(const float* __restrict__ b1)
{
    const int bm = blockIdx.x * 128;
    const int bn = blockIdx.y * 64;

    GEMM_PROLOG

    const int NCH = FEAT/32;   // 20
    loadA_async(AsB[0], g_featb, FEAT/2, bm, 0, tid);
    loadB_async(BsB[0], g_w1, HID/2, bn, 0, tid);
    CP_COMMIT;
    for (int ch = 0; ch < NCH; ch++) {
        if (ch + 1 < NCH) {
            int nb = (ch + 1) & 1;
            loadA_async(AsB[nb], g_featb, FEAT/2, bm, (ch+1)*16, tid);
            loadB_async(BsB[nb], g_w1, HID/2, bn, (ch+1)*32, tid);
            CP_COMMIT;
            CP_WAIT1;
        } else {
            CP_WAIT0;
        }
        __syncthreads();
        mma_chunk_bf(AsB[ch & 1], BsB[ch & 1], acc, warpM, warpN, g, t4, lane);
        __syncthreads();
    }

#pragma unroll
    for (int mt = 0; mt < 4; mt++) {
#pragma unroll
        for (int nt = 0; nt < 2; nt++) {
            int R0 = bm + warpM*64 + mt*16 + g;
            int C  = bn + warpN*16 + nt*8 + 2*t4;
            float bx = b1[C], by = b1[C+1];
            g_h1b[(size_t)R0*(HID/2)     + C/2] =
                bf2(fmaxf(acc[mt][nt][0] + bx, 0.f), fmaxf(acc[mt][nt][1] + by, 0.f));
            g_h1b[(size_t)(R0+8)*(HID/2) + C/2] =
                bf2(fmaxf(acc[mt][nt][2] + bx, 0.f), fmaxf(acc[mt][nt][3] + by, 0.f));
        }
    }
}

// ============================================================
// K3b: y = x + mask*(h1 @ W2 + b2)   (4096x256, K=512)
// ============================================================
__global__ void __launch_bounds__(256) k_mlp2(
    const float* __restrict__ x, const float* __restrict__ b2,
    const int* __restrict__ mask)
{
    const int bm = blockIdx.x * 128;
    const int bn = blockIdx.y * 64;

    GEMM_PROLOG

    const int NCH = HID/32;   // 16
    loadA_async(AsB[0], g_h1b, HID/2, bm, 0, tid);
    loadB_async(BsB[0], g_w2, OUTD/2, bn, 0, tid);
    CP_COMMIT;
    for (int ch = 0; ch < NCH; ch++) {
        if (ch + 1 < NCH) {
            int nb = (ch + 1) & 1;
            loadA_async(AsB[nb], g_h1b, HID/2, bm, (ch+1)*16, tid);
            loadB_async(BsB[nb], g_w2, OUTD/2, bn, (ch+1)*32, tid);
            CP_COMMIT;
            CP_WAIT1;
        } else {
            CP_WAIT0;
        }
        __syncthreads();
        mma_chunk_bf(AsB[ch & 1], BsB[ch & 1], acc, warpM, warpN, g, t4, lane);
        __syncthreads();
    }

#pragma unroll
    for (int mt = 0; mt < 4; mt++) {
#pragma unroll
        for (int nt = 0; nt < 2; nt++) {
            int R0 = bm + warpM*64 + mt*16 + g;
            int C  = bn + warpN*16 + nt*8 + 2*t4;
            float bx = b2[C], by = b2[C+1];
#pragma unroll
            for (int half = 0; half < 2; half++) {
                int R = R0 + half*8;
                float2 xv = *(const float2*)&x[(size_t)R*OUTD + C];
                float2 v;
                if (mask[R]) {
                    v.x = xv.x + acc[mt][nt][2*half+0] + bx;
                    v.y = xv.y + acc[mt][nt][2*half+1] + by;
                } else {
                    v = xv;
                }
                *(float2*)&g_y[(size_t)R*OUTD + C] = v;
            }
        }
    }
}

// ============================================================
// K4: LayerNorm. One warp per row.
// ============================================================
__global__ void __launch_bounds__(256) k_ln(
    const float* __restrict__ lng, const float* __restrict__ lnb,
    float* __restrict__ out)
{
    const int wid  = threadIdx.x >> 5;
    const int lane = threadIdx.x & 31;
    const int row  = blockIdx.x * 8 + wid;

    const float* yr = g_y + (size_t)row * OUTD;
    float yv[8];
    float ssum = 0.0f, ssq = 0.0f;
#pragma unroll
    for (int t = 0; t < 2; t++) {
        float4 v = *(const float4*)&yr[lane*4 + t*128];
        yv[t*4+0]=v.x; yv[t*4+1]=v.y; yv[t*4+2]=v.z; yv[t*4+3]=v.w;
        ssum += v.x+v.y+v.z+v.w;
        ssq  += v.x*v.x+v.y*v.y+v.z*v.z+v.w*v.w;
    }
#pragma unroll
    for (int off = 16; off > 0; off >>= 1) {
        ssum += __shfl_xor_sync(0xFFFFFFFF, ssum, off);
        ssq  += __shfl_xor_sync(0xFFFFFFFF, ssq,  off);
    }
    float mu  = ssum * (1.0f / OUTD);
    float var = ssq * (1.0f / OUTD) - mu * mu;
    float rs  = rsqrtf(var + 1e-5f);
#pragma unroll
    for (int t = 0; t < 2; t++) {
        int c = lane*4 + t*128;
        float4 gg = *(const float4*)&lng[c];
        float4 bb = *(const float4*)&lnb[c];
        float4 o;
        o.x = (yv[t*4+0]-mu)*rs*gg.x + bb.x;
        o.y = (yv[t*4+1]-mu)*rs*gg.y + bb.y;
        o.z = (yv[t*4+2]-mu)*rs*gg.z + bb.z;
        o.w = (yv[t*4+3]-mu)*rs*gg.w + bb.w;
        *(float4*)&out[(size_t)row*OUTD + c] = o;
    }
}

// ============================================================
extern "C" void kernel_launch(void* const* d_in, const int* in_sizes, int n_in,
                              void* d_out, int out_size)
{
    const float* x     = (const float*)d_in[0];
    const float* posCA = (const float*)d_in[1];
    const float* posCB = (const float*)d_in[2];
    const float* frame = (const float*)d_in[3];
    const int*   mask  = (const int*)  d_in[4];
    const float* Wq    = (const float*)d_in[5];
    const float* Wk    = (const float*)d_in[6];
    const float* Wv    = (const float*)d_in[7];
    const float* seW1  = (const float*)d_in[8];
    const float* seb1  = (const float*)d_in[9];
    const float* seW2  = (const float*)d_in[10];
    const float* seb2  = (const float*)d_in[11];
    const float* otW1  = (const float*)d_in[12];
    const float* otb1  = (const float*)d_in[13];
    const float* otW2  = (const float*)d_in[14];
    const float* otb2  = (const float*)d_in[15];
    const float* lng   = (const float*)d_in[16];
    const float* lnb   = (const float*)d_in[17];
    float* out = (float*)d_out;

    // Qs + Ps + 2xKs + 2xVs + mkf
    const int smem_attn = (2*256*20 + 2*32*20 + 2*32*36) * 4 + 512*4;  // 57344
    cudaFuncSetAttribute(k_attn, cudaFuncAttributeMaxDynamicSharedMemorySize, smem_attn);

    k_cvtw<<<dim3(512, 7), 256>>>(Wq, Wk, Wv, seW2, otW1, otW2, x);
    k_spat<<<NL/128, 128>>>(posCA, seW1, seb1);
    k_qkv<<<dim3(NL/128, 24), 256>>>(seb2);
    k_attn<<<dim3(HH, NB, 2), 256, smem_attn>>>(posCA, posCB, frame, mask);
    k_mlp1<<<dim3(NL/128, HID/64),  256>>>(otb1);
    k_mlp2<<<dim3(NL/128, OUTD/64), 256>>>(x, otb2, mask);
    k_ln<<<NL/8, 256>>>(lng, lnb, out);
}

// round 12
// speedup vs baseline: 5.4751x; 1.0383x over previous
#include <cuda_runtime.h>
#include <cuda_bf16.h>
#include <math.h>
#include <stdint.h>

// ---------------- problem constants ----------------
#define NB   8
#define LL   512
#define DD   256
#define HH   16
#define QK   32
#define VD   32
#define OUTD 256
#define NL   (NB*LL)          // 4096
#define QKH  (QK*HH)          // 512
#define FEAT 640              // 512 node + 128 spatial
#define HID  512              // OUT*2

// ---------------- bf16 / async helpers ----------------
__device__ __forceinline__ uint32_t bf2(float lo, float hi) {
    uint32_t d;
    asm("cvt.rn.bf16x2.f32 %0, %1, %2;" : "=r"(d) : "f"(hi), "f"(lo));
    return d;
}
__device__ __forceinline__ void mma_bf16(float c[4],
                                         uint32_t a0, uint32_t a1, uint32_t a2, uint32_t a3,
                                         uint32_t b0, uint32_t b1) {
    asm volatile("mma.sync.aligned.m16n8k16.row.col.f32.bf16.bf16.f32 "
                 "{%0,%1,%2,%3}, {%4,%5,%6,%7}, {%8,%9}, {%0,%1,%2,%3};"
                 : "+f"(c[0]), "+f"(c[1]), "+f"(c[2]), "+f"(c[3])
                 : "r"(a0), "r"(a1), "r"(a2), "r"(a3), "r"(b0), "r"(b1));
}
__device__ __forceinline__ uint2 ldsm2t(const void* p) {
    uint32_t a = (uint32_t)__cvta_generic_to_shared(p);
    uint2 r;
    asm volatile("ldmatrix.sync.aligned.m8n8.x2.trans.shared.b16 {%0,%1}, [%2];"
                 : "=r"(r.x), "=r"(r.y) : "r"(a));
    return r;
}
__device__ __forceinline__ void cpa16(void* s, const void* g) {
    uint32_t a = (uint32_t)__cvta_generic_to_shared(s);
    asm volatile("cp.async.ca.shared.global [%0], [%1], 16;" :: "r"(a), "l"(g));
}
#define CP_COMMIT asm volatile("cp.async.commit_group;" ::: "memory")
#define CP_WAIT0  asm volatile("cp.async.wait_group 0;" ::: "memory")
#define CP_WAIT1  asm volatile("cp.async.wait_group 1;" ::: "memory")

// FMA-only exp (no MUFU). |rel err| ~3e-6.
__device__ __forceinline__ float fexp(float x) {
    float y = x * 1.4426950408889634f;
    float r = y + 12582912.0f;
    int   n = __float_as_int(r) - 0x4B400000;
    float f = y - (r - 12582912.0f);
    float p = 1.3333558146e-3f;
    p = fmaf(p, f, 9.6181291076e-3f);
    p = fmaf(p, f, 5.5504108665e-2f);
    p = fmaf(p, f, 2.4022650696e-1f);
    p = fmaf(p, f, 6.9314718056e-1f);
    p = fmaf(p, f, 1.0f);
    return __int_as_float(__float_as_int(p) + (n << 23));
}

// ---------------- scratch (no allocs allowed) ----------------
__device__ uint32_t g_qb[(size_t)NL*QKH/2];     // bf16x2 packed activations
__device__ uint32_t g_kb[(size_t)NL*QKH/2];
__device__ uint32_t g_vb[(size_t)NL*QKH/2];
__device__ uint32_t g_h1b[(size_t)NL*HID/2];
__device__ uint32_t g_featb[(size_t)NL*FEAT/2];
__device__ uint32_t g_xb[(size_t)NL*DD/2];
__device__ uint32_t g_tb[(size_t)NL*QK/2];
__device__ float    g_y[(size_t)NL*OUTD];
// bf16 weights [k][n] (converted once per launch)
__device__ uint32_t g_wq[DD*QKH/2];
__device__ uint32_t g_wk[DD*QKH/2];
__device__ uint32_t g_wv[DD*QKH/2];
__device__ uint32_t g_wse[QK*QKH/2];
__device__ uint32_t g_w1[FEAT*HID/2];
__device__ uint32_t g_w2[HID*OUTD/2];

// ============================================================
// K-1: convert weights + x  fp32 -> packed bf16
// ============================================================
__global__ void k_cvtw(const float* __restrict__ Wq, const float* __restrict__ Wk,
                       const float* __restrict__ Wv, const float* __restrict__ seW2,
                       const float* __restrict__ W1, const float* __restrict__ W2,
                       const float* __restrict__ x)
{
    const int m = blockIdx.y;
    const float* src; uint32_t* dst; int ng;   // groups of 8 elements
    switch (m) {
        case 0: src = Wq;   dst = g_wq;  ng = DD*QKH/8;   break;
        case 1: src = Wk;   dst = g_wk;  ng = DD*QKH/8;   break;
        case 2: src = Wv;   dst = g_wv;  ng = DD*QKH/8;   break;
        case 3: src = seW2; dst = g_wse; ng = QK*QKH/8;   break;
        case 4: src = W1;   dst = g_w1;  ng = FEAT*HID/8; break;
        case 5: src = W2;   dst = g_w2;  ng = HID*OUTD/8; break;
        default:src = x;    dst = g_xb;  ng = NL*DD/8;    break;
    }
    int i = blockIdx.x * blockDim.x + threadIdx.x;
    if (i >= ng) return;
    float4 a = ((const float4*)src)[2*i];
    float4 b = ((const float4*)src)[2*i+1];
    uint4 w;
    w.x = bf2(a.x, a.y); w.y = bf2(a.z, a.w);
    w.z = bf2(b.x, b.y); w.w = bf2(b.z, b.w);
    ((uint4*)dst)[i] = w;
}

// ============================================================
// K0: t = relu(pos_CA @ se_W1 + se_b1) -> packed bf16 (4096x32)
// ============================================================
__global__ void k_spat(const float* __restrict__ posCA,
                       const float* __restrict__ seW1,
                       const float* __restrict__ seb1)
{
    int r = blockIdx.x * blockDim.x + threadIdx.x;
    if (r >= NL) return;
    float p0 = posCA[r*3+0], p1 = posCA[r*3+1], p2 = posCA[r*3+2];
#pragma unroll
    for (int j = 0; j < QK/2; j++) {
        int c0 = 2*j, c1 = 2*j+1;
        float v0 = seb1[c0] + p0*seW1[c0] + p1*seW1[QK + c0] + p2*seW1[2*QK + c0];
        float v1 = seb1[c1] + p0*seW1[c1] + p1*seW1[QK + c1] + p2*seW1[2*QK + c1];
        g_tb[(size_t)r*(QK/2) + j] = bf2(fmaxf(v0, 0.0f), fmaxf(v1, 0.0f));
    }
}

// ============================================================
// GEMM: BM=128, BN=64, BK=32, 8 warps (2M x 4N), m16n8k16.
// cp.async double-buffered.
// ============================================================
__device__ __forceinline__ void loadA_async(uint32_t (*As)[20], const uint32_t* A,
                                            int ldp, int bm, int kcp, int tid)
{
    int r = tid >> 1;
    int h = (tid & 1) * 8;
    const uint32_t* p = A + (size_t)(bm + r) * ldp + kcp + h;
    cpa16(&As[r][h],     p);
    cpa16(&As[r][h + 4], p + 4);
}
__device__ __forceinline__ void loadB_async(__nv_bfloat16 (*Bs16)[72], const uint32_t* W,
                                            int ldn2, int bn, int kc, int tid)
{
    int k  = tid >> 3;
    int n0 = (tid & 7) * 8;
    cpa16(&Bs16[k][n0], W + (size_t)(kc + k) * ldn2 + (bn + n0)/2);
}

__device__ __forceinline__ void mma_chunk_bf(const uint32_t (*As)[20],
                                             const __nv_bfloat16 (*Bs16)[72],
                                             float acc[4][2][4], int warpM, int warpN,
                                             int g, int t4, int lane)
{
    const int i16 = lane & 15;
#pragma unroll
    for (int s = 0; s < 2; s++) {
        const int k0 = s * 8;   // pair units
        uint2 b[2];
#pragma unroll
        for (int nt = 0; nt < 2; nt++)
            b[nt] = ldsm2t(&Bs16[s*16 + i16][warpN*16 + nt*8]);
#pragma unroll
        for (int mt = 0; mt < 4; mt++) {
            int mr = warpM * 64 + mt * 16;
            uint32_t a0 = As[mr + g][k0 + t4];
            uint32_t a1 = As[mr + g + 8][k0 + t4];
            uint32_t a2 = As[mr + g][k0 + t4 + 4];
            uint32_t a3 = As[mr + g + 8][k0 + t4 + 4];
#pragma unroll
            for (int nt = 0; nt < 2; nt++)
                mma_bf16(acc[mt][nt], a0, a1, a2, a3, b[nt].x, b[nt].y);
        }
    }
}

#define GEMM_PROLOG                                                  \
    __shared__ __align__(16) uint32_t AsB[2][128][20];               \
    __shared__ __align__(16) __nv_bfloat16 BsB[2][32][72];           \
    const int tid  = threadIdx.x;                                    \
    const int wid  = tid >> 5;                                       \
    const int lane = tid & 31;                                       \
    const int g    = lane >> 2, t4 = lane & 3;                       \
    const int warpM = wid >> 2, warpN = wid & 3;                     \
    float acc[4][2][4];                                              \
    _Pragma("unroll") for (int i = 0; i < 4; i++)                    \
    _Pragma("unroll") for (int j = 0; j < 2; j++)                    \
    _Pragma("unroll") for (int q = 0; q < 4; q++) acc[i][j][q] = 0.0f;

// ============================================================
// K1: fused QKV projection (4096 x 1536, K=256; q adds t@se_W2+b)
// ============================================================
__global__ void __launch_bounds__(256) k_qkv(const float* __restrict__ seb2)
{
    const int bm  = blockIdx.x * 128;
    const int mat = blockIdx.y >> 3;           // 0=q 1=k 2=v
    const int bn  = (blockIdx.y & 7) * 64;
    const uint32_t* W = (mat == 0) ? g_wq : (mat == 1) ? g_wk : g_wv;

    GEMM_PROLOG

    const int nchunks = (mat == 0) ? 9 : 8;
    loadA_async(AsB[0], g_xb, DD/2, bm, 0, tid);
    loadB_async(BsB[0], W, QKH/2, bn, 0, tid);
    CP_COMMIT;
    for (int ch = 0; ch < nchunks; ch++) {
        if (ch + 1 < nchunks) {
            int nb = (ch + 1) & 1;
            if (ch + 1 < 8) {
                loadA_async(AsB[nb], g_xb, DD/2, bm, (ch+1)*16, tid);
                loadB_async(BsB[nb], W, QKH/2, bn, (ch+1)*32, tid);
            } else {
                loadA_async(AsB[nb], g_tb, QK/2, bm, 0, tid);
                loadB_async(BsB[nb], g_wse, QKH/2, bn, 0, tid);
            }
            CP_COMMIT;
            CP_WAIT1;
        } else {
            CP_WAIT0;
        }
        __syncthreads();
        mma_chunk_bf(AsB[ch & 1], BsB[ch & 1], acc, warpM, warpN, g, t4, lane);
        __syncthreads();
    }

    uint32_t* dst = (mat == 0) ? g_qb : (mat == 1) ? g_kb : g_vb;
#pragma unroll
    for (int mt = 0; mt < 4; mt++) {
#pragma unroll
        for (int nt = 0; nt < 2; nt++) {
            int R0 = bm + warpM*64 + mt*16 + g;
            int C  = bn + warpN*16 + nt*8 + 2*t4;
            float bx = 0.f, by = 0.f;
            if (mat == 0) { bx = seb2[C]; by = seb2[C+1]; }
            dst[(size_t)R0*(QKH/2)     + C/2] = bf2(acc[mt][nt][0] + bx, acc[mt][nt][1] + by);
            dst[(size_t)(R0+8)*(QKH/2) + C/2] = bf2(acc[mt][nt][2] + bx, acc[mt][nt][3] + by);
        }
    }
}

// ============================================================
// K2: bf16 TC attention, q-split, cp.async pipeline,
// register-resident P (S C-fragment == O A-fragment layout),
// Q fragments hoisted into registers.
// Grid (HH, NB, 2): block = 256 q-rows of one (b,h), 8 warps.
// Smem: Qs[256][20] KsB[2][32][20] VsB[2][32][72]h mkf[512] = 36.9KB
// ============================================================
__global__ void __launch_bounds__(256, 2) k_attn(
    const float* __restrict__ posCA,
    const float* __restrict__ posCB,
    const float* __restrict__ frame,
    const int*   __restrict__ mask)
{
    extern __shared__ __align__(16) uint32_t smu[];
    uint32_t (*Qs)[20] = (uint32_t (*)[20])smu;                              // [256][20]
    uint32_t (*KsB)[32][20] = (uint32_t (*)[32][20])(smu + 256*20);          // [2][32][20]
    __nv_bfloat16 (*VsB)[32][72] = (__nv_bfloat16 (*)[32][72])(smu + 256*20 + 2*32*20); // [2][32][72]
    float* mkf = (float*)(smu + 256*20 + 2*32*20 + 2*32*36);                 // [512]

    const int h  = blockIdx.x;
    const int b  = blockIdx.y;
    const int qh = blockIdx.z;
    const int tid = threadIdx.x;
    const int w = tid >> 5, lane = tid & 31;
    const int g = lane >> 2, t4 = lane & 3;
    const int i16 = lane & 15;
    const int qbase = qh * 256;

    // ---- group 0: Q + K/V chunk 0 ----
#pragma unroll
    for (int it = 0; it < 4; it++) {
        int idx = tid + 256*it;
        int r = idx >> 2, c4 = idx & 3;
        cpa16(&Qs[r][c4*4], g_qb + ((size_t)b*LL + qbase + r)*(QKH/2) + h*(QK/2) + c4*4);
    }
    if (tid < 128) {
        int j = tid >> 2, c4 = tid & 3;
        cpa16(&VsB[0][j][c4*8], g_vb + ((size_t)b*LL + j)*(QKH/2) + h*(QK/2) + c4*4);
    } else {
        int t = tid - 128;
        int j = t >> 2, c4 = t & 3;
        cpa16(&KsB[0][j][c4*4], g_kb + ((size_t)b*LL + j)*(QKH/2) + h*(QK/2) + c4*4);
    }
    CP_COMMIT;
    if (tid < 32) {
        int j = tid;
        const float* pp = posCB + ((size_t)b*LL + j)*3;
        VsB[0][j][32] = __float2bfloat16(pp[0]);
        VsB[0][j][33] = __float2bfloat16(pp[1]);
        VsB[0][j][34] = __float2bfloat16(pp[2]);
        VsB[0][j][35] = __float2bfloat16(1.0f);
        VsB[0][j][36] = __float2bfloat16(0.0f);
        VsB[0][j][37] = __float2bfloat16(0.0f);
        VsB[0][j][38] = __float2bfloat16(0.0f);
        VsB[0][j][39] = __float2bfloat16(0.0f);
    }
    mkf[tid]       = mask[b*LL + tid]       ? 1.0f : 0.0f;
    mkf[tid + 256] = mask[b*LL + tid + 256] ? 1.0f : 0.0f;

    // ---- group 1: K/V chunk 1 ----
    if (tid < 128) {
        int j = tid >> 2, c4 = tid & 3;
        cpa16(&VsB[1][j][c4*8], g_vb + ((size_t)b*LL + 32 + j)*(QKH/2) + h*(QK/2) + c4*4);
    } else {
        int t = tid - 128;
        int j = t >> 2, c4 = t & 3;
        cpa16(&KsB[1][j][c4*4], g_kb + ((size_t)b*LL + 32 + j)*(QKH/2) + h*(QK/2) + c4*4);
    }
    CP_COMMIT;
    if (tid < 32) {
        int j = tid;
        const float* pp = posCB + ((size_t)b*LL + 32 + j)*3;
        VsB[1][j][32] = __float2bfloat16(pp[0]);
        VsB[1][j][33] = __float2bfloat16(pp[1]);
        VsB[1][j][34] = __float2bfloat16(pp[2]);
        VsB[1][j][35] = __float2bfloat16(1.0f);
        VsB[1][j][36] = __float2bfloat16(0.0f);
        VsB[1][j][37] = __float2bfloat16(0.0f);
        VsB[1][j][38] = __float2bfloat16(0.0f);
        VsB[1][j][39] = __float2bfloat16(0.0f);
    }
    CP_WAIT1;        // group 0 (Q + chunk 0) complete
    __syncthreads();

    // ---- hoist Q fragments into registers (chunk-invariant) ----
    uint32_t qreg[2][2][4];
#pragma unroll
    for (int mt = 0; mt < 2; mt++) {
        const int rb = w*32 + mt*16;
#pragma unroll
        for (int s = 0; s < 2; s++) {
            qreg[mt][s][0] = Qs[rb+g][s*8+t4];
            qreg[mt][s][1] = Qs[rb+g+8][s*8+t4];
            qreg[mt][s][2] = Qs[rb+g][s*8+t4+4];
            qreg[mt][s][3] = Qs[rb+g+8][s*8+t4+4];
        }
    }

    float acc[2][5][4];
#pragma unroll
    for (int i = 0; i < 2; i++)
#pragma unroll
        for (int j = 0; j < 5; j++)
#pragma unroll
            for (int q = 0; q < 4; q++) acc[i][j][q] = 0.0f;

    for (int ch = 0; ch < 16; ch++) {
        const int cb = ch & 1;
        const int j0 = ch * 32;

        // K fragments (scalar LDS, conflict-free pitch 20)
        uint32_t kb[4][2][2];
#pragma unroll
        for (int nt = 0; nt < 4; nt++)
#pragma unroll
            for (int s = 0; s < 2; s++) {
                kb[nt][s][0] = KsB[cb][8*nt + g][s*8 + t4];
                kb[nt][s][1] = KsB[cb][8*nt + g][s*8 + t4 + 4];
            }
        // V fragments
        uint2 vb[2][5];
#pragma unroll
        for (int s = 0; s < 2; s++)
#pragma unroll
            for (int nt = 0; nt < 5; nt++)
                vb[s][nt] = ldsm2t(&VsB[cb][s*16 + i16][nt*8]);

        // masks for this chunk (per-thread columns)
        float mk0[4], mk1[4];
#pragma unroll
        for (int nt = 0; nt < 4; nt++) {
            mk0[nt] = mkf[j0 + 8*nt + 2*t4];
            mk1[nt] = mkf[j0 + 8*nt + 2*t4 + 1];
        }

#pragma unroll
        for (int mt = 0; mt < 2; mt++) {
            // ---- S = Q @ K^T ----
            float S[4][4];
#pragma unroll
            for (int nt = 0; nt < 4; nt++)
#pragma unroll
                for (int q = 0; q < 4; q++) S[nt][q] = 0.0f;
#pragma unroll
            for (int s = 0; s < 2; s++)
#pragma unroll
                for (int nt = 0; nt < 4; nt++)
                    mma_bf16(S[nt], qreg[mt][s][0], qreg[mt][s][1],
                             qreg[mt][s][2], qreg[mt][s][3],
                             kb[nt][s][0], kb[nt][s][1]);
            // ---- P = mask*exp(S), packed directly as O-phase A fragments ----
            uint32_t pa[2][4];
#pragma unroll
            for (int hf = 0; hf < 2; hf++) {
                const int na = 2*hf, nb2 = 2*hf + 1;
                pa[hf][0] = bf2(mk0[na]*fexp(S[na][0]),  mk1[na]*fexp(S[na][1]));
                pa[hf][1] = bf2(mk0[na]*fexp(S[na][2]),  mk1[na]*fexp(S[na][3]));
                pa[hf][2] = bf2(mk0[nb2]*fexp(S[nb2][0]), mk1[nb2]*fexp(S[nb2][1]));
                pa[hf][3] = bf2(mk0[nb2]*fexp(S[nb2][2]), mk1[nb2]*fexp(S[nb2][3]));
            }
            // ---- O += P @ Vaug ----
#pragma unroll
            for (int s = 0; s < 2; s++)
#pragma unroll
                for (int nt = 0; nt < 5; nt++)
                    mma_bf16(acc[mt][nt], pa[s][0], pa[s][1], pa[s][2], pa[s][3],
                             vb[s][nt].x, vb[s][nt].y);
        }

        __syncthreads();   // all warps done reading buffer cb
        if (ch + 2 < 16) {
            const int j2 = (ch + 2) * 32;
            if (tid < 128) {
                int j = tid >> 2, c4 = tid & 3;
                cpa16(&VsB[cb][j][c4*8], g_vb + ((size_t)b*LL + j2 + j)*(QKH/2) + h*(QK/2) + c4*4);
            } else {
                int t = tid - 128;
                int j = t >> 2, c4 = t & 3;
                cpa16(&KsB[cb][j][c4*4], g_kb + ((size_t)b*LL + j2 + j)*(QKH/2) + h*(QK/2) + c4*4);
            }
            CP_COMMIT;
            if (tid < 32) {
                int j = tid;
                const float* pp = posCB + ((size_t)b*LL + j2 + j)*3;
                VsB[cb][j][32] = __float2bfloat16(pp[0]);
                VsB[cb][j][33] = __float2bfloat16(pp[1]);
                VsB[cb][j][34] = __float2bfloat16(pp[2]);
                VsB[cb][j][35] = __float2bfloat16(1.0f);
                VsB[cb][j][36] = __float2bfloat16(0.0f);
                VsB[cb][j][37] = __float2bfloat16(0.0f);
                VsB[cb][j][38] = __float2bfloat16(0.0f);
                VsB[cb][j][39] = __float2bfloat16(0.0f);
            }
        }
        if (ch + 1 < 16) {
            if (ch + 2 < 16) { CP_WAIT1; } else { CP_WAIT0; }
            __syncthreads();
        }
    }

    // ---- epilogue (fp32 math, bf16 feature stores) ----
#pragma unroll
    for (int mt = 0; mt < 2; mt++) {
#pragma unroll
        for (int half = 0; half < 2; half++) {
            const int rloc = w*32 + mt*16 + g + half*8;
            const size_t grow = (size_t)b*LL + qbase + rloc;
            float c_lo = half ? acc[mt][4][2] : acc[mt][4][0];
            float c_hi = half ? acc[mt][4][3] : acc[mt][4][1];
            const int qb = lane & ~3;
            float ap0 = __shfl_sync(0xffffffffu, c_lo, qb + 0);
            float ap1 = __shfl_sync(0xffffffffu, c_hi, qb + 0);
            float ap2 = __shfl_sync(0xffffffffu, c_lo, qb + 1);
            float s   = __shfl_sync(0xffffffffu, c_hi, qb + 1);
            const bool ok = (mkf[qbase + rloc] != 0.0f) && (s > 0.0f);
            const float inv = ok ? 1.0f / s : 0.0f;
            uint32_t* fr = g_featb + grow * (FEAT/2);
            __nv_bfloat16* fr16 = (__nv_bfloat16*)fr;
#pragma unroll
            for (int nt = 0; nt < 4; nt++) {
                float v0 = half ? acc[mt][nt][2] : acc[mt][nt][0];
                float v1 = half ? acc[mt][nt][3] : acc[mt][nt][1];
                fr[h*16 + nt*4 + t4] = bf2(v0*inv, v1*inv);
            }
            if (t4 == 0) {
                if (!ok) {
                    fr16[512+h*3+0] = __float2bfloat16(0.0f);
                    fr16[512+h*3+1] = __float2bfloat16(0.0f);
                    fr16[512+h*3+2] = __float2bfloat16(0.0f);
                    fr16[560+h]     = __float2bfloat16(0.0f);
                    fr16[576+h*3+0] = __float2bfloat16(0.0f);
                    fr16[576+h*3+1] = __float2bfloat16(0.0f);
                    fr16[576+h*3+2] = __float2bfloat16(0.0f);
                    fr16[624+h]     = __float2bfloat16(0.0f);
                } else {
                    float a0 = ap0*inv - posCA[grow*3+0];
                    float a1 = ap1*inv - posCA[grow*3+1];
                    float a2 = ap2*inv - posCA[grow*3+2];
                    const float* F = frame + grow * 9;
                    float pt0 = F[0]*a0 + F[1]*a1 + F[2]*a2;
                    float pt1 = F[3]*a0 + F[4]*a1 + F[5]*a2;
                    float pt2 = F[6]*a0 + F[7]*a1 + F[8]*a2;
                    float dist = sqrtf(a0*a0 + a1*a1 + a2*a2);
                    float pn   = sqrtf(pt0*pt0 + pt1*pt1 + pt2*pt2);
                    float id   = 1.0f / (pn + 1e-10f);
                    float ang  = atan2f(pt1, pt0);
                    fr16[512+h*3+0] = __float2bfloat16(pt0);
                    fr16[512+h*3+1] = __float2bfloat16(pt1);
                    fr16[512+h*3+2] = __float2bfloat16(pt2);
                    fr16[560+h]     = __float2bfloat16(dist);
                    fr16[576+h*3+0] = __float2bfloat16(pt0*id);
                    fr16[576+h*3+1] = __float2bfloat16(pt1*id);
                    fr16[576+h*3+2] = __float2bfloat16(pt2*id);
                    fr16[624+h]     = __float2bfloat16(ang);
                }
            }
        }
    }
}

// ============================================================
// K3a: h1 = relu(feat @ W1 + b1) -> packed bf16 (4096x512,K=640)
// ============================================================
__global__ void __launch_bounds__(256) k_mlp1(const float* __restrict__ b1)
{
    const int bm = blockIdx.x * 128;
    const int bn = blockIdx.y * 64;

    GEMM_PROLOG

    const int NCH = FEAT/32;   // 20
    loadA_async(AsB[0], g_featb, FEAT/2, bm, 0, tid);
    loadB_async(BsB[0], g_w1, HID/2, bn, 0, tid);
    CP_COMMIT;
    for (int ch = 0; ch < NCH; ch++) {
        if (ch + 1 < NCH) {
            int nb = (ch + 1) & 1;
            loadA_async(AsB[nb], g_featb, FEAT/2, bm, (ch+1)*16, tid);
            loadB_async(BsB[nb], g_w1, HID/2, bn, (ch+1)*32, tid);
            CP_COMMIT;
            CP_WAIT1;
        } else {
            CP_WAIT0;
        }
        __syncthreads();
        mma_chunk_bf(AsB[ch & 1], BsB[ch & 1], acc, warpM, warpN, g, t4, lane);
        __syncthreads();
    }

#pragma unroll
    for (int mt = 0; mt < 4; mt++) {
#pragma unroll
        for (int nt = 0; nt < 2; nt++) {
            int R0 = bm + warpM*64 + mt*16 + g;
            int C  = bn + warpN*16 + nt*8 + 2*t4;
            float bx = b1[C], by = b1[C+1];
            g_h1b[(size_t)R0*(HID/2)     + C/2] =
                bf2(fmaxf(acc[mt][nt][0] + bx, 0.f), fmaxf(acc[mt][nt][1] + by, 0.f));
            g_h1b[(size_t)(R0+8)*(HID/2) + C/2] =
                bf2(fmaxf(acc[mt][nt][2] + bx, 0.f), fmaxf(acc[mt][nt][3] + by, 0.f));
        }
    }
}

// ============================================================
// K3b: y = x + mask*(h1 @ W2 + b2)   (4096x256, K=512)
// ============================================================
__global__ void __launch_bounds__(256) k_mlp2(
    const float* __restrict__ x, const float* __restrict__ b2,
    const int* __restrict__ mask)
{
    const int bm = blockIdx.x * 128;
    const int bn = blockIdx.y * 64;

    GEMM_PROLOG

    const int NCH = HID/32;   // 16
    loadA_async(AsB[0], g_h1b, HID/2, bm, 0, tid);
    loadB_async(BsB[0], g_w2, OUTD/2, bn, 0, tid);
    CP_COMMIT;
    for (int ch = 0; ch < NCH; ch++) {
        if (ch + 1 < NCH) {
            int nb = (ch + 1) & 1;
            loadA_async(AsB[nb], g_h1b, HID/2, bm, (ch+1)*16, tid);
            loadB_async(BsB[nb], g_w2, OUTD/2, bn, (ch+1)*32, tid);
            CP_COMMIT;
            CP_WAIT1;
        } else {
            CP_WAIT0;
        }
        __syncthreads();
        mma_chunk_bf(AsB[ch & 1], BsB[ch & 1], acc, warpM, warpN, g, t4, lane);
        __syncthreads();
    }

#pragma unroll
    for (int mt = 0; mt < 4; mt++) {
#pragma unroll
        for (int nt = 0; nt < 2; nt++) {
            int R0 = bm + warpM*64 + mt*16 + g;
            int C  = bn + warpN*16 + nt*8 + 2*t4;
            float bx = b2[C], by = b2[C+1];
#pragma unroll
            for (int half = 0; half < 2; half++) {
                int R = R0 + half*8;
                float2 xv = *(const float2*)&x[(size_t)R*OUTD + C];
                float2 v;
                if (mask[R]) {
                    v.x = xv.x + acc[mt][nt][2*half+0] + bx;
                    v.y = xv.y + acc[mt][nt][2*half+1] + by;
                } else {
                    v = xv;
                }
                *(float2*)&g_y[(size_t)R*OUTD + C] = v;
            }
        }
    }
}

// ============================================================
// K4: LayerNorm. One warp per row.
// ============================================================
__global__ void __launch_bounds__(256) k_ln(
    const float* __restrict__ lng, const float* __restrict__ lnb,
    float* __restrict__ out)
{
    const int wid  = threadIdx.x >> 5;
    const int lane = threadIdx.x & 31;
    const int row  = blockIdx.x * 8 + wid;

    const float* yr = g_y + (size_t)row * OUTD;
    float yv[8];
    float ssum = 0.0f, ssq = 0.0f;
#pragma unroll
    for (int t = 0; t < 2; t++) {
        float4 v = *(const float4*)&yr[lane*4 + t*128];
        yv[t*4+0]=v.x; yv[t*4+1]=v.y; yv[t*4+2]=v.z; yv[t*4+3]=v.w;
        ssum += v.x+v.y+v.z+v.w;
        ssq  += v.x*v.x+v.y*v.y+v.z*v.z+v.w*v.w;
    }
#pragma unroll
    for (int off = 16; off > 0; off >>= 1) {
        ssum += __shfl_xor_sync(0xFFFFFFFF, ssum, off);
        ssq  += __shfl_xor_sync(0xFFFFFFFF, ssq,  off);
    }
    float mu  = ssum * (1.0f / OUTD);
    float var = ssq * (1.0f / OUTD) - mu * mu;
    float rs  = rsqrtf(var + 1e-5f);
#pragma unroll
    for (int t = 0; t < 2; t++) {
        int c = lane*4 + t*128;
        float4 gg = *(const float4*)&lng[c];
        float4 bb = *(const float4*)&lnb[c];
        float4 o;
        o.x = (yv[t*4+0]-mu)*rs*gg.x + bb.x;
        o.y = (yv[t*4+1]-mu)*rs*gg.y + bb.y;
        o.z = (yv[t*4+2]-mu)*rs*gg.z + bb.z;
        o.w = (yv[t*4+3]-mu)*rs*gg.w + bb.w;
        *(float4*)&out[(size_t)row*OUTD + c] = o;
    }
}

// ============================================================
extern "C" void kernel_launch(void* const* d_in, const int* in_sizes, int n_in,
                              void* d_out, int out_size)
{
    const float* x     = (const float*)d_in[0];
    const float* posCA = (const float*)d_in[1];
    const float* posCB = (const float*)d_in[2];
    const float* frame = (const float*)d_in[3];
    const int*   mask  = (const int*)  d_in[4];
    const float* Wq    = (const float*)d_in[5];
    const float* Wk    = (const float*)d_in[6];
    const float* Wv    = (const float*)d_in[7];
    const float* seW1  = (const float*)d_in[8];
    const float* seb1  = (const float*)d_in[9];
    const float* seW2  = (const float*)d_in[10];
    const float* seb2  = (const float*)d_in[11];
    const float* otW1  = (const float*)d_in[12];
    const float* otb1  = (const float*)d_in[13];
    const float* otW2  = (const float*)d_in[14];
    const float* otb2  = (const float*)d_in[15];
    const float* lng   = (const float*)d_in[16];
    const float* lnb   = (const float*)d_in[17];
    float* out = (float*)d_out;

    // Qs + 2xKs (u32) + 2xVs (halves) + mkf
    const int smem_attn = (256*20 + 2*32*20) * 4 + 2*32*72*2 + 512*4;  // 36864
    cudaFuncSetAttribute(k_attn, cudaFuncAttributeMaxDynamicSharedMemorySize, smem_attn);

    k_cvtw<<<dim3(512, 7), 256>>>(Wq, Wk, Wv, seW2, otW1, otW2, x);
    k_spat<<<NL/128, 128>>>(posCA, seW1, seb1);
    k_qkv<<<dim3(NL/128, 24), 256>>>(seb2);
    k_attn<<<dim3(HH, NB, 2), 256, smem_attn>>>(posCA, posCB, frame, mask);
    k_mlp1<<<dim3(NL/128, HID/64),  256>>>(otb1);
    k_mlp2<<<dim3(NL/128, OUTD/64), 256>>>(x, otb2, mask);
    k_ln<<<NL/8, 256>>>(lng, lnb, out);
}

// round 13
// speedup vs baseline: 5.7834x; 1.0563x over previous
#include <cuda_runtime.h>
#include <cuda_bf16.h>
#include <math.h>
#include <stdint.h>

// ---------------- problem constants ----------------
#define NB   8
#define LL   512
#define DD   256
#define HH   16
#define QK   32
#define VD   32
#define OUTD 256
#define NL   (NB*LL)          // 4096
#define QKH  (QK*HH)          // 512
#define FEAT 640              // 512 node + 128 spatial
#define HID  512              // OUT*2
#define LOG2E 1.4426950408889634f

// ---------------- bf16 / async helpers ----------------
__device__ __forceinline__ uint32_t bf2(float lo, float hi) {
    uint32_t d;
    asm("cvt.rn.bf16x2.f32 %0, %1, %2;" : "=r"(d) : "f"(hi), "f"(lo));
    return d;
}
__device__ __forceinline__ void mma_bf16(float c[4],
                                         uint32_t a0, uint32_t a1, uint32_t a2, uint32_t a3,
                                         uint32_t b0, uint32_t b1) {
    asm volatile("mma.sync.aligned.m16n8k16.row.col.f32.bf16.bf16.f32 "
                 "{%0,%1,%2,%3}, {%4,%5,%6,%7}, {%8,%9}, {%0,%1,%2,%3};"
                 : "+f"(c[0]), "+f"(c[1]), "+f"(c[2]), "+f"(c[3])
                 : "r"(a0), "r"(a1), "r"(a2), "r"(a3), "r"(b0), "r"(b1));
}
__device__ __forceinline__ uint2 ldsm2t(const void* p) {   // transposed x2
    uint32_t a = (uint32_t)__cvta_generic_to_shared(p);
    uint2 r;
    asm volatile("ldmatrix.sync.aligned.m8n8.x2.trans.shared.b16 {%0,%1}, [%2];"
                 : "=r"(r.x), "=r"(r.y) : "r"(a));
    return r;
}
__device__ __forceinline__ uint2 ldsm2(const void* p) {    // non-trans x2
    uint32_t a = (uint32_t)__cvta_generic_to_shared(p);
    uint2 r;
    asm volatile("ldmatrix.sync.aligned.m8n8.x2.shared.b16 {%0,%1}, [%2];"
                 : "=r"(r.x), "=r"(r.y) : "r"(a));
    return r;
}
__device__ __forceinline__ uint4 ldsm4(const void* p) {    // non-trans x4 (A m16k16)
    uint32_t a = (uint32_t)__cvta_generic_to_shared(p);
    uint4 r;
    asm volatile("ldmatrix.sync.aligned.m8n8.x4.shared.b16 {%0,%1,%2,%3}, [%4];"
                 : "=r"(r.x), "=r"(r.y), "=r"(r.z), "=r"(r.w) : "r"(a));
    return r;
}
__device__ __forceinline__ void cpa16(void* s, const void* g) {
    uint32_t a = (uint32_t)__cvta_generic_to_shared(s);
    asm volatile("cp.async.ca.shared.global [%0], [%1], 16;" :: "r"(a), "l"(g));
}
#define CP_COMMIT asm volatile("cp.async.commit_group;" ::: "memory")
#define CP_WAIT0  asm volatile("cp.async.wait_group 0;" ::: "memory")
#define CP_WAIT1  asm volatile("cp.async.wait_group 1;" ::: "memory")

// 2^y via FMA-only, degree-3 (|rel err| ~6e-4 — below bf16 P quantization)
__device__ __forceinline__ float fexp2(float y) {
    float r = y + 12582912.0f;                    // round to int (1.5*2^23)
    int   n = __float_as_int(r) - 0x4B400000;
    float f = y - (r - 12582912.0f);              // f in [-0.5, 0.5]
    float p = 5.5504108665e-2f;
    p = fmaf(p, f, 2.4022650696e-1f);
    p = fmaf(p, f, 6.9314718056e-1f);
    p = fmaf(p, f, 1.0f);
    return __int_as_float(__float_as_int(p) + (n << 23));
}

// ---------------- scratch (no allocs allowed) ----------------
__device__ uint32_t g_qb[(size_t)NL*QKH/2];     // bf16x2 packed; q pre-scaled by log2(e)
__device__ uint32_t g_kb[(size_t)NL*QKH/2];
__device__ uint32_t g_vb[(size_t)NL*QKH/2];
__device__ uint32_t g_h1b[(size_t)NL*HID/2];
__device__ uint32_t g_featb[(size_t)NL*FEAT/2];
__device__ uint32_t g_xb[(size_t)NL*DD/2];
__device__ uint32_t g_tb[(size_t)NL*QK/2];
__device__ float    g_y[(size_t)NL*OUTD];
// bf16 weights [k][n] (converted once per launch)
__device__ uint32_t g_wq[DD*QKH/2];
__device__ uint32_t g_wk[DD*QKH/2];
__device__ uint32_t g_wv[DD*QKH/2];
__device__ uint32_t g_wse[QK*QKH/2];
__device__ uint32_t g_w1[FEAT*HID/2];
__device__ uint32_t g_w2[HID*OUTD/2];

// ============================================================
// K-1: convert weights + x  fp32 -> packed bf16
// ============================================================
__global__ void k_cvtw(const float* __restrict__ Wq, const float* __restrict__ Wk,
                       const float* __restrict__ Wv, const float* __restrict__ seW2,
                       const float* __restrict__ W1, const float* __restrict__ W2,
                       const float* __restrict__ x)
{
    const int m = blockIdx.y;
    const float* src; uint32_t* dst; int ng;   // groups of 8 elements
    switch (m) {
        case 0: src = Wq;   dst = g_wq;  ng = DD*QKH/8;   break;
        case 1: src = Wk;   dst = g_wk;  ng = DD*QKH/8;   break;
        case 2: src = Wv;   dst = g_wv;  ng = DD*QKH/8;   break;
        case 3: src = seW2; dst = g_wse; ng = QK*QKH/8;   break;
        case 4: src = W1;   dst = g_w1;  ng = FEAT*HID/8; break;
        case 5: src = W2;   dst = g_w2;  ng = HID*OUTD/8; break;
        default:src = x;    dst = g_xb;  ng = NL*DD/8;    break;
    }
    int i = blockIdx.x * blockDim.x + threadIdx.x;
    if (i >= ng) return;
    float4 a = ((const float4*)src)[2*i];
    float4 b = ((const float4*)src)[2*i+1];
    uint4 w;
    w.x = bf2(a.x, a.y); w.y = bf2(a.z, a.w);
    w.z = bf2(b.x, b.y); w.w = bf2(b.z, b.w);
    ((uint4*)dst)[i] = w;
}

// ============================================================
// K0: t = relu(pos_CA @ se_W1 + se_b1) -> packed bf16 (4096x32)
// ============================================================
__global__ void k_spat(const float* __restrict__ posCA,
                       const float* __restrict__ seW1,
                       const float* __restrict__ seb1)
{
    int r = blockIdx.x * blockDim.x + threadIdx.x;
    if (r >= NL) return;
    float p0 = posCA[r*3+0], p1 = posCA[r*3+1], p2 = posCA[r*3+2];
#pragma unroll
    for (int j = 0; j < QK/2; j++) {
        int c0 = 2*j, c1 = 2*j+1;
        float v0 = seb1[c0] + p0*seW1[c0] + p1*seW1[QK + c0] + p2*seW1[2*QK + c0];
        float v1 = seb1[c1] + p0*seW1[c1] + p1*seW1[QK + c1] + p2*seW1[2*QK + c1];
        g_tb[(size_t)r*(QK/2) + j] = bf2(fmaxf(v0, 0.0f), fmaxf(v1, 0.0f));
    }
}

// ============================================================
// GEMM: BM=128, BN=64, BK=32, 8 warps (2M x 4N), m16n8k16.
// cp.async double-buffered; A fragments via ldmatrix.x4.
// ============================================================
__device__ __forceinline__ void loadA_async(uint32_t (*As)[20], const uint32_t* A,
                                            int ldp, int bm, int kcp, int tid)
{
    int r = tid >> 1;
    int h = (tid & 1) * 8;
    const uint32_t* p = A + (size_t)(bm + r) * ldp + kcp + h;
    cpa16(&As[r][h],     p);
    cpa16(&As[r][h + 4], p + 4);
}
__device__ __forceinline__ void loadB_async(__nv_bfloat16 (*Bs16)[72], const uint32_t* W,
                                            int ldn2, int bn, int kc, int tid)
{
    int k  = tid >> 3;
    int n0 = (tid & 7) * 8;
    cpa16(&Bs16[k][n0], W + (size_t)(kc + k) * ldn2 + (bn + n0)/2);
}

__device__ __forceinline__ void mma_chunk_bf(const uint32_t (*As)[20],
                                             const __nv_bfloat16 (*Bs16)[72],
                                             float acc[4][2][4], int warpM, int warpN,
                                             int lane)
{
    const int i16 = lane & 15;
    const int hi4 = (lane >> 4) * 4;   // u32 (pair) offset for ldsm4 col window
#pragma unroll
    for (int s = 0; s < 2; s++) {
        uint2 b[2];
#pragma unroll
        for (int nt = 0; nt < 2; nt++)
            b[nt] = ldsm2t(&Bs16[s*16 + i16][warpN*16 + nt*8]);
#pragma unroll
        for (int mt = 0; mt < 4; mt++) {
            uint4 a = ldsm4(&As[warpM*64 + mt*16 + i16][s*8 + hi4]);
#pragma unroll
            for (int nt = 0; nt < 2; nt++)
                mma_bf16(acc[mt][nt], a.x, a.y, a.z, a.w, b[nt].x, b[nt].y);
        }
    }
}

#define GEMM_PROLOG                                                  \
    __shared__ __align__(16) uint32_t AsB[2][128][20];               \
    __shared__ __align__(16) __nv_bfloat16 BsB[2][32][72];           \
    const int tid  = threadIdx.x;                                    \
    const int wid  = tid >> 5;                                       \
    const int lane = tid & 31;                                       \
    const int g    = lane >> 2, t4 = lane & 3;                       \
    const int warpM = wid >> 2, warpN = wid & 3;                     \
    float acc[4][2][4];                                              \
    _Pragma("unroll") for (int i = 0; i < 4; i++)                    \
    _Pragma("unroll") for (int j = 0; j < 2; j++)                    \
    _Pragma("unroll") for (int q = 0; q < 4; q++) acc[i][j][q] = 0.0f;

// ============================================================
// K1: fused QKV projection (4096 x 1536, K=256; q adds t@se_W2+b,
// then scales q by log2(e) so attention uses exp2)
// ============================================================
__global__ void __launch_bounds__(256) k_qkv(const float* __restrict__ seb2)
{
    const int bm  = blockIdx.x * 128;
    const int mat = blockIdx.y >> 3;           // 0=q 1=k 2=v
    const int bn  = (blockIdx.y & 7) * 64;
    const uint32_t* W = (mat == 0) ? g_wq : (mat == 1) ? g_wk : g_wv;

    GEMM_PROLOG
    (void)g; (void)t4;

    const int nchunks = (mat == 0) ? 9 : 8;
    loadA_async(AsB[0], g_xb, DD/2, bm, 0, tid);
    loadB_async(BsB[0], W, QKH/2, bn, 0, tid);
    CP_COMMIT;
    for (int ch = 0; ch < nchunks; ch++) {
        if (ch + 1 < nchunks) {
            int nb = (ch + 1) & 1;
            if (ch + 1 < 8) {
                loadA_async(AsB[nb], g_xb, DD/2, bm, (ch+1)*16, tid);
                loadB_async(BsB[nb], W, QKH/2, bn, (ch+1)*32, tid);
            } else {
                loadA_async(AsB[nb], g_tb, QK/2, bm, 0, tid);
                loadB_async(BsB[nb], g_wse, QKH/2, bn, 0, tid);
            }
            CP_COMMIT;
            CP_WAIT1;
        } else {
            CP_WAIT0;
        }
        __syncthreads();
        mma_chunk_bf(AsB[ch & 1], BsB[ch & 1], acc, warpM, warpN, lane);
        __syncthreads();
    }

    uint32_t* dst = (mat == 0) ? g_qb : (mat == 1) ? g_kb : g_vb;
    const int gg = lane >> 2, tt = lane & 3;
#pragma unroll
    for (int mt = 0; mt < 4; mt++) {
#pragma unroll
        for (int nt = 0; nt < 2; nt++) {
            int R0 = bm + warpM*64 + mt*16 + gg;
            int C  = bn + warpN*16 + nt*8 + 2*tt;
            float v0 = acc[mt][nt][0], v1 = acc[mt][nt][1];
            float v2 = acc[mt][nt][2], v3 = acc[mt][nt][3];
            if (mat == 0) {
                float bx = seb2[C], by = seb2[C+1];
                v0 = (v0 + bx) * LOG2E; v1 = (v1 + by) * LOG2E;
                v2 = (v2 + bx) * LOG2E; v3 = (v3 + by) * LOG2E;
            }
            dst[(size_t)R0*(QKH/2)     + C/2] = bf2(v0, v1);
            dst[(size_t)(R0+8)*(QKH/2) + C/2] = bf2(v2, v3);
        }
    }
}

// ============================================================
// K2: bf16 TC attention, q-split, cp.async pipeline,
// register-resident P, Q in registers, K frags via ldmatrix.x2,
// exp2 with pre-scaled q.
// Grid (HH, NB, 2): block = 256 q-rows of one (b,h), 8 warps.
// ============================================================
__global__ void __launch_bounds__(256, 2) k_attn(
    const float* __restrict__ posCA,
    const float* __restrict__ posCB,
    const float* __restrict__ frame,
    const int*   __restrict__ mask)
{
    extern __shared__ __align__(16) uint32_t smu[];
    uint32_t (*Qs)[20] = (uint32_t (*)[20])smu;                              // [256][20]
    uint32_t (*KsB)[32][20] = (uint32_t (*)[32][20])(smu + 256*20);          // [2][32][20]
    __nv_bfloat16 (*VsB)[32][72] = (__nv_bfloat16 (*)[32][72])(smu + 256*20 + 2*32*20); // [2][32][72]
    float* mkf = (float*)(smu + 256*20 + 2*32*20 + 2*32*36);                 // [512]

    const int h  = blockIdx.x;
    const int b  = blockIdx.y;
    const int qh = blockIdx.z;
    const int tid = threadIdx.x;
    const int w = tid >> 5, lane = tid & 31;
    const int g = lane >> 2, t4 = lane & 3;
    const int i16 = lane & 15;
    const int krow = lane & 7, khalf = (lane >> 3) & 1;   // ldmatrix.x2 addressing
    const int qbase = qh * 256;

    // ---- group 0: Q + K/V chunk 0 ----
#pragma unroll
    for (int it = 0; it < 4; it++) {
        int idx = tid + 256*it;
        int r = idx >> 2, c4 = idx & 3;
        cpa16(&Qs[r][c4*4], g_qb + ((size_t)b*LL + qbase + r)*(QKH/2) + h*(QK/2) + c4*4);
    }
    if (tid < 128) {
        int j = tid >> 2, c4 = tid & 3;
        cpa16(&VsB[0][j][c4*8], g_vb + ((size_t)b*LL + j)*(QKH/2) + h*(QK/2) + c4*4);
    } else {
        int t = tid - 128;
        int j = t >> 2, c4 = t & 3;
        cpa16(&KsB[0][j][c4*4], g_kb + ((size_t)b*LL + j)*(QKH/2) + h*(QK/2) + c4*4);
    }
    CP_COMMIT;
    if (tid < 32) {
        int j = tid;
        const float* pp = posCB + ((size_t)b*LL + j)*3;
        VsB[0][j][32] = __float2bfloat16(pp[0]);
        VsB[0][j][33] = __float2bfloat16(pp[1]);
        VsB[0][j][34] = __float2bfloat16(pp[2]);
        VsB[0][j][35] = __float2bfloat16(1.0f);
        VsB[0][j][36] = __float2bfloat16(0.0f);
        VsB[0][j][37] = __float2bfloat16(0.0f);
        VsB[0][j][38] = __float2bfloat16(0.0f);
        VsB[0][j][39] = __float2bfloat16(0.0f);
    }
    mkf[tid]       = mask[b*LL + tid]       ? 1.0f : 0.0f;
    mkf[tid + 256] = mask[b*LL + tid + 256] ? 1.0f : 0.0f;

    // ---- group 1: K/V chunk 1 ----
    if (tid < 128) {
        int j = tid >> 2, c4 = tid & 3;
        cpa16(&VsB[1][j][c4*8], g_vb + ((size_t)b*LL + 32 + j)*(QKH/2) + h*(QK/2) + c4*4);
    } else {
        int t = tid - 128;
        int j = t >> 2, c4 = t & 3;
        cpa16(&KsB[1][j][c4*4], g_kb + ((size_t)b*LL + 32 + j)*(QKH/2) + h*(QK/2) + c4*4);
    }
    CP_COMMIT;
    if (tid < 32) {
        int j = tid;
        const float* pp = posCB + ((size_t)b*LL + 32 + j)*3;
        VsB[1][j][32] = __float2bfloat16(pp[0]);
        VsB[1][j][33] = __float2bfloat16(pp[1]);
        VsB[1][j][34] = __float2bfloat16(pp[2]);
        VsB[1][j][35] = __float2bfloat16(1.0f);
        VsB[1][j][36] = __float2bfloat16(0.0f);
        VsB[1][j][37] = __float2bfloat16(0.0f);
        VsB[1][j][38] = __float2bfloat16(0.0f);
        VsB[1][j][39] = __float2bfloat16(0.0f);
    }
    CP_WAIT1;        // group 0 (Q + chunk 0) complete
    __syncthreads();

    // ---- hoist Q fragments into registers (chunk-invariant) ----
    uint32_t qreg[2][2][4];
#pragma unroll
    for (int mt = 0; mt < 2; mt++) {
        const int rb = w*32 + mt*16;
#pragma unroll
        for (int s = 0; s < 2; s++) {
            qreg[mt][s][0] = Qs[rb+g][s*8+t4];
            qreg[mt][s][1] = Qs[rb+g+8][s*8+t4];
            qreg[mt][s][2] = Qs[rb+g][s*8+t4+4];
            qreg[mt][s][3] = Qs[rb+g+8][s*8+t4+4];
        }
    }

    float acc[2][5][4];
#pragma unroll
    for (int i = 0; i < 2; i++)
#pragma unroll
        for (int j = 0; j < 5; j++)
#pragma unroll
            for (int q = 0; q < 4; q++) acc[i][j][q] = 0.0f;

    for (int ch = 0; ch < 16; ch++) {
        const int cb = ch & 1;
        const int j0 = ch * 32;

        // K fragments via ldmatrix.x2 (non-trans on [n][k] layout)
        uint32_t kb[4][2][2];
#pragma unroll
        for (int nt = 0; nt < 4; nt++)
#pragma unroll
            for (int s = 0; s < 2; s++) {
                uint2 t = ldsm2(&KsB[cb][8*nt + krow][s*8 + khalf*4]);
                kb[nt][s][0] = t.x;
                kb[nt][s][1] = t.y;
            }
        // V fragments
        uint2 vb[2][5];
#pragma unroll
        for (int s = 0; s < 2; s++)
#pragma unroll
            for (int nt = 0; nt < 5; nt++)
                vb[s][nt] = ldsm2t(&VsB[cb][s*16 + i16][nt*8]);

        // masks for this chunk (per-thread columns)
        float mk0[4], mk1[4];
#pragma unroll
        for (int nt = 0; nt < 4; nt++) {
            mk0[nt] = mkf[j0 + 8*nt + 2*t4];
            mk1[nt] = mkf[j0 + 8*nt + 2*t4 + 1];
        }

#pragma unroll
        for (int mt = 0; mt < 2; mt++) {
            // ---- S = Q @ K^T  (q pre-scaled: S is log2-domain) ----
            float S[4][4];
#pragma unroll
            for (int nt = 0; nt < 4; nt++)
#pragma unroll
                for (int q = 0; q < 4; q++) S[nt][q] = 0.0f;
#pragma unroll
            for (int s = 0; s < 2; s++)
#pragma unroll
                for (int nt = 0; nt < 4; nt++)
                    mma_bf16(S[nt], qreg[mt][s][0], qreg[mt][s][1],
                             qreg[mt][s][2], qreg[mt][s][3],
                             kb[nt][s][0], kb[nt][s][1]);
            // ---- P = mask*exp2(S), packed directly as O-phase A fragments ----
            uint32_t pa[2][4];
#pragma unroll
            for (int hf = 0; hf < 2; hf++) {
                const int na = 2*hf, nb2 = 2*hf + 1;
                pa[hf][0] = bf2(mk0[na]*fexp2(S[na][0]),  mk1[na]*fexp2(S[na][1]));
                pa[hf][1] = bf2(mk0[na]*fexp2(S[na][2]),  mk1[na]*fexp2(S[na][3]));
                pa[hf][2] = bf2(mk0[nb2]*fexp2(S[nb2][0]), mk1[nb2]*fexp2(S[nb2][1]));
                pa[hf][3] = bf2(mk0[nb2]*fexp2(S[nb2][2]), mk1[nb2]*fexp2(S[nb2][3]));
            }
            // ---- O += P @ Vaug ----
#pragma unroll
            for (int s = 0; s < 2; s++)
#pragma unroll
                for (int nt = 0; nt < 5; nt++)
                    mma_bf16(acc[mt][nt], pa[s][0], pa[s][1], pa[s][2], pa[s][3],
                             vb[s][nt].x, vb[s][nt].y);
        }

        __syncthreads();   // all warps done reading buffer cb
        if (ch + 2 < 16) {
            const int j2 = (ch + 2) * 32;
            if (tid < 128) {
                int j = tid >> 2, c4 = tid & 3;
                cpa16(&VsB[cb][j][c4*8], g_vb + ((size_t)b*LL + j2 + j)*(QKH/2) + h*(QK/2) + c4*4);
            } else {
                int t = tid - 128;
                int j = t >> 2, c4 = t & 3;
                cpa16(&KsB[cb][j][c4*4], g_kb + ((size_t)b*LL + j2 + j)*(QKH/2) + h*(QK/2) + c4*4);
            }
            CP_COMMIT;
            if (tid < 32) {
                int j = tid;
                const float* pp = posCB + ((size_t)b*LL + j2 + j)*3;
                VsB[cb][j][32] = __float2bfloat16(pp[0]);
                VsB[cb][j][33] = __float2bfloat16(pp[1]);
                VsB[cb][j][34] = __float2bfloat16(pp[2]);
                VsB[cb][j][35] = __float2bfloat16(1.0f);
                VsB[cb][j][36] = __float2bfloat16(0.0f);
                VsB[cb][j][37] = __float2bfloat16(0.0f);
                VsB[cb][j][38] = __float2bfloat16(0.0f);
                VsB[cb][j][39] = __float2bfloat16(0.0f);
            }
        }
        if (ch + 1 < 16) {
            if (ch + 2 < 16) { CP_WAIT1; } else { CP_WAIT0; }
            __syncthreads();
        }
    }

    // ---- epilogue (fp32 math, bf16 feature stores) ----
#pragma unroll
    for (int mt = 0; mt < 2; mt++) {
#pragma unroll
        for (int half = 0; half < 2; half++) {
            const int rloc = w*32 + mt*16 + g + half*8;
            const size_t grow = (size_t)b*LL + qbase + rloc;
            float c_lo = half ? acc[mt][4][2] : acc[mt][4][0];
            float c_hi = half ? acc[mt][4][3] : acc[mt][4][1];
            const int qb = lane & ~3;
            float ap0 = __shfl_sync(0xffffffffu, c_lo, qb + 0);
            float ap1 = __shfl_sync(0xffffffffu, c_hi, qb + 0);
            float ap2 = __shfl_sync(0xffffffffu, c_lo, qb + 1);
            float s   = __shfl_sync(0xffffffffu, c_hi, qb + 1);
            const bool ok = (mkf[qbase + rloc] != 0.0f) && (s > 0.0f);
            const float inv = ok ? 1.0f / s : 0.0f;
            uint32_t* fr = g_featb + grow * (FEAT/2);
            __nv_bfloat16* fr16 = (__nv_bfloat16*)fr;
#pragma unroll
            for (int nt = 0; nt < 4; nt++) {
                float v0 = half ? acc[mt][nt][2] : acc[mt][nt][0];
                float v1 = half ? acc[mt][nt][3] : acc[mt][nt][1];
                fr[h*16 + nt*4 + t4] = bf2(v0*inv, v1*inv);
            }
            if (t4 == 0) {
                if (!ok) {
                    fr16[512+h*3+0] = __float2bfloat16(0.0f);
                    fr16[512+h*3+1] = __float2bfloat16(0.0f);
                    fr16[512+h*3+2] = __float2bfloat16(0.0f);
                    fr16[560+h]     = __float2bfloat16(0.0f);
                    fr16[576+h*3+0] = __float2bfloat16(0.0f);
                    fr16[576+h*3+1] = __float2bfloat16(0.0f);
                    fr16[576+h*3+2] = __float2bfloat16(0.0f);
                    fr16[624+h]     = __float2bfloat16(0.0f);
                } else {
                    float a0 = ap0*inv - posCA[grow*3+0];
                    float a1 = ap1*inv - posCA[grow*3+1];
                    float a2 = ap2*inv - posCA[grow*3+2];
                    const float* F = frame + grow * 9;
                    float pt0 = F[0]*a0 + F[1]*a1 + F[2]*a2;
                    float pt1 = F[3]*a0 + F[4]*a1 + F[5]*a2;
                    float pt2 = F[6]*a0 + F[7]*a1 + F[8]*a2;
                    float dist = sqrtf(a0*a0 + a1*a1 + a2*a2);
                    float pn   = sqrtf(pt0*pt0 + pt1*pt1 + pt2*pt2);
                    float id   = 1.0f / (pn + 1e-10f);
                    float ang  = atan2f(pt1, pt0);
                    fr16[512+h*3+0] = __float2bfloat16(pt0);
                    fr16[512+h*3+1] = __float2bfloat16(pt1);
                    fr16[512+h*3+2] = __float2bfloat16(pt2);
                    fr16[560+h]     = __float2bfloat16(dist);
                    fr16[576+h*3+0] = __float2bfloat16(pt0*id);
                    fr16[576+h*3+1] = __float2bfloat16(pt1*id);
                    fr16[576+h*3+2] = __float2bfloat16(pt2*id);
                    fr16[624+h]     = __float2bfloat16(ang);
                }
            }
        }
    }
}

// ============================================================
// K3a: h1 = relu(feat @ W1 + b1) -> packed bf16 (4096x512,K=640)
// ============================================================
__global__ void __launch_bounds__(256) k_mlp1(const float* __restrict__ b1)
{
    const int bm = blockIdx.x * 128;
    const int bn = blockIdx.y * 64;

    GEMM_PROLOG

    const int NCH = FEAT/32;   // 20
    loadA_async(AsB[0], g_featb, FEAT/2, bm, 0, tid);
    loadB_async(BsB[0], g_w1, HID/2, bn, 0, tid);
    CP_COMMIT;
    for (int ch = 0; ch < NCH; ch++) {
        if (ch + 1 < NCH) {
            int nb = (ch + 1) & 1;
            loadA_async(AsB[nb], g_featb, FEAT/2, bm, (ch+1)*16, tid);
            loadB_async(BsB[nb], g_w1, HID/2, bn, (ch+1)*32, tid);
            CP_COMMIT;
            CP_WAIT1;
        } else {
            CP_WAIT0;
        }
        __syncthreads();
        mma_chunk_bf(AsB[ch & 1], BsB[ch & 1], acc, warpM, warpN, lane);
        __syncthreads();
    }

#pragma unroll
    for (int mt = 0; mt < 4; mt++) {
#pragma unroll
        for (int nt = 0; nt < 2; nt++) {
            int R0 = bm + warpM*64 + mt*16 + g;
            int C  = bn + warpN*16 + nt*8 + 2*t4;
            float bx = b1[C], by = b1[C+1];
            g_h1b[(size_t)R0*(HID/2)     + C/2] =
                bf2(fmaxf(acc[mt][nt][0] + bx, 0.f), fmaxf(acc[mt][nt][1] + by, 0.f));
            g_h1b[(size_t)(R0+8)*(HID/2) + C/2] =
                bf2(fmaxf(acc[mt][nt][2] + bx, 0.f), fmaxf(acc[mt][nt][3] + by, 0.f));
        }
    }
}

// ============================================================
// K3b: y = x + mask*(h1 @ W2 + b2)   (4096x256, K=512)
// ============================================================
__global__ void __launch_bounds__(256) k_mlp2(
    const float* __restrict__ x, const float* __restrict__ b2,
    const int* __restrict__ mask)
{
    const int bm = blockIdx.x * 128;
    const int bn = blockIdx.y * 64;

    GEMM_PROLOG

    const int NCH = HID/32;   // 16
    loadA_async(AsB[0], g_h1b, HID/2, bm, 0, tid);
    loadB_async(BsB[0], g_w2, OUTD/2, bn, 0, tid);
    CP_COMMIT;
    for (int ch = 0; ch < NCH; ch++) {
        if (ch + 1 < NCH) {
            int nb = (ch + 1) & 1;
            loadA_async(AsB[nb], g_h1b, HID/2, bm, (ch+1)*16, tid);
            loadB_async(BsB[nb], g_w2, OUTD/2, bn, (ch+1)*32, tid);
            CP_COMMIT;
            CP_WAIT1;
        } else {
            CP_WAIT0;
        }
        __syncthreads();
        mma_chunk_bf(AsB[ch & 1], BsB[ch & 1], acc, warpM, warpN, lane);
        __syncthreads();
    }

#pragma unroll
    for (int mt = 0; mt < 4; mt++) {
#pragma unroll
        for (int nt = 0; nt < 2; nt++) {
            int R0 = bm + warpM*64 + mt*16 + g;
            int C  = bn + warpN*16 + nt*8 + 2*t4;
            float bx = b2[C], by = b2[C+1];
#pragma unroll
            for (int half = 0; half < 2; half++) {
                int R = R0 + half*8;
                float2 xv = *(const float2*)&x[(size_t)R*OUTD + C];
                float2 v;
                if (mask[R]) {
                    v.x = xv.x + acc[mt][nt][2*half+0] + bx;
                    v.y = xv.y + acc[mt][nt][2*half+1] + by;
                } else {
                    v = xv;
                }
                *(float2*)&g_y[(size_t)R*OUTD + C] = v;
            }
        }
    }
}

// ============================================================
// K4: LayerNorm. One warp per row.
// ============================================================
__global__ void __launch_bounds__(256) k_ln(
    const float* __restrict__ lng, const float* __restrict__ lnb,
    float* __restrict__ out)
{
    const int wid  = threadIdx.x >> 5;
    const int lane = threadIdx.x & 31;
    const int row  = blockIdx.x * 8 + wid;

    const float* yr = g_y + (size_t)row * OUTD;
    float yv[8];
    float ssum = 0.0f, ssq = 0.0f;
#pragma unroll
    for (int t = 0; t < 2; t++) {
        float4 v = *(const float4*)&yr[lane*4 + t*128];
        yv[t*4+0]=v.x; yv[t*4+1]=v.y; yv[t*4+2]=v.z; yv[t*4+3]=v.w;
        ssum += v.x+v.y+v.z+v.w;
        ssq  += v.x*v.x+v.y*v.y+v.z*v.z+v.w*v.w;
    }
#pragma unroll
    for (int off = 16; off > 0; off >>= 1) {
        ssum += __shfl_xor_sync(0xFFFFFFFF, ssum, off);
        ssq  += __shfl_xor_sync(0xFFFFFFFF, ssq,  off);
    }
    float mu  = ssum * (1.0f / OUTD);
    float var = ssq * (1.0f / OUTD) - mu * mu;
    float rs  = rsqrtf(var + 1e-5f);
#pragma unroll
    for (int t = 0; t < 2; t++) {
        int c = lane*4 + t*128;
        float4 gg = *(const float4*)&lng[c];
        float4 bb = *(const float4*)&lnb[c];
        float4 o;
        o.x = (yv[t*4+0]-mu)*rs*gg.x + bb.x;
        o.y = (yv[t*4+1]-mu)*rs*gg.y + bb.y;
        o.z = (yv[t*4+2]-mu)*rs*gg.z + bb.z;
        o.w = (yv[t*4+3]-mu)*rs*gg.w + bb.w;
        *(float4*)&out[(size_t)row*OUTD + c] = o;
    }
}

// ============================================================
extern "C" void kernel_launch(void* const* d_in, const int* in_sizes, int n_in,
                              void* d_out, int out_size)
{
    const float* x     = (const float*)d_in[0];
    const float* posCA = (const float*)d_in[1];
    const float* posCB = (const float*)d_in[2];
    const float* frame = (const float*)d_in[3];
    const int*   mask  = (const int*)  d_in[4];
    const float* Wq    = (const float*)d_in[5];
    const float* Wk    = (const float*)d_in[6];
    const float* Wv    = (const float*)d_in[7];
    const float* seW1  = (const float*)d_in[8];
    const float* seb1  = (const float*)d_in[9];
    const float* seW2  = (const float*)d_in[10];
    const float* seb2  = (const float*)d_in[11];
    const float* otW1  = (const float*)d_in[12];
    const float* otb1  = (const float*)d_in[13];
    const float* otW2  = (const float*)d_in[14];
    const float* otb2  = (const float*)d_in[15];
    const float* lng   = (const float*)d_in[16];
    const float* lnb   = (const float*)d_in[17];
    float* out = (float*)d_out;

    // Qs + 2xKs (u32) + 2xVs (halves) + mkf
    const int smem_attn = (256*20 + 2*32*20) * 4 + 2*32*72*2 + 512*4;  // 36864
    cudaFuncSetAttribute(k_attn, cudaFuncAttributeMaxDynamicSharedMemorySize, smem_attn);

    k_cvtw<<<dim3(512, 7), 256>>>(Wq, Wk, Wv, seW2, otW1, otW2, x);
    k_spat<<<NL/128, 128>>>(posCA, seW1, seb1);
    k_qkv<<<dim3(NL/128, 24), 256>>>(seb2);
    k_attn<<<dim3(HH, NB, 2), 256, smem_attn>>>(posCA, posCB, frame, mask);
    k_mlp1<<<dim3(NL/128, HID/64),  256>>>(otb1);
    k_mlp2<<<dim3(NL/128, OUTD/64), 256>>>(x, otb2, mask);
    k_ln<<<NL/8, 256>>>(lng, lnb, out);
}

// round 14
// speedup vs baseline: 5.8088x; 1.0044x over previous
#include <cuda_runtime.h>
#include <cuda_bf16.h>
#include <math.h>
#include <stdint.h>

// ---------------- problem constants ----------------
#define NB   8
#define LL   512
#define DD   256
#define HH   16
#define QK   32
#define VD   32
#define OUTD 256
#define NL   (NB*LL)          // 4096
#define QKH  (QK*HH)          // 512
#define FEAT 640              // 512 node + 128 spatial
#define HID  512              // OUT*2
#define LOG2E 1.4426950408889634f

// ---------------- bf16 / async helpers ----------------
__device__ __forceinline__ uint32_t bf2(float lo, float hi) {
    uint32_t d;
    asm("cvt.rn.bf16x2.f32 %0, %1, %2;" : "=r"(d) : "f"(hi), "f"(lo));
    return d;
}
__device__ __forceinline__ void mma_bf16(float c[4],
                                         uint32_t a0, uint32_t a1, uint32_t a2, uint32_t a3,
                                         uint32_t b0, uint32_t b1) {
    asm volatile("mma.sync.aligned.m16n8k16.row.col.f32.bf16.bf16.f32 "
                 "{%0,%1,%2,%3}, {%4,%5,%6,%7}, {%8,%9}, {%0,%1,%2,%3};"
                 : "+f"(c[0]), "+f"(c[1]), "+f"(c[2]), "+f"(c[3])
                 : "r"(a0), "r"(a1), "r"(a2), "r"(a3), "r"(b0), "r"(b1));
}
__device__ __forceinline__ uint2 ldsm2t(const void* p) {   // transposed x2
    uint32_t a = (uint32_t)__cvta_generic_to_shared(p);
    uint2 r;
    asm volatile("ldmatrix.sync.aligned.m8n8.x2.trans.shared.b16 {%0,%1}, [%2];"
                 : "=r"(r.x), "=r"(r.y) : "r"(a));
    return r;
}
__device__ __forceinline__ uint2 ldsm2(const void* p) {    // non-trans x2
    uint32_t a = (uint32_t)__cvta_generic_to_shared(p);
    uint2 r;
    asm volatile("ldmatrix.sync.aligned.m8n8.x2.shared.b16 {%0,%1}, [%2];"
                 : "=r"(r.x), "=r"(r.y) : "r"(a));
    return r;
}
__device__ __forceinline__ uint4 ldsm4(const void* p) {    // non-trans x4 (A m16k16)
    uint32_t a = (uint32_t)__cvta_generic_to_shared(p);
    uint4 r;
    asm volatile("ldmatrix.sync.aligned.m8n8.x4.shared.b16 {%0,%1,%2,%3}, [%4];"
                 : "=r"(r.x), "=r"(r.y), "=r"(r.z), "=r"(r.w) : "r"(a));
    return r;
}
__device__ __forceinline__ void cpa16(void* s, const void* g) {
    uint32_t a = (uint32_t)__cvta_generic_to_shared(s);
    asm volatile("cp.async.ca.shared.global [%0], [%1], 16;" :: "r"(a), "l"(g));
}
#define CP_COMMIT asm volatile("cp.async.commit_group;" ::: "memory")
#define CP_WAIT0  asm volatile("cp.async.wait_group 0;" ::: "memory")
#define CP_WAIT1  asm volatile("cp.async.wait_group 1;" ::: "memory")

// 2^y via FMA-only, degree-4 Taylor (|rel err| ~3e-5)
__device__ __forceinline__ float fexp2(float y) {
    float r = y + 12582912.0f;                    // round to int (1.5*2^23)
    int   n = __float_as_int(r) - 0x4B400000;
    float f = y - (r - 12582912.0f);              // f in [-0.5, 0.5]
    float p = 9.6181291076e-3f;
    p = fmaf(p, f, 5.5504108665e-2f);
    p = fmaf(p, f, 2.4022650696e-1f);
    p = fmaf(p, f, 6.9314718056e-1f);
    p = fmaf(p, f, 1.0f);
    return __int_as_float(__float_as_int(p) + (n << 23));
}

// ---------------- scratch (no allocs allowed) ----------------
__device__ uint32_t g_qb[(size_t)NL*QKH/2];     // bf16x2 packed; q pre-scaled by log2(e)
__device__ uint32_t g_kb[(size_t)NL*QKH/2];
__device__ uint32_t g_vb[(size_t)NL*QKH/2];     // V rows pre-masked (zero where !mask)
__device__ uint32_t g_h1b[(size_t)NL*HID/2];
__device__ uint32_t g_featb[(size_t)NL*FEAT/2];
__device__ uint32_t g_xb[(size_t)NL*DD/2];
__device__ uint32_t g_tb[(size_t)NL*QK/2];
__device__ float    g_y[(size_t)NL*OUTD];
// bf16 weights [k][n] (converted once per launch)
__device__ uint32_t g_wq[DD*QKH/2];
__device__ uint32_t g_wk[DD*QKH/2];
__device__ uint32_t g_wv[DD*QKH/2];
__device__ uint32_t g_wse[QK*QKH/2];
__device__ uint32_t g_w1[FEAT*HID/2];
__device__ uint32_t g_w2[HID*OUTD/2];

// ============================================================
// K-1: convert weights + x  fp32 -> packed bf16
// ============================================================
__global__ void k_cvtw(const float* __restrict__ Wq, const float* __restrict__ Wk,
                       const float* __restrict__ Wv, const float* __restrict__ seW2,
                       const float* __restrict__ W1, const float* __restrict__ W2,
                       const float* __restrict__ x)
{
    const int m = blockIdx.y;
    const float* src; uint32_t* dst; int ng;   // groups of 8 elements
    switch (m) {
        case 0: src = Wq;   dst = g_wq;  ng = DD*QKH/8;   break;
        case 1: src = Wk;   dst = g_wk;  ng = DD*QKH/8;   break;
        case 2: src = Wv;   dst = g_wv;  ng = DD*QKH/8;   break;
        case 3: src = seW2; dst = g_wse; ng = QK*QKH/8;   break;
        case 4: src = W1;   dst = g_w1;  ng = FEAT*HID/8; break;
        case 5: src = W2;   dst = g_w2;  ng = HID*OUTD/8; break;
        default:src = x;    dst = g_xb;  ng = NL*DD/8;    break;
    }
    int i = blockIdx.x * blockDim.x + threadIdx.x;
    if (i >= ng) return;
    float4 a = ((const float4*)src)[2*i];
    float4 b = ((const float4*)src)[2*i+1];
    uint4 w;
    w.x = bf2(a.x, a.y); w.y = bf2(a.z, a.w);
    w.z = bf2(b.x, b.y); w.w = bf2(b.z, b.w);
    ((uint4*)dst)[i] = w;
}

// ============================================================
// K0: t = relu(pos_CA @ se_W1 + se_b1) -> packed bf16 (4096x32)
// ============================================================
__global__ void k_spat(const float* __restrict__ posCA,
                       const float* __restrict__ seW1,
                       const float* __restrict__ seb1)
{
    int r = blockIdx.x * blockDim.x + threadIdx.x;
    if (r >= NL) return;
    float p0 = posCA[r*3+0], p1 = posCA[r*3+1], p2 = posCA[r*3+2];
#pragma unroll
    for (int j = 0; j < QK/2; j++) {
        int c0 = 2*j, c1 = 2*j+1;
        float v0 = seb1[c0] + p0*seW1[c0] + p1*seW1[QK + c0] + p2*seW1[2*QK + c0];
        float v1 = seb1[c1] + p0*seW1[c1] + p1*seW1[QK + c1] + p2*seW1[2*QK + c1];
        g_tb[(size_t)r*(QK/2) + j] = bf2(fmaxf(v0, 0.0f), fmaxf(v1, 0.0f));
    }
}

// ============================================================
// GEMM: BM=128, BN=64, BK=32, 8 warps (2M x 4N), m16n8k16.
// cp.async double-buffered; A fragments via ldmatrix.x4.
// ============================================================
__device__ __forceinline__ void loadA_async(uint32_t (*As)[20], const uint32_t* A,
                                            int ldp, int bm, int kcp, int tid)
{
    int r = tid >> 1;
    int h = (tid & 1) * 8;
    const uint32_t* p = A + (size_t)(bm + r) * ldp + kcp + h;
    cpa16(&As[r][h],     p);
    cpa16(&As[r][h + 4], p + 4);
}
__device__ __forceinline__ void loadB_async(__nv_bfloat16 (*Bs16)[72], const uint32_t* W,
                                            int ldn2, int bn, int kc, int tid)
{
    int k  = tid >> 3;
    int n0 = (tid & 7) * 8;
    cpa16(&Bs16[k][n0], W + (size_t)(kc + k) * ldn2 + (bn + n0)/2);
}

__device__ __forceinline__ void mma_chunk_bf(const uint32_t (*As)[20],
                                             const __nv_bfloat16 (*Bs16)[72],
                                             float acc[4][2][4], int warpM, int warpN,
                                             int lane)
{
    const int i16 = lane & 15;
    const int hi4 = (lane >> 4) * 4;   // u32 (pair) offset for ldsm4 col window
#pragma unroll
    for (int s = 0; s < 2; s++) {
        uint2 b[2];
#pragma unroll
        for (int nt = 0; nt < 2; nt++)
            b[nt] = ldsm2t(&Bs16[s*16 + i16][warpN*16 + nt*8]);
#pragma unroll
        for (int mt = 0; mt < 4; mt++) {
            uint4 a = ldsm4(&As[warpM*64 + mt*16 + i16][s*8 + hi4]);
#pragma unroll
            for (int nt = 0; nt < 2; nt++)
                mma_bf16(acc[mt][nt], a.x, a.y, a.z, a.w, b[nt].x, b[nt].y);
        }
    }
}

#define GEMM_PROLOG                                                  \
    __shared__ __align__(16) uint32_t AsB[2][128][20];               \
    __shared__ __align__(16) __nv_bfloat16 BsB[2][32][72];           \
    const int tid  = threadIdx.x;                                    \
    const int wid  = tid >> 5;                                       \
    const int lane = tid & 31;                                       \
    const int g    = lane >> 2, t4 = lane & 3;                       \
    const int warpM = wid >> 2, warpN = wid & 3;                     \
    float acc[4][2][4];                                              \
    _Pragma("unroll") for (int i = 0; i < 4; i++)                    \
    _Pragma("unroll") for (int j = 0; j < 2; j++)                    \
    _Pragma("unroll") for (int q = 0; q < 4; q++) acc[i][j][q] = 0.0f;

// ============================================================
// K1: fused QKV projection (4096 x 1536, K=256).
// q: + t@se_W2 + se_b2, then *log2(e).  v: pre-masked by row mask.
// ============================================================
__global__ void __launch_bounds__(256) k_qkv(const float* __restrict__ seb2,
                                             const int* __restrict__ mask)
{
    const int bm  = blockIdx.x * 128;
    const int mat = blockIdx.y >> 3;           // 0=q 1=k 2=v
    const int bn  = (blockIdx.y & 7) * 64;
    const uint32_t* W = (mat == 0) ? g_wq : (mat == 1) ? g_wk : g_wv;

    GEMM_PROLOG
    (void)g; (void)t4;

    const int nchunks = (mat == 0) ? 9 : 8;
    loadA_async(AsB[0], g_xb, DD/2, bm, 0, tid);
    loadB_async(BsB[0], W, QKH/2, bn, 0, tid);
    CP_COMMIT;
    for (int ch = 0; ch < nchunks; ch++) {
        if (ch + 1 < nchunks) {
            int nb = (ch + 1) & 1;
            if (ch + 1 < 8) {
                loadA_async(AsB[nb], g_xb, DD/2, bm, (ch+1)*16, tid);
                loadB_async(BsB[nb], W, QKH/2, bn, (ch+1)*32, tid);
            } else {
                loadA_async(AsB[nb], g_tb, QK/2, bm, 0, tid);
                loadB_async(BsB[nb], g_wse, QKH/2, bn, 0, tid);
            }
            CP_COMMIT;
            CP_WAIT1;
        } else {
            CP_WAIT0;
        }
        __syncthreads();
        mma_chunk_bf(AsB[ch & 1], BsB[ch & 1], acc, warpM, warpN, lane);
        __syncthreads();
    }

    uint32_t* dst = (mat == 0) ? g_qb : (mat == 1) ? g_kb : g_vb;
    const int gg = lane >> 2, tt = lane & 3;
#pragma unroll
    for (int mt = 0; mt < 4; mt++) {
#pragma unroll
        for (int nt = 0; nt < 2; nt++) {
            int R0 = bm + warpM*64 + mt*16 + gg;
            int C  = bn + warpN*16 + nt*8 + 2*tt;
            float v0 = acc[mt][nt][0], v1 = acc[mt][nt][1];
            float v2 = acc[mt][nt][2], v3 = acc[mt][nt][3];
            if (mat == 0) {
                float bx = seb2[C], by = seb2[C+1];
                v0 = (v0 + bx) * LOG2E; v1 = (v1 + by) * LOG2E;
                v2 = (v2 + bx) * LOG2E; v3 = (v3 + by) * LOG2E;
            } else if (mat == 2) {
                float m0 = mask[R0]     ? 1.0f : 0.0f;
                float m1 = mask[R0 + 8] ? 1.0f : 0.0f;
                v0 *= m0; v1 *= m0; v2 *= m1; v3 *= m1;
            }
            dst[(size_t)R0*(QKH/2)     + C/2] = bf2(v0, v1);
            dst[(size_t)(R0+8)*(QKH/2) + C/2] = bf2(v2, v3);
        }
    }
}

// ============================================================
// K2: bf16 TC attention, q-split, cp.async pipeline,
// register-resident P (no inner-loop masking: V pre-masked,
// augmented cols masked at write), Q in regs, exp2 pre-scaled q.
// Grid (HH, NB, 2): block = 256 q-rows of one (b,h), 8 warps.
// ============================================================
__global__ void __launch_bounds__(256, 2) k_attn(
    const float* __restrict__ posCA,
    const float* __restrict__ posCB,
    const float* __restrict__ frame,
    const int*   __restrict__ mask)
{
    extern __shared__ __align__(16) uint32_t smu[];
    uint32_t (*Qs)[20] = (uint32_t (*)[20])smu;                              // [256][20]
    uint32_t (*KsB)[32][20] = (uint32_t (*)[32][20])(smu + 256*20);          // [2][32][20]
    __nv_bfloat16 (*VsB)[32][72] = (__nv_bfloat16 (*)[32][72])(smu + 256*20 + 2*32*20); // [2][32][72]
    float* mkf = (float*)(smu + 256*20 + 2*32*20 + 2*32*36);                 // [512]

    const int h  = blockIdx.x;
    const int b  = blockIdx.y;
    const int qh = blockIdx.z;
    const int tid = threadIdx.x;
    const int w = tid >> 5, lane = tid & 31;
    const int g = lane >> 2, t4 = lane & 3;
    const int i16 = lane & 15;
    const int krow = lane & 7, khalf = (lane >> 3) & 1;   // ldmatrix.x2 addressing
    const int qbase = qh * 256;

    // ---- group 0: Q + K/V chunk 0 ----
#pragma unroll
    for (int it = 0; it < 4; it++) {
        int idx = tid + 256*it;
        int r = idx >> 2, c4 = idx & 3;
        cpa16(&Qs[r][c4*4], g_qb + ((size_t)b*LL + qbase + r)*(QKH/2) + h*(QK/2) + c4*4);
    }
    if (tid < 128) {
        int j = tid >> 2, c4 = tid & 3;
        cpa16(&VsB[0][j][c4*8], g_vb + ((size_t)b*LL + j)*(QKH/2) + h*(QK/2) + c4*4);
    } else {
        int t = tid - 128;
        int j = t >> 2, c4 = t & 3;
        cpa16(&KsB[0][j][c4*4], g_kb + ((size_t)b*LL + j)*(QKH/2) + h*(QK/2) + c4*4);
    }
    CP_COMMIT;
    if (tid < 32) {
        int j = tid;
        float mj = mask[b*LL + j] ? 1.0f : 0.0f;
        const float* pp = posCB + ((size_t)b*LL + j)*3;
        VsB[0][j][32] = __float2bfloat16(mj * pp[0]);
        VsB[0][j][33] = __float2bfloat16(mj * pp[1]);
        VsB[0][j][34] = __float2bfloat16(mj * pp[2]);
        VsB[0][j][35] = __float2bfloat16(mj);
        VsB[0][j][36] = __float2bfloat16(0.0f);
        VsB[0][j][37] = __float2bfloat16(0.0f);
        VsB[0][j][38] = __float2bfloat16(0.0f);
        VsB[0][j][39] = __float2bfloat16(0.0f);
    }
    mkf[tid]       = mask[b*LL + tid]       ? 1.0f : 0.0f;
    mkf[tid + 256] = mask[b*LL + tid + 256] ? 1.0f : 0.0f;

    // ---- group 1: K/V chunk 1 ----
    if (tid < 128) {
        int j = tid >> 2, c4 = tid & 3;
        cpa16(&VsB[1][j][c4*8], g_vb + ((size_t)b*LL + 32 + j)*(QKH/2) + h*(QK/2) + c4*4);
    } else {
        int t = tid - 128;
        int j = t >> 2, c4 = t & 3;
        cpa16(&KsB[1][j][c4*4], g_kb + ((size_t)b*LL + 32 + j)*(QKH/2) + h*(QK/2) + c4*4);
    }
    CP_COMMIT;
    if (tid < 32) {
        int j = tid;
        float mj = mask[b*LL + 32 + j] ? 1.0f : 0.0f;
        const float* pp = posCB + ((size_t)b*LL + 32 + j)*3;
        VsB[1][j][32] = __float2bfloat16(mj * pp[0]);
        VsB[1][j][33] = __float2bfloat16(mj * pp[1]);
        VsB[1][j][34] = __float2bfloat16(mj * pp[2]);
        VsB[1][j][35] = __float2bfloat16(mj);
        VsB[1][j][36] = __float2bfloat16(0.0f);
        VsB[1][j][37] = __float2bfloat16(0.0f);
        VsB[1][j][38] = __float2bfloat16(0.0f);
        VsB[1][j][39] = __float2bfloat16(0.0f);
    }
    CP_WAIT1;        // group 0 (Q + chunk 0) complete
    __syncthreads();

    // ---- hoist Q fragments into registers (chunk-invariant) ----
    uint32_t qreg[2][2][4];
#pragma unroll
    for (int mt = 0; mt < 2; mt++) {
        const int rb = w*32 + mt*16;
#pragma unroll
        for (int s = 0; s < 2; s++) {
            qreg[mt][s][0] = Qs[rb+g][s*8+t4];
            qreg[mt][s][1] = Qs[rb+g+8][s*8+t4];
            qreg[mt][s][2] = Qs[rb+g][s*8+t4+4];
            qreg[mt][s][3] = Qs[rb+g+8][s*8+t4+4];
        }
    }

    float acc[2][5][4];
#pragma unroll
    for (int i = 0; i < 2; i++)
#pragma unroll
        for (int j = 0; j < 5; j++)
#pragma unroll
            for (int q = 0; q < 4; q++) acc[i][j][q] = 0.0f;

    for (int ch = 0; ch < 16; ch++) {
        const int cb = ch & 1;

        // K fragments via ldmatrix.x2 (non-trans on [n][k] layout)
        uint32_t kb[4][2][2];
#pragma unroll
        for (int nt = 0; nt < 4; nt++)
#pragma unroll
            for (int s = 0; s < 2; s++) {
                uint2 t = ldsm2(&KsB[cb][8*nt + krow][s*8 + khalf*4]);
                kb[nt][s][0] = t.x;
                kb[nt][s][1] = t.y;
            }
        // V fragments
        uint2 vb[2][5];
#pragma unroll
        for (int s = 0; s < 2; s++)
#pragma unroll
            for (int nt = 0; nt < 5; nt++)
                vb[s][nt] = ldsm2t(&VsB[cb][s*16 + i16][nt*8]);

#pragma unroll
        for (int mt = 0; mt < 2; mt++) {
            // ---- S = Q @ K^T  (q pre-scaled: S is log2-domain) ----
            float S[4][4];
#pragma unroll
            for (int nt = 0; nt < 4; nt++)
#pragma unroll
                for (int q = 0; q < 4; q++) S[nt][q] = 0.0f;
#pragma unroll
            for (int s = 0; s < 2; s++)
#pragma unroll
                for (int nt = 0; nt < 4; nt++)
                    mma_bf16(S[nt], qreg[mt][s][0], qreg[mt][s][1],
                             qreg[mt][s][2], qreg[mt][s][3],
                             kb[nt][s][0], kb[nt][s][1]);
            // ---- P = exp2(S) (mask folded into V), packed as A fragments ----
            uint32_t pa[2][4];
#pragma unroll
            for (int hf = 0; hf < 2; hf++) {
                const int na = 2*hf, nb2 = 2*hf + 1;
                pa[hf][0] = bf2(fexp2(S[na][0]),  fexp2(S[na][1]));
                pa[hf][1] = bf2(fexp2(S[na][2]),  fexp2(S[na][3]));
                pa[hf][2] = bf2(fexp2(S[nb2][0]), fexp2(S[nb2][1]));
                pa[hf][3] = bf2(fexp2(S[nb2][2]), fexp2(S[nb2][3]));
            }
            // ---- O += P @ Vaug ----
#pragma unroll
            for (int s = 0; s < 2; s++)
#pragma unroll
                for (int nt = 0; nt < 5; nt++)
                    mma_bf16(acc[mt][nt], pa[s][0], pa[s][1], pa[s][2], pa[s][3],
                             vb[s][nt].x, vb[s][nt].y);
        }

        __syncthreads();   // all warps done reading buffer cb
        if (ch + 2 < 16) {
            const int j2 = (ch + 2) * 32;
            if (tid < 128) {
                int j = tid >> 2, c4 = tid & 3;
                cpa16(&VsB[cb][j][c4*8], g_vb + ((size_t)b*LL + j2 + j)*(QKH/2) + h*(QK/2) + c4*4);
            } else {
                int t = tid - 128;
                int j = t >> 2, c4 = t & 3;
                cpa16(&KsB[cb][j][c4*4], g_kb + ((size_t)b*LL + j2 + j)*(QKH/2) + h*(QK/2) + c4*4);
            }
            CP_COMMIT;
            if (tid < 32) {
                int j = tid;
                float mj = mask[b*LL + j2 + j] ? 1.0f : 0.0f;
                const float* pp = posCB + ((size_t)b*LL + j2 + j)*3;
                VsB[cb][j][32] = __float2bfloat16(mj * pp[0]);
                VsB[cb][j][33] = __float2bfloat16(mj * pp[1]);
                VsB[cb][j][34] = __float2bfloat16(mj * pp[2]);
                VsB[cb][j][35] = __float2bfloat16(mj);
                VsB[cb][j][36] = __float2bfloat16(0.0f);
                VsB[cb][j][37] = __float2bfloat16(0.0f);
                VsB[cb][j][38] = __float2bfloat16(0.0f);
                VsB[cb][j][39] = __float2bfloat16(0.0f);
            }
        }
        if (ch + 1 < 16) {
            if (ch + 2 < 16) { CP_WAIT1; } else { CP_WAIT0; }
            __syncthreads();
        }
    }

    // ---- epilogue (fp32 math, bf16 feature stores) ----
#pragma unroll
    for (int mt = 0; mt < 2; mt++) {
#pragma unroll
        for (int half = 0; half < 2; half++) {
            const int rloc = w*32 + mt*16 + g + half*8;
            const size_t grow = (size_t)b*LL + qbase + rloc;
            float c_lo = half ? acc[mt][4][2] : acc[mt][4][0];
            float c_hi = half ? acc[mt][4][3] : acc[mt][4][1];
            const int qb = lane & ~3;
            float ap0 = __shfl_sync(0xffffffffu, c_lo, qb + 0);
            float ap1 = __shfl_sync(0xffffffffu, c_hi, qb + 0);
            float ap2 = __shfl_sync(0xffffffffu, c_lo, qb + 1);
            float s   = __shfl_sync(0xffffffffu, c_hi, qb + 1);
            const bool ok = (mkf[qbase + rloc] != 0.0f) && (s > 0.0f);
            const float inv = ok ? 1.0f / s : 0.0f;
            uint32_t* fr = g_featb + grow * (FEAT/2);
            __nv_bfloat16* fr16 = (__nv_bfloat16*)fr;
#pragma unroll
            for (int nt = 0; nt < 4; nt++) {
                float v0 = half ? acc[mt][nt][2] : acc[mt][nt][0];
                float v1 = half ? acc[mt][nt][3] : acc[mt][nt][1];
                fr[h*16 + nt*4 + t4] = bf2(v0*inv, v1*inv);
            }
            if (t4 == 0) {
                if (!ok) {
                    fr16[512+h*3+0] = __float2bfloat16(0.0f);
                    fr16[512+h*3+1] = __float2bfloat16(0.0f);
                    fr16[512+h*3+2] = __float2bfloat16(0.0f);
                    fr16[560+h]     = __float2bfloat16(0.0f);
                    fr16[576+h*3+0] = __float2bfloat16(0.0f);
                    fr16[576+h*3+1] = __float2bfloat16(0.0f);
                    fr16[576+h*3+2] = __float2bfloat16(0.0f);
                    fr16[624+h]     = __float2bfloat16(0.0f);
                } else {
                    float a0 = ap0*inv - posCA[grow*3+0];
                    float a1 = ap1*inv - posCA[grow*3+1];
                    float a2 = ap2*inv - posCA[grow*3+2];
                    const float* F = frame + grow * 9;
                    float pt0 = F[0]*a0 + F[1]*a1 + F[2]*a2;
                    float pt1 = F[3]*a0 + F[4]*a1 + F[5]*a2;
                    float pt2 = F[6]*a0 + F[7]*a1 + F[8]*a2;
                    float dist = sqrtf(a0*a0 + a1*a1 + a2*a2);
                    float pn   = sqrtf(pt0*pt0 + pt1*pt1 + pt2*pt2);
                    float id   = 1.0f / (pn + 1e-10f);
                    float ang  = atan2f(pt1, pt0);
                    fr16[512+h*3+0] = __float2bfloat16(pt0);
                    fr16[512+h*3+1] = __float2bfloat16(pt1);
                    fr16[512+h*3+2] = __float2bfloat16(pt2);
                    fr16[560+h]     = __float2bfloat16(dist);
                    fr16[576+h*3+0] = __float2bfloat16(pt0*id);
                    fr16[576+h*3+1] = __float2bfloat16(pt1*id);
                    fr16[576+h*3+2] = __float2bfloat16(pt2*id);
                    fr16[624+h]     = __float2bfloat16(ang);
                }
            }
        }
    }
}

// ============================================================
// K3a: h1 = relu(feat @ W1 + b1) -> packed bf16 (4096x512,K=640)
// ============================================================
__global__ void __launch_bounds__(256) k_mlp1(const float* __restrict__ b1)
{
    const int bm = blockIdx.x * 128;
    const int bn = blockIdx.y * 64;

    GEMM_PROLOG

    const int NCH = FEAT/32;   // 20
    loadA_async(AsB[0], g_featb, FEAT/2, bm, 0, tid);
    loadB_async(BsB[0], g_w1, HID/2, bn, 0, tid);
    CP_COMMIT;
    for (int ch = 0; ch < NCH; ch++) {
        if (ch + 1 < NCH) {
            int nb = (ch + 1) & 1;
            loadA_async(AsB[nb], g_featb, FEAT/2, bm, (ch+1)*16, tid);
            loadB_async(BsB[nb], g_w1, HID/2, bn, (ch+1)*32, tid);
            CP_COMMIT;
            CP_WAIT1;
        } else {
            CP_WAIT0;
        }
        __syncthreads();
        mma_chunk_bf(AsB[ch & 1], BsB[ch & 1], acc, warpM, warpN, lane);
        __syncthreads();
    }

#pragma unroll
    for (int mt = 0; mt < 4; mt++) {
#pragma unroll
        for (int nt = 0; nt < 2; nt++) {
            int R0 = bm + warpM*64 + mt*16 + g;
            int C  = bn + warpN*16 + nt*8 + 2*t4;
            float bx = b1[C], by = b1[C+1];
            g_h1b[(size_t)R0*(HID/2)     + C/2] =
                bf2(fmaxf(acc[mt][nt][0] + bx, 0.f), fmaxf(acc[mt][nt][1] + by, 0.f));
            g_h1b[(size_t)(R0+8)*(HID/2) + C/2] =
                bf2(fmaxf(acc[mt][nt][2] + bx, 0.f), fmaxf(acc[mt][nt][3] + by, 0.f));
        }
    }
}

// ============================================================
// K3b: y = x + mask*(h1 @ W2 + b2)   (4096x256, K=512)
// ============================================================
__global__ void __launch_bounds__(256) k_mlp2(
    const float* __restrict__ x, const float* __restrict__ b2,
    const int* __restrict__ mask)
{
    const int bm = blockIdx.x * 128;
    const int bn = blockIdx.y * 64;

    GEMM_PROLOG

    const int NCH = HID/32;   // 16
    loadA_async(AsB[0], g_h1b, HID/2, bm, 0, tid);
    loadB_async(BsB[0], g_w2, OUTD/2, bn, 0, tid);
    CP_COMMIT;
    for (int ch = 0; ch < NCH; ch++) {
        if (ch + 1 < NCH) {
            int nb = (ch + 1) & 1;
            loadA_async(AsB[nb], g_h1b, HID/2, bm, (ch+1)*16, tid);
            loadB_async(BsB[nb], g_w2, OUTD/2, bn, (ch+1)*32, tid);
            CP_COMMIT;
            CP_WAIT1;
        } else {
            CP_WAIT0;
        }
        __syncthreads();
        mma_chunk_bf(AsB[ch & 1], BsB[ch & 1], acc, warpM, warpN, lane);
        __syncthreads();
    }

#pragma unroll
    for (int mt = 0; mt < 4; mt++) {
#pragma unroll
        for (int nt = 0; nt < 2; nt++) {
            int R0 = bm + warpM*64 + mt*16 + g;
            int C  = bn + warpN*16 + nt*8 + 2*t4;
            float bx = b2[C], by = b2[C+1];
#pragma unroll
            for (int half = 0; half < 2; half++) {
                int R = R0 + half*8;
                float2 xv = *(const float2*)&x[(size_t)R*OUTD + C];
                float2 v;
                if (mask[R]) {
                    v.x = xv.x + acc[mt][nt][2*half+0] + bx;
                    v.y = xv.y + acc[mt][nt][2*half+1] + by;
                } else {
                    v = xv;
                }
                *(float2*)&g_y[(size_t)R*OUTD + C] = v;
            }
        }
    }
}

// ============================================================
// K4: LayerNorm. One warp per row.
// ============================================================
__global__ void __launch_bounds__(256) k_ln(
    const float* __restrict__ lng, const float* __restrict__ lnb,
    float* __restrict__ out)
{
    const int wid  = threadIdx.x >> 5;
    const int lane = threadIdx.x & 31;
    const int row  = blockIdx.x * 8 + wid;

    const float* yr = g_y + (size_t)row * OUTD;
    float yv[8];
    float ssum = 0.0f, ssq = 0.0f;
#pragma unroll
    for (int t = 0; t < 2; t++) {
        float4 v = *(const float4*)&yr[lane*4 + t*128];
        yv[t*4+0]=v.x; yv[t*4+1]=v.y; yv[t*4+2]=v.z; yv[t*4+3]=v.w;
        ssum += v.x+v.y+v.z+v.w;
        ssq  += v.x*v.x+v.y*v.y+v.z*v.z+v.w*v.w;
    }
#pragma unroll
    for (int off = 16; off > 0; off >>= 1) {
        ssum += __shfl_xor_sync(0xFFFFFFFF, ssum, off);
        ssq  += __shfl_xor_sync(0xFFFFFFFF, ssq,  off);
    }
    float mu  = ssum * (1.0f / OUTD);
    float var = ssq * (1.0f / OUTD) - mu * mu;
    float rs  = rsqrtf(var + 1e-5f);
#pragma unroll
    for (int t = 0; t < 2; t++) {
        int c = lane*4 + t*128;
        float4 gg = *(const float4*)&lng[c];
        float4 bb = *(const float4*)&lnb[c];
        float4 o;
        o.x = (yv[t*4+0]-mu)*rs*gg.x + bb.x;
        o.y = (yv[t*4+1]-mu)*rs*gg.y + bb.y;
        o.z = (yv[t*4+2]-mu)*rs*gg.z + bb.z;
        o.w = (yv[t*4+3]-mu)*rs*gg.w + bb.w;
        *(float4*)&out[(size_t)row*OUTD + c] = o;
    }
}

// ============================================================
extern "C" void kernel_launch(void* const* d_in, const int* in_sizes, int n_in,
                              void* d_out, int out_size)
{
    const float* x     = (const float*)d_in[0];
    const float* posCA = (const float*)d_in[1];
    const float* posCB = (const float*)d_in[2];
    const float* frame = (const float*)d_in[3];
    const int*   mask  = (const int*)  d_in[4];
    const float* Wq    = (const float*)d_in[5];
    const float* Wk    = (const float*)d_in[6];
    const float* Wv    = (const float*)d_in[7];
    const float* seW1  = (const float*)d_in[8];
    const float* seb1  = (const float*)d_in[9];
    const float* seW2  = (const float*)d_in[10];
    const float* seb2  = (const float*)d_in[11];
    const float* otW1  = (const float*)d_in[12];
    const float* otb1  = (const float*)d_in[13];
    const float* otW2  = (const float*)d_in[14];
    const float* otb2  = (const float*)d_in[15];
    const float* lng   = (const float*)d_in[16];
    const float* lnb   = (const float*)d_in[17];
    float* out = (float*)d_out;

    // Qs + 2xKs (u32) + 2xVs (halves) + mkf
    const int smem_attn = (256*20 + 2*32*20) * 4 + 2*32*72*2 + 512*4;  // 36864
    cudaFuncSetAttribute(k_attn, cudaFuncAttributeMaxDynamicSharedMemorySize, smem_attn);

    k_cvtw<<<dim3(512, 7), 256>>>(Wq, Wk, Wv, seW2, otW1, otW2, x);
    k_spat<<<NL/128, 128>>>(posCA, seW1, seb1);
    k_qkv<<<dim3(NL/128, 24), 256>>>(seb2, mask);
    k_attn<<<dim3(HH, NB, 2), 256, smem_attn>>>(posCA, posCB, frame, mask);
    k_mlp1<<<dim3(NL/128, HID/64),  256>>>(otb1);
    k_mlp2<<<dim3(NL/128, OUTD/64), 256>>>(x, otb2, mask);
    k_ln<<<NL/8, 256>>>(lng, lnb, out);
}

// round 15
// speedup vs baseline: 5.8935x; 1.0146x over previous
#include <cuda_runtime.h>
#include <cuda_bf16.h>
#include <math.h>
#include <stdint.h>

// ---------------- problem constants ----------------
#define NB   8
#define LL   512
#define DD   256
#define HH   16
#define QK   32
#define VD   32
#define OUTD 256
#define NL   (NB*LL)          // 4096
#define QKH  (QK*HH)          // 512
#define FEAT 640              // 512 node + 128 spatial
#define HID  512              // OUT*2
#define LOG2E 1.4426950408889634f

// ---------------- bf16 / async helpers ----------------
__device__ __forceinline__ uint32_t bf2(float lo, float hi) {
    uint32_t d;
    asm("cvt.rn.bf16x2.f32 %0, %1, %2;" : "=r"(d) : "f"(hi), "f"(lo));
    return d;
}
__device__ __forceinline__ void mma_bf16(float c[4],
                                         uint32_t a0, uint32_t a1, uint32_t a2, uint32_t a3,
                                         uint32_t b0, uint32_t b1) {
    asm volatile("mma.sync.aligned.m16n8k16.row.col.f32.bf16.bf16.f32 "
                 "{%0,%1,%2,%3}, {%4,%5,%6,%7}, {%8,%9}, {%0,%1,%2,%3};"
                 : "+f"(c[0]), "+f"(c[1]), "+f"(c[2]), "+f"(c[3])
                 : "r"(a0), "r"(a1), "r"(a2), "r"(a3), "r"(b0), "r"(b1));
}
__device__ __forceinline__ uint2 ldsm2t(const void* p) {   // transposed x2
    uint32_t a = (uint32_t)__cvta_generic_to_shared(p);
    uint2 r;
    asm volatile("ldmatrix.sync.aligned.m8n8.x2.trans.shared.b16 {%0,%1}, [%2];"
                 : "=r"(r.x), "=r"(r.y) : "r"(a));
    return r;
}
__device__ __forceinline__ uint2 ldsm2(const void* p) {    // non-trans x2
    uint32_t a = (uint32_t)__cvta_generic_to_shared(p);
    uint2 r;
    asm volatile("ldmatrix.sync.aligned.m8n8.x2.shared.b16 {%0,%1}, [%2];"
                 : "=r"(r.x), "=r"(r.y) : "r"(a));
    return r;
}
__device__ __forceinline__ uint4 ldsm4(const void* p) {    // non-trans x4 (A m16k16)
    uint32_t a = (uint32_t)__cvta_generic_to_shared(p);
    uint4 r;
    asm volatile("ldmatrix.sync.aligned.m8n8.x4.shared.b16 {%0,%1,%2,%3}, [%4];"
                 : "=r"(r.x), "=r"(r.y), "=r"(r.z), "=r"(r.w) : "r"(a));
    return r;
}
__device__ __forceinline__ void cpa16(void* s, const void* g) {
    uint32_t a = (uint32_t)__cvta_generic_to_shared(s);
    asm volatile("cp.async.ca.shared.global [%0], [%1], 16;" :: "r"(a), "l"(g));
}
#define CP_COMMIT asm volatile("cp.async.commit_group;" ::: "memory")
#define CP_WAIT0  asm volatile("cp.async.wait_group 0;" ::: "memory")
#define CP_WAIT1  asm volatile("cp.async.wait_group 1;" ::: "memory")

// 2^y via FMA-only, degree-4 Taylor (|rel err| ~3e-5)
__device__ __forceinline__ float fexp2(float y) {
    float r = y + 12582912.0f;                    // round to int (1.5*2^23)
    int   n = __float_as_int(r) - 0x4B400000;
    float f = y - (r - 12582912.0f);              // f in [-0.5, 0.5]
    float p = 9.6181291076e-3f;
    p = fmaf(p, f, 5.5504108665e-2f);
    p = fmaf(p, f, 2.4022650696e-1f);
    p = fmaf(p, f, 6.9314718056e-1f);
    p = fmaf(p, f, 1.0f);
    return __int_as_float(__float_as_int(p) + (n << 23));
}

// ---------------- scratch (no allocs allowed) ----------------
__device__ uint32_t g_qb[(size_t)NL*QKH/2];     // bf16x2 packed; q pre-scaled by log2(e)
__device__ uint32_t g_kb[(size_t)NL*QKH/2];
__device__ uint32_t g_vb[(size_t)NL*QKH/2];     // V rows pre-masked (zero where !mask)
__device__ uint32_t g_h1b[(size_t)NL*HID/2];
__device__ uint32_t g_featb[(size_t)NL*FEAT/2];
__device__ uint32_t g_xb[(size_t)NL*DD/2];
__device__ uint32_t g_tb[(size_t)NL*QK/2];
__device__ float    g_y[(size_t)NL*OUTD];
// bf16 weights [k][n] (converted once per launch)
__device__ uint32_t g_wq[DD*QKH/2];
__device__ uint32_t g_wk[DD*QKH/2];
__device__ uint32_t g_wv[DD*QKH/2];
__device__ uint32_t g_wse[QK*QKH/2];
__device__ uint32_t g_w1[FEAT*HID/2];
__device__ uint32_t g_w2[HID*OUTD/2];

// ============================================================
// K-1: convert weights + x  fp32 -> packed bf16
// ============================================================
__global__ void k_cvtw(const float* __restrict__ Wq, const float* __restrict__ Wk,
                       const float* __restrict__ Wv, const float* __restrict__ seW2,
                       const float* __restrict__ W1, const float* __restrict__ W2,
                       const float* __restrict__ x)
{
    const int m = blockIdx.y;
    const float* src; uint32_t* dst; int ng;   // groups of 8 elements
    switch (m) {
        case 0: src = Wq;   dst = g_wq;  ng = DD*QKH/8;   break;
        case 1: src = Wk;   dst = g_wk;  ng = DD*QKH/8;   break;
        case 2: src = Wv;   dst = g_wv;  ng = DD*QKH/8;   break;
        case 3: src = seW2; dst = g_wse; ng = QK*QKH/8;   break;
        case 4: src = W1;   dst = g_w1;  ng = FEAT*HID/8; break;
        case 5: src = W2;   dst = g_w2;  ng = HID*OUTD/8; break;
        default:src = x;    dst = g_xb;  ng = NL*DD/8;    break;
    }
    int i = blockIdx.x * blockDim.x + threadIdx.x;
    if (i >= ng) return;
    float4 a = ((const float4*)src)[2*i];
    float4 b = ((const float4*)src)[2*i+1];
    uint4 w;
    w.x = bf2(a.x, a.y); w.y = bf2(a.z, a.w);
    w.z = bf2(b.x, b.y); w.w = bf2(b.z, b.w);
    ((uint4*)dst)[i] = w;
}

// ============================================================
// K0: t = relu(pos_CA @ se_W1 + se_b1) -> packed bf16 (4096x32)
// ============================================================
__global__ void k_spat(const float* __restrict__ posCA,
                       const float* __restrict__ seW1,
                       const float* __restrict__ seb1)
{
    int r = blockIdx.x * blockDim.x + threadIdx.x;
    if (r >= NL) return;
    float p0 = posCA[r*3+0], p1 = posCA[r*3+1], p2 = posCA[r*3+2];
#pragma unroll
    for (int j = 0; j < QK/2; j++) {
        int c0 = 2*j, c1 = 2*j+1;
        float v0 = seb1[c0] + p0*seW1[c0] + p1*seW1[QK + c0] + p2*seW1[2*QK + c0];
        float v1 = seb1[c1] + p0*seW1[c1] + p1*seW1[QK + c1] + p2*seW1[2*QK + c1];
        g_tb[(size_t)r*(QK/2) + j] = bf2(fmaxf(v0, 0.0f), fmaxf(v1, 0.0f));
    }
}

// ============================================================
// GEMM: BM=128, BN=64, BK=32, 8 warps (2M x 4N), m16n8k16.
// cp.async double-buffered; A fragments via ldmatrix.x4.
// ============================================================
__device__ __forceinline__ void loadA_async(uint32_t (*As)[20], const uint32_t* A,
                                            int ldp, int bm, int kcp, int tid)
{
    int r = tid >> 1;
    int h = (tid & 1) * 8;
    const uint32_t* p = A + (size_t)(bm + r) * ldp + kcp + h;
    cpa16(&As[r][h],     p);
    cpa16(&As[r][h + 4], p + 4);
}
__device__ __forceinline__ void loadB_async(__nv_bfloat16 (*Bs16)[72], const uint32_t* W,
                                            int ldn2, int bn, int kc, int tid)
{
    int k  = tid >> 3;
    int n0 = (tid & 7) * 8;
    cpa16(&Bs16[k][n0], W + (size_t)(kc + k) * ldn2 + (bn + n0)/2);
}

__device__ __forceinline__ void mma_chunk_bf(const uint32_t (*As)[20],
                                             const __nv_bfloat16 (*Bs16)[72],
                                             float acc[4][2][4], int warpM, int warpN,
                                             int lane)
{
    const int i16 = lane & 15;
    const int hi4 = (lane >> 4) * 4;   // u32 (pair) offset for ldsm4 col window
#pragma unroll
    for (int s = 0; s < 2; s++) {
        uint2 b[2];
#pragma unroll
        for (int nt = 0; nt < 2; nt++)
            b[nt] = ldsm2t(&Bs16[s*16 + i16][warpN*16 + nt*8]);
#pragma unroll
        for (int mt = 0; mt < 4; mt++) {
            uint4 a = ldsm4(&As[warpM*64 + mt*16 + i16][s*8 + hi4]);
#pragma unroll
            for (int nt = 0; nt < 2; nt++)
                mma_bf16(acc[mt][nt], a.x, a.y, a.z, a.w, b[nt].x, b[nt].y);
        }
    }
}

#define GEMM_PROLOG                                                  \
    __shared__ __align__(16) uint32_t AsB[2][128][20];               \
    __shared__ __align__(16) __nv_bfloat16 BsB[2][32][72];           \
    const int tid  = threadIdx.x;                                    \
    const int wid  = tid >> 5;                                       \
    const int lane = tid & 31;                                       \
    const int g    = lane >> 2, t4 = lane & 3;                       \
    const int warpM = wid >> 2, warpN = wid & 3;                     \
    float acc[4][2][4];                                              \
    _Pragma("unroll") for (int i = 0; i < 4; i++)                    \
    _Pragma("unroll") for (int j = 0; j < 2; j++)                    \
    _Pragma("unroll") for (int q = 0; q < 4; q++) acc[i][j][q] = 0.0f;

// ============================================================
// K1: fused QKV projection (4096 x 1536, K=256).
// q: + t@se_W2 + se_b2, then *log2(e).  v: pre-masked by row mask.
// ============================================================
__global__ void __launch_bounds__(256) k_qkv(const float* __restrict__ seb2,
                                             const int* __restrict__ mask)
{
    const int bm  = blockIdx.x * 128;
    const int mat = blockIdx.y >> 3;           // 0=q 1=k 2=v
    const int bn  = (blockIdx.y & 7) * 64;
    const uint32_t* W = (mat == 0) ? g_wq : (mat == 1) ? g_wk : g_wv;

    GEMM_PROLOG
    (void)g; (void)t4;

    const int nchunks = (mat == 0) ? 9 : 8;
    loadA_async(AsB[0], g_xb, DD/2, bm, 0, tid);
    loadB_async(BsB[0], W, QKH/2, bn, 0, tid);
    CP_COMMIT;
    for (int ch = 0; ch < nchunks; ch++) {
        if (ch + 1 < nchunks) {
            int nb = (ch + 1) & 1;
            if (ch + 1 < 8) {
                loadA_async(AsB[nb], g_xb, DD/2, bm, (ch+1)*16, tid);
                loadB_async(BsB[nb], W, QKH/2, bn, (ch+1)*32, tid);
            } else {
                loadA_async(AsB[nb], g_tb, QK/2, bm, 0, tid);
                loadB_async(BsB[nb], g_wse, QKH/2, bn, 0, tid);
            }
            CP_COMMIT;
            CP_WAIT1;
        } else {
            CP_WAIT0;
        }
        __syncthreads();
        mma_chunk_bf(AsB[ch & 1], BsB[ch & 1], acc, warpM, warpN, lane);
        __syncthreads();
    }

    uint32_t* dst = (mat == 0) ? g_qb : (mat == 1) ? g_kb : g_vb;
    const int gg = lane >> 2, tt = lane & 3;
#pragma unroll
    for (int mt = 0; mt < 4; mt++) {
#pragma unroll
        for (int nt = 0; nt < 2; nt++) {
            int R0 = bm + warpM*64 + mt*16 + gg;
            int C  = bn + warpN*16 + nt*8 + 2*tt;
            float v0 = acc[mt][nt][0], v1 = acc[mt][nt][1];
            float v2 = acc[mt][nt][2], v3 = acc[mt][nt][3];
            if (mat == 0) {
                float bx = seb2[C], by = seb2[C+1];
                v0 = (v0 + bx) * LOG2E; v1 = (v1 + by) * LOG2E;
                v2 = (v2 + bx) * LOG2E; v3 = (v3 + by) * LOG2E;
            } else if (mat == 2) {
                float m0 = mask[R0]     ? 1.0f : 0.0f;
                float m1 = mask[R0 + 8] ? 1.0f : 0.0f;
                v0 *= m0; v1 *= m0; v2 *= m1; v3 *= m1;
            }
            dst[(size_t)R0*(QKH/2)     + C/2] = bf2(v0, v1);
            dst[(size_t)(R0+8)*(QKH/2) + C/2] = bf2(v2, v3);
        }
    }
}

// ============================================================
// K2: bf16 TC attention, q-split, cp.async pipeline,
// register-resident P (no inner-loop masking: V pre-masked,
// augmented cols masked at write), Q in regs, exp2 pre-scaled q.
// Grid (HH, NB, 2): block = 256 q-rows of one (b,h), 8 warps.
// ============================================================
__global__ void __launch_bounds__(256, 2) k_attn(
    const float* __restrict__ posCA,
    const float* __restrict__ posCB,
    const float* __restrict__ frame,
    const int*   __restrict__ mask)
{
    extern __shared__ __align__(16) uint32_t smu[];
    uint32_t (*Qs)[20] = (uint32_t (*)[20])smu;                              // [256][20]
    uint32_t (*KsB)[32][20] = (uint32_t (*)[32][20])(smu + 256*20);          // [2][32][20]
    __nv_bfloat16 (*VsB)[32][72] = (__nv_bfloat16 (*)[32][72])(smu + 256*20 + 2*32*20); // [2][32][72]
    float* mkf = (float*)(smu + 256*20 + 2*32*20 + 2*32*36);                 // [512]

    const int h  = blockIdx.x;
    const int b  = blockIdx.y;
    const int qh = blockIdx.z;
    const int tid = threadIdx.x;
    const int w = tid >> 5, lane = tid & 31;
    const int g = lane >> 2, t4 = lane & 3;
    const int i16 = lane & 15;
    const int krow = lane & 7, khalf = (lane >> 3) & 1;   // ldmatrix.x2 addressing
    const int qbase = qh * 256;

    // ---- group 0: Q + K/V chunk 0 ----
#pragma unroll
    for (int it = 0; it < 4; it++) {
        int idx = tid + 256*it;
        int r = idx >> 2, c4 = idx & 3;
        cpa16(&Qs[r][c4*4], g_qb + ((size_t)b*LL + qbase + r)*(QKH/2) + h*(QK/2) + c4*4);
    }
    if (tid < 128) {
        int j = tid >> 2, c4 = tid & 3;
        cpa16(&VsB[0][j][c4*8], g_vb + ((size_t)b*LL + j)*(QKH/2) + h*(QK/2) + c4*4);
    } else {
        int t = tid - 128;
        int j = t >> 2, c4 = t & 3;
        cpa16(&KsB[0][j][c4*4], g_kb + ((size_t)b*LL + j)*(QKH/2) + h*(QK/2) + c4*4);
    }
    CP_COMMIT;
    if (tid < 32) {
        int j = tid;
        float mj = mask[b*LL + j] ? 1.0f : 0.0f;
        const float* pp = posCB + ((size_t)b*LL + j)*3;
        VsB[0][j][32] = __float2bfloat16(mj * pp[0]);
        VsB[0][j][33] = __float2bfloat16(mj * pp[1]);
        VsB[0][j][34] = __float2bfloat16(mj * pp[2]);
        VsB[0][j][35] = __float2bfloat16(mj);
        VsB[0][j][36] = __float2bfloat16(0.0f);
        VsB[0][j][37] = __float2bfloat16(0.0f);
        VsB[0][j][38] = __float2bfloat16(0.0f);
        VsB[0][j][39] = __float2bfloat16(0.0f);
    }
    mkf[tid]       = mask[b*LL + tid]       ? 1.0f : 0.0f;
    mkf[tid + 256] = mask[b*LL + tid + 256] ? 1.0f : 0.0f;

    // ---- group 1: K/V chunk 1 ----
    if (tid < 128) {
        int j = tid >> 2, c4 = tid & 3;
        cpa16(&VsB[1][j][c4*8], g_vb + ((size_t)b*LL + 32 + j)*(QKH/2) + h*(QK/2) + c4*4);
    } else {
        int t = tid - 128;
        int j = t >> 2, c4 = t & 3;
        cpa16(&KsB[1][j][c4*4], g_kb + ((size_t)b*LL + 32 + j)*(QKH/2) + h*(QK/2) + c4*4);
    }
    CP_COMMIT;
    if (tid < 32) {
        int j = tid;
        float mj = mask[b*LL + 32 + j] ? 1.0f : 0.0f;
        const float* pp = posCB + ((size_t)b*LL + 32 + j)*3;
        VsB[1][j][32] = __float2bfloat16(mj * pp[0]);
        VsB[1][j][33] = __float2bfloat16(mj * pp[1]);
        VsB[1][j][34] = __float2bfloat16(mj * pp[2]);
        VsB[1][j][35] = __float2bfloat16(mj);
        VsB[1][j][36] = __float2bfloat16(0.0f);
        VsB[1][j][37] = __float2bfloat16(0.0f);
        VsB[1][j][38] = __float2bfloat16(0.0f);
        VsB[1][j][39] = __float2bfloat16(0.0f);
    }
    CP_WAIT1;        // group 0 (Q + chunk 0) complete
    __syncthreads();

    // ---- hoist Q fragments into registers (chunk-invariant) ----
    uint32_t qreg[2][2][4];
#pragma unroll
    for (int mt = 0; mt < 2; mt++) {
        const int rb = w*32 + mt*16;
#pragma unroll
        for (int s = 0; s < 2; s++) {
            qreg[mt][s][0] = Qs[rb+g][s*8+t4];
            qreg[mt][s][1] = Qs[rb+g+8][s*8+t4];
            qreg[mt][s][2] = Qs[rb+g][s*8+t4+4];
            qreg[mt][s][3] = Qs[rb+g+8][s*8+t4+4];
        }
    }

    float acc[2][5][4];
#pragma unroll
    for (int i = 0; i < 2; i++)
#pragma unroll
        for (int j = 0; j < 5; j++)
#pragma unroll
            for (int q = 0; q < 4; q++) acc[i][j][q] = 0.0f;

    for (int ch = 0; ch < 16; ch++) {
        const int cb = ch & 1;

        // K fragments via ldmatrix.x2 (non-trans on [n][k] layout)
        uint32_t kb[4][2][2];
#pragma unroll
        for (int nt = 0; nt < 4; nt++)
#pragma unroll
            for (int s = 0; s < 2; s++) {
                uint2 t = ldsm2(&KsB[cb][8*nt + krow][s*8 + khalf*4]);
                kb[nt][s][0] = t.x;
                kb[nt][s][1] = t.y;
            }
        // V fragments
        uint2 vb[2][5];
#pragma unroll
        for (int s = 0; s < 2; s++)
#pragma unroll
            for (int nt = 0; nt < 5; nt++)
                vb[s][nt] = ldsm2t(&VsB[cb][s*16 + i16][nt*8]);

#pragma unroll
        for (int mt = 0; mt < 2; mt++) {
            // ---- S = Q @ K^T  (q pre-scaled: S is log2-domain) ----
            float S[4][4];
#pragma unroll
            for (int nt = 0; nt < 4; nt++)
#pragma unroll
                for (int q = 0; q < 4; q++) S[nt][q] = 0.0f;
#pragma unroll
            for (int s = 0; s < 2; s++)
#pragma unroll
                for (int nt = 0; nt < 4; nt++)
                    mma_bf16(S[nt], qreg[mt][s][0], qreg[mt][s][1],
                             qreg[mt][s][2], qreg[mt][s][3],
                             kb[nt][s][0], kb[nt][s][1]);
            // ---- P = exp2(S) (mask folded into V), packed as A fragments ----
            uint32_t pa[2][4];
#pragma unroll
            for (int hf = 0; hf < 2; hf++) {
                const int na = 2*hf, nb2 = 2*hf + 1;
                pa[hf][0] = bf2(fexp2(S[na][0]),  fexp2(S[na][1]));
                pa[hf][1] = bf2(fexp2(S[na][2]),  fexp2(S[na][3]));
                pa[hf][2] = bf2(fexp2(S[nb2][0]), fexp2(S[nb2][1]));
                pa[hf][3] = bf2(fexp2(S[nb2][2]), fexp2(S[nb2][3]));
            }
            // ---- O += P @ Vaug ----
#pragma unroll
            for (int s = 0; s < 2; s++)
#pragma unroll
                for (int nt = 0; nt < 5; nt++)
                    mma_bf16(acc[mt][nt], pa[s][0], pa[s][1], pa[s][2], pa[s][3],
                             vb[s][nt].x, vb[s][nt].y);
        }

        __syncthreads();   // all warps done reading buffer cb
        if (ch + 2 < 16) {
            const int j2 = (ch + 2) * 32;
            if (tid < 128) {
                int j = tid >> 2, c4 = tid & 3;
                cpa16(&VsB[cb][j][c4*8], g_vb + ((size_t)b*LL + j2 + j)*(QKH/2) + h*(QK/2) + c4*4);
            } else {
                int t = tid - 128;
                int j = t >> 2, c4 = t & 3;
                cpa16(&KsB[cb][j][c4*4], g_kb + ((size_t)b*LL + j2 + j)*(QKH/2) + h*(QK/2) + c4*4);
            }
            CP_COMMIT;
            if (tid < 32) {
                int j = tid;
                float mj = mask[b*LL + j2 + j] ? 1.0f : 0.0f;
                const float* pp = posCB + ((size_t)b*LL + j2 + j)*3;
                VsB[cb][j][32] = __float2bfloat16(mj * pp[0]);
                VsB[cb][j][33] = __float2bfloat16(mj * pp[1]);
                VsB[cb][j][34] = __float2bfloat16(mj * pp[2]);
                VsB[cb][j][35] = __float2bfloat16(mj);
                VsB[cb][j][36] = __float2bfloat16(0.0f);
                VsB[cb][j][37] = __float2bfloat16(0.0f);
                VsB[cb][j][38] = __float2bfloat16(0.0f);
                VsB[cb][j][39] = __float2bfloat16(0.0f);
            }
        }
        if (ch + 1 < 16) {
            if (ch + 2 < 16) { CP_WAIT1; } else { CP_WAIT0; }
            __syncthreads();
        }
    }

    // ---- epilogue (fp32 math, bf16 feature stores) ----
#pragma unroll
    for (int mt = 0; mt < 2; mt++) {
#pragma unroll
        for (int half = 0; half < 2; half++) {
            const int rloc = w*32 + mt*16 + g + half*8;
            const size_t grow = (size_t)b*LL + qbase + rloc;
            float c_lo = half ? acc[mt][4][2] : acc[mt][4][0];
            float c_hi = half ? acc[mt][4][3] : acc[mt][4][1];
            const int qb = lane & ~3;
            float ap0 = __shfl_sync(0xffffffffu, c_lo, qb + 0);
            float ap1 = __shfl_sync(0xffffffffu, c_hi, qb + 0);
            float ap2 = __shfl_sync(0xffffffffu, c_lo, qb + 1);
            float s   = __shfl_sync(0xffffffffu, c_hi, qb + 1);
            const bool ok = (mkf[qbase + rloc] != 0.0f) && (s > 0.0f);
            const float inv = ok ? 1.0f / s : 0.0f;
            uint32_t* fr = g_featb + grow * (FEAT/2);
            __nv_bfloat16* fr16 = (__nv_bfloat16*)fr;
#pragma unroll
            for (int nt = 0; nt < 4; nt++) {
                float v0 = half ? acc[mt][nt][2] : acc[mt][nt][0];
                float v1 = half ? acc[mt][nt][3] : acc[mt][nt][1];
                fr[h*16 + nt*4 + t4] = bf2(v0*inv, v1*inv);
            }
            if (t4 == 0) {
                if (!ok) {
                    fr16[512+h*3+0] = __float2bfloat16(0.0f);
                    fr16[512+h*3+1] = __float2bfloat16(0.0f);
                    fr16[512+h*3+2] = __float2bfloat16(0.0f);
                    fr16[560+h]     = __float2bfloat16(0.0f);
                    fr16[576+h*3+0] = __float2bfloat16(0.0f);
                    fr16[576+h*3+1] = __float2bfloat16(0.0f);
                    fr16[576+h*3+2] = __float2bfloat16(0.0f);
                    fr16[624+h]     = __float2bfloat16(0.0f);
                } else {
                    float a0 = ap0*inv - posCA[grow*3+0];
                    float a1 = ap1*inv - posCA[grow*3+1];
                    float a2 = ap2*inv - posCA[grow*3+2];
                    const float* F = frame + grow * 9;
                    float pt0 = F[0]*a0 + F[1]*a1 + F[2]*a2;
                    float pt1 = F[3]*a0 + F[4]*a1 + F[5]*a2;
                    float pt2 = F[6]*a0 + F[7]*a1 + F[8]*a2;
                    float dist = sqrtf(a0*a0 + a1*a1 + a2*a2);
                    float pn   = sqrtf(pt0*pt0 + pt1*pt1 + pt2*pt2);
                    float id   = 1.0f / (pn + 1e-10f);
                    float ang  = atan2f(pt1, pt0);
                    fr16[512+h*3+0] = __float2bfloat16(pt0);
                    fr16[512+h*3+1] = __float2bfloat16(pt1);
                    fr16[512+h*3+2] = __float2bfloat16(pt2);
                    fr16[560+h]     = __float2bfloat16(dist);
                    fr16[576+h*3+0] = __float2bfloat16(pt0*id);
                    fr16[576+h*3+1] = __float2bfloat16(pt1*id);
                    fr16[576+h*3+2] = __float2bfloat16(pt2*id);
                    fr16[624+h]     = __float2bfloat16(ang);
                }
            }
        }
    }
}

// ============================================================
// K3a: h1 = relu(feat @ W1 + b1) -> packed bf16 (4096x512,K=640)
// ============================================================
__global__ void __launch_bounds__(256) k_mlp1(const float* __restrict__ b1)
{
    const int bm = blockIdx.x * 128;
    const int bn = blockIdx.y * 64;

    GEMM_PROLOG

    const int NCH = FEAT/32;   // 20
    loadA_async(AsB[0], g_featb, FEAT/2, bm, 0, tid);
    loadB_async(BsB[0], g_w1, HID/2, bn, 0, tid);
    CP_COMMIT;
    for (int ch = 0; ch < NCH; ch++) {
        if (ch + 1 < NCH) {
            int nb = (ch + 1) & 1;
            loadA_async(AsB[nb], g_featb, FEAT/2, bm, (ch+1)*16, tid);
            loadB_async(BsB[nb], g_w1, HID/2, bn, (ch+1)*32, tid);
            CP_COMMIT;
            CP_WAIT1;
        } else {
            CP_WAIT0;
        }
        __syncthreads();
        mma_chunk_bf(AsB[ch & 1], BsB[ch & 1], acc, warpM, warpN, lane);
        __syncthreads();
    }

#pragma unroll
    for (int mt = 0; mt < 4; mt++) {
#pragma unroll
        for (int nt = 0; nt < 2; nt++) {
            int R0 = bm + warpM*64 + mt*16 + g;
            int C  = bn + warpN*16 + nt*8 + 2*t4;
            float bx = b1[C], by = b1[C+1];
            g_h1b[(size_t)R0*(HID/2)     + C/2] =
                bf2(fmaxf(acc[mt][nt][0] + bx, 0.f), fmaxf(acc[mt][nt][1] + by, 0.f));
            g_h1b[(size_t)(R0+8)*(HID/2) + C/2] =
                bf2(fmaxf(acc[mt][nt][2] + bx, 0.f), fmaxf(acc[mt][nt][3] + by, 0.f));
        }
    }
}

// ============================================================
// K3b: y = x + mask*(h1 @ W2 + b2)   (4096x256, K=512)
// ============================================================
__global__ void __launch_bounds__(256) k_mlp2(
    const float* __restrict__ x, const float* __restrict__ b2,
    const int* __restrict__ mask)
{
    const int bm = blockIdx.x * 128;
    const int bn = blockIdx.y * 64;

    GEMM_PROLOG

    const int NCH = HID/32;   // 16
    loadA_async(AsB[0], g_h1b, HID/2, bm, 0, tid);
    loadB_async(BsB[0], g_w2, OUTD/2, bn, 0, tid);
    CP_COMMIT;
    for (int ch = 0; ch < NCH; ch++) {
        if (ch + 1 < NCH) {
            int nb = (ch + 1) & 1;
            loadA_async(AsB[nb], g_h1b, HID/2, bm, (ch+1)*16, tid);
            loadB_async(BsB[nb], g_w2, OUTD/2, bn, (ch+1)*32, tid);
            CP_COMMIT;
            CP_WAIT1;
        } else {
            CP_WAIT0;
        }
        __syncthreads();
        mma_chunk_bf(AsB[ch & 1], BsB[ch & 1], acc, warpM, warpN, lane);
        __syncthreads();
    }

#pragma unroll
    for (int mt = 0; mt < 4; mt++) {
#pragma unroll
        for (int nt = 0; nt < 2; nt++) {
            int R0 = bm + warpM*64 + mt*16 + g;
            int C  = bn + warpN*16 + nt*8 + 2*t4;
            float bx = b2[C], by = b2[C+1];
#pragma unroll
            for (int half = 0; half < 2; half++) {
                int R = R0 + half*8;
                float2 xv = *(const float2*)&x[(size_t)R*OUTD + C];
                float2 v;
                if (mask[R]) {
                    v.x = xv.x + acc[mt][nt][2*half+0] + bx;
                    v.y = xv.y + acc[mt][nt][2*half+1] + by;
                } else {
                    v = xv;
                }
                *(float2*)&g_y[(size_t)R*OUTD + C] = v;
            }
        }
    }
}

// ============================================================
// K4: LayerNorm. One warp per row.
// ============================================================
__global__ void __launch_bounds__(256) k_ln(
    const float* __restrict__ lng, const float* __restrict__ lnb,
    float* __restrict__ out)
{
    const int wid  = threadIdx.x >> 5;
    const int lane = threadIdx.x & 31;
    const int row  = blockIdx.x * 8 + wid;

    const float* yr = g_y + (size_t)row * OUTD;
    float yv[8];
    float ssum = 0.0f, ssq = 0.0f;
#pragma unroll
    for (int t = 0; t < 2; t++) {
        float4 v = *(const float4*)&yr[lane*4 + t*128];
        yv[t*4+0]=v.x; yv[t*4+1]=v.y; yv[t*4+2]=v.z; yv[t*4+3]=v.w;
        ssum += v.x+v.y+v.z+v.w;
        ssq  += v.x*v.x+v.y*v.y+v.z*v.z+v.w*v.w;
    }
#pragma unroll
    for (int off = 16; off > 0; off >>= 1) {
        ssum += __shfl_xor_sync(0xFFFFFFFF, ssum, off);
        ssq  += __shfl_xor_sync(0xFFFFFFFF, ssq,  off);
    }
    float mu  = ssum * (1.0f / OUTD);
    float var = ssq * (1.0f / OUTD) - mu * mu;
    float rs  = rsqrtf(var + 1e-5f);
#pragma unroll
    for (int t = 0; t < 2; t++) {
        int c = lane*4 + t*128;
        float4 gg = *(const float4*)&lng[c];
        float4 bb = *(const float4*)&lnb[c];
        float4 o;
        o.x = (yv[t*4+0]-mu)*rs*gg.x + bb.x;
        o.y = (yv[t*4+1]-mu)*rs*gg.y + bb.y;
        o.z = (yv[t*4+2]-mu)*rs*gg.z + bb.z;
        o.w = (yv[t*4+3]-mu)*rs*gg.w + bb.w;
        *(float4*)&out[(size_t)row*OUTD + c] = o;
    }
}

// ============================================================
extern "C" void kernel_launch(void* const* d_in, const int* in_sizes, int n_in,
                              void* d_out, int out_size)
{
    const float* x     = (const float*)d_in[0];
    const float* posCA = (const float*)d_in[1];
    const float* posCB = (const float*)d_in[2];
    const float* frame = (const float*)d_in[3];
    const int*   mask  = (const int*)  d_in[4];
    const float* Wq    = (const float*)d_in[5];
    const float* Wk    = (const float*)d_in[6];
    const float* Wv    = (const float*)d_in[7];
    const float* seW1  = (const float*)d_in[8];
    const float* seb1  = (const float*)d_in[9];
    const float* seW2  = (const float*)d_in[10];
    const float* seb2  = (const float*)d_in[11];
    const float* otW1  = (const float*)d_in[12];
    const float* otb1  = (const float*)d_in[13];
    const float* otW2  = (const float*)d_in[14];
    const float* otb2  = (const float*)d_in[15];
    const float* lng   = (const float*)d_in[16];
    const float* lnb   = (const float*)d_in[17];
    float* out = (float*)d_out;

    // Qs + 2xKs (u32) + 2xVs (halves) + mkf
    const int smem_attn = (256*20 + 2*32*20) * 4 + 2*32*72*2 + 512*4;  // 36864
    cudaFuncSetAttribute(k_attn, cudaFuncAttributeMaxDynamicSharedMemorySize, smem_attn);

    k_cvtw<<<dim3(512, 7), 256>>>(Wq, Wk, Wv, seW2, otW1, otW2, x);
    k_spat<<<NL/128, 128>>>(posCA, seW1, seb1);
    k_qkv<<<dim3(NL/128, 24), 256>>>(seb2, mask);
    k_attn<<<dim3(HH, NB, 2), 256, smem_attn>>>(posCA, posCB, frame, mask);
    k_mlp1<<<dim3(NL/128, HID/64),  256>>>(otb1);
    k_mlp2<<<dim3(NL/128, OUTD/64), 256>>>(x, otb2, mask);
    k_ln<<<NL/8, 256>>>(lng, lnb, out);
}